// round 2
// baseline (speedup 1.0000x reference)
#include <cuda_runtime.h>
#include <cstddef>

#define B_SZ   4
#define T_LEN  512
#define S_LEN  4096
#define HID    1024
#define NH     16
#define HD     64

// Scratch (allocation-free contract: __device__ globals)
__device__ float g_Q[B_SZ * T_LEN * HID];                       // 8 MB
__device__ float g_K[B_SZ * S_LEN * HID];                       // 64 MB
__device__ float g_V[B_SZ * S_LEN * HID];                       // 64 MB
__device__ float g_Wt[(size_t)B_SZ * NH * T_LEN * S_LEN];       // 512 MB scores->weights
__device__ float g_att[B_SZ * T_LEN * HID];                     // 8 MB

// ---------------------------------------------------------------------------
// Generic SGEMM: C[M,N] = A[M,K] @ W[K,N] + bias[N]  (+ seg_emb gather if SEG)
// M % 128 == 0, N % 128 == 0, K % 8 == 0. 128x128 tile, BK=8, double-buffered.
// ---------------------------------------------------------------------------
template<int SEG>
__global__ __launch_bounds__(256, 2)
void gemm_bias_kernel(const float* __restrict__ A, const float* __restrict__ Wm,
                      const float* __restrict__ bias,
                      const int* __restrict__ seg_ids,
                      const float* __restrict__ seg_emb,
                      float* __restrict__ C, int M, int N, int K)
{
    __shared__ float As[2][8][128];
    __shared__ float Bs[2][8][128];
    const int tid  = threadIdx.x;
    const int trow = tid / 16, tcol = tid % 16;
    const int aRow = tid >> 1, aCol = (tid & 1) * 4;
    const int bRow = tid >> 5, bCol = (tid & 31) * 4;
    const float* Ab = A + (size_t)blockIdx.y * 128 * K;
    const float* Wb = Wm + blockIdx.x * 128;

    float acc[8][8] = {};

#define GB_LOAD(kt, bf) do {                                                        \
    float4 av_ = *reinterpret_cast<const float4*>(Ab + (size_t)aRow * K + (kt) + aCol); \
    As[bf][aCol + 0][aRow] = av_.x; As[bf][aCol + 1][aRow] = av_.y;                 \
    As[bf][aCol + 2][aRow] = av_.z; As[bf][aCol + 3][aRow] = av_.w;                 \
    float4 bv_ = *reinterpret_cast<const float4*>(Wb + (size_t)((kt) + bRow) * N + bCol); \
    *reinterpret_cast<float4*>(&Bs[bf][bRow][bCol]) = bv_;                          \
  } while (0)

    GB_LOAD(0, 0);
    __syncthreads();
    int buf = 0;
    for (int kt = 0; kt < K; kt += 8) {
        if (kt + 8 < K) GB_LOAD(kt + 8, buf ^ 1);
        #pragma unroll
        for (int k = 0; k < 8; k++) {
            float rm[8], rn[8];
            #pragma unroll
            for (int i = 0; i < 8; i++) rm[i] = As[buf][k][trow * 8 + i];
            #pragma unroll
            for (int j = 0; j < 8; j++) rn[j] = Bs[buf][k][tcol * 8 + j];
            #pragma unroll
            for (int i = 0; i < 8; i++)
                #pragma unroll
                for (int j = 0; j < 8; j++)
                    acc[i][j] = fmaf(rm[i], rn[j], acc[i][j]);
        }
        __syncthreads();
        buf ^= 1;
    }
#undef GB_LOAD

    #pragma unroll
    for (int i = 0; i < 8; i++) {
        const int m = blockIdx.y * 128 + trow * 8 + i;
        float* Crow = C + (size_t)m * N + blockIdx.x * 128 + tcol * 8;
        const float* br = bias + blockIdx.x * 128 + tcol * 8;
        const float* sr = nullptr;
        if (SEG) sr = seg_emb + (size_t)seg_ids[m] * N + blockIdx.x * 128 + tcol * 8;
        #pragma unroll
        for (int j = 0; j < 8; j += 4) {
            float4 o;
            o.x = acc[i][j + 0] + br[j + 0];
            o.y = acc[i][j + 1] + br[j + 1];
            o.z = acc[i][j + 2] + br[j + 2];
            o.w = acc[i][j + 3] + br[j + 3];
            if (SEG) { o.x += sr[j]; o.y += sr[j + 1]; o.z += sr[j + 2]; o.w += sr[j + 3]; }
            *reinterpret_cast<float4*>(Crow + j) = o;
        }
    }
}

// ---------------------------------------------------------------------------
// Scores: Sc[bh, t, s] = (QK^T)/8 with mask.  Batched over bh = b*NH + h.
// A = Q_bh [T,64] (row stride HID), B = K_bh [S,64] (row stride HID), C = A·B^T
// grid: (S/128, T/128, B*NH), 128x128 tile, BK=8 over d=64, double-buffered
// ---------------------------------------------------------------------------
__global__ __launch_bounds__(256, 2)
void scores_kernel(const float* __restrict__ Q, const float* __restrict__ Kp,
                   const int* __restrict__ amask, float* __restrict__ Sc)
{
    __shared__ float Qs[2][8][128];
    __shared__ float Ks[2][8][128];
    const int bh = blockIdx.z, b = bh / NH, h = bh % NH;
    const int tid  = threadIdx.x;
    const int trow = tid / 16, tcol = tid % 16;
    const int lRow = tid >> 1, lCol = (tid & 1) * 4;
    const float* Qb = Q + (size_t)(b * T_LEN + blockIdx.y * 128) * HID + h * HD;
    const float* Kb = Kp + (size_t)(b * S_LEN + blockIdx.x * 128) * HID + h * HD;
    float acc[8][8] = {};

#define SC_LOAD(kt, bf) do {                                                          \
    float4 qa_ = *reinterpret_cast<const float4*>(Qb + (size_t)lRow * HID + (kt) + lCol); \
    Qs[bf][lCol + 0][lRow] = qa_.x; Qs[bf][lCol + 1][lRow] = qa_.y;                   \
    Qs[bf][lCol + 2][lRow] = qa_.z; Qs[bf][lCol + 3][lRow] = qa_.w;                   \
    float4 ka_ = *reinterpret_cast<const float4*>(Kb + (size_t)lRow * HID + (kt) + lCol); \
    Ks[bf][lCol + 0][lRow] = ka_.x; Ks[bf][lCol + 1][lRow] = ka_.y;                   \
    Ks[bf][lCol + 2][lRow] = ka_.z; Ks[bf][lCol + 3][lRow] = ka_.w;                   \
  } while (0)

    SC_LOAD(0, 0);
    __syncthreads();
    int buf = 0;
    for (int kt = 0; kt < HD; kt += 8) {
        if (kt + 8 < HD) SC_LOAD(kt + 8, buf ^ 1);
        #pragma unroll
        for (int k = 0; k < 8; k++) {
            float rm[8], rn[8];
            #pragma unroll
            for (int i = 0; i < 8; i++) rm[i] = Qs[buf][k][trow * 8 + i];
            #pragma unroll
            for (int j = 0; j < 8; j++) rn[j] = Ks[buf][k][tcol * 8 + j];
            #pragma unroll
            for (int i = 0; i < 8; i++)
                #pragma unroll
                for (int j = 0; j < 8; j++)
                    acc[i][j] = fmaf(rm[i], rn[j], acc[i][j]);
        }
        __syncthreads();
        buf ^= 1;
    }
#undef SC_LOAD

    const int s0 = blockIdx.x * 128 + tcol * 8;
    float* Sb = Sc + (size_t)bh * T_LEN * S_LEN;
    #pragma unroll
    for (int i = 0; i < 8; i++) {
        const int t = blockIdx.y * 128 + trow * 8 + i;
        float* row = Sb + (size_t)t * S_LEN + s0;
        #pragma unroll
        for (int j = 0; j < 8; j++) {
            float v = acc[i][j] * 0.125f;  // 1/sqrt(64)
            if (amask[b * S_LEN + s0 + j] == 0) v = -1e9f;
            row[j] = v;
        }
    }
}

// ---------------------------------------------------------------------------
// Row softmax over s (4096), one block per (bh, t) row. Register-resident.
// ---------------------------------------------------------------------------
__global__ __launch_bounds__(256)
void softmax_kernel(float* __restrict__ Wt)
{
    float* row = Wt + (size_t)blockIdx.x * S_LEN;
    const int tid = threadIdx.x;
    __shared__ float red[8];

    float v[16];
    #pragma unroll
    for (int i = 0; i < 16; i++) v[i] = row[tid + i * 256];

    float m = -1e30f;
    #pragma unroll
    for (int i = 0; i < 16; i++) m = fmaxf(m, v[i]);
    #pragma unroll
    for (int o = 16; o; o >>= 1) m = fmaxf(m, __shfl_xor_sync(0xFFFFFFFFu, m, o));
    if ((tid & 31) == 0) red[tid >> 5] = m;
    __syncthreads();
    float gmax = red[0];
    #pragma unroll
    for (int w = 1; w < 8; w++) gmax = fmaxf(gmax, red[w]);
    __syncthreads();

    float s = 0.f;
    #pragma unroll
    for (int i = 0; i < 16; i++) { v[i] = expf(v[i] - gmax); s += v[i]; }
    #pragma unroll
    for (int o = 16; o; o >>= 1) s += __shfl_xor_sync(0xFFFFFFFFu, s, o);
    if ((tid & 31) == 0) red[tid >> 5] = s;
    __syncthreads();
    float tot = red[0];
    #pragma unroll
    for (int w = 1; w < 8; w++) tot += red[w];

    const float inv = 1.0f / tot;
    #pragma unroll
    for (int i = 0; i < 16; i++) row[tid + i * 256] = v[i] * inv;
}

// ---------------------------------------------------------------------------
// provenance[b,t,s] = mean over heads of weights
// ---------------------------------------------------------------------------
__global__ __launch_bounds__(256)
void provenance_kernel(const float* __restrict__ Wt, float* __restrict__ out)
{
    const size_t idx = (size_t)blockIdx.x * 256 + threadIdx.x;  // over B*T*S
    const int s = (int)(idx & (S_LEN - 1));
    const int t = (int)((idx >> 12) & (T_LEN - 1));
    const int b = (int)(idx >> 21);
    float sum = 0.f;
    #pragma unroll
    for (int h = 0; h < NH; h++)
        sum += Wt[((size_t)(b * NH + h) * T_LEN + t) * S_LEN + s];
    out[idx] = sum * (1.0f / NH);
}

// ---------------------------------------------------------------------------
// attended[b,t,h,d] = sum_s W[bh,t,s] * V[b,s,h*64+d]
// Batched GEMM per bh: [T,S] @ [S,64]. 64x64 tile, BK=32.
// grid: (T/64, B*NH), 256 threads, 4x4 micro-tile.
// ---------------------------------------------------------------------------
__global__ __launch_bounds__(256, 2)
void attended_kernel(const float* __restrict__ Wt, const float* __restrict__ V,
                     float* __restrict__ att)
{
    __shared__ float Ps[32][65];  // Ps[k][m]
    __shared__ float Vs[32][65];  // Vs[k][n]
    const int bh = blockIdx.y, b = bh / NH, h = bh % NH;
    const int tid  = threadIdx.x;
    const int trow = tid / 16, tcol = tid % 16;
    const float* Wb = Wt + (size_t)bh * T_LEN * S_LEN + (size_t)blockIdx.x * 64 * S_LEN;
    const float* Vb = V + (size_t)b * S_LEN * HID + h * HD;
    float acc[4][4] = {};

    const int aR = tid >> 3;        // 0..31 (row of W tile)
    const int aC = (tid & 7) * 4;   // 0..28 (k within chunk)
    const int bR = tid >> 4;        // 0..15 (k row of V tile)
    const int bC = (tid & 15) * 4;  // 0..60 (n)

    for (int kt = 0; kt < S_LEN; kt += 32) {
        #pragma unroll
        for (int u = 0; u < 2; u++) {
            const int r = aR + u * 32;
            float4 a = *reinterpret_cast<const float4*>(Wb + (size_t)r * S_LEN + kt + aC);
            Ps[aC + 0][r] = a.x; Ps[aC + 1][r] = a.y;
            Ps[aC + 2][r] = a.z; Ps[aC + 3][r] = a.w;
        }
        #pragma unroll
        for (int u = 0; u < 2; u++) {
            const int r = bR + u * 16;
            float4 vv = *reinterpret_cast<const float4*>(Vb + (size_t)(kt + r) * HID + bC);
            Vs[r][bC + 0] = vv.x; Vs[r][bC + 1] = vv.y;
            Vs[r][bC + 2] = vv.z; Vs[r][bC + 3] = vv.w;
        }
        __syncthreads();
        #pragma unroll
        for (int k = 0; k < 32; k++) {
            float rm[4], rn[4];
            #pragma unroll
            for (int i = 0; i < 4; i++) rm[i] = Ps[k][trow * 4 + i];
            #pragma unroll
            for (int j = 0; j < 4; j++) rn[j] = Vs[k][tcol * 4 + j];
            #pragma unroll
            for (int i = 0; i < 4; i++)
                #pragma unroll
                for (int j = 0; j < 4; j++)
                    acc[i][j] = fmaf(rm[i], rn[j], acc[i][j]);
        }
        __syncthreads();
    }

    #pragma unroll
    for (int i = 0; i < 4; i++) {
        const int t = blockIdx.x * 64 + trow * 4 + i;
        float* arow = att + (size_t)(b * T_LEN + t) * HID + h * HD + tcol * 4;
        float4 o = { acc[i][0], acc[i][1], acc[i][2], acc[i][3] };
        *reinterpret_cast<float4*>(arow) = o;
    }
}

// ---------------------------------------------------------------------------
extern "C" void kernel_launch(void* const* d_in, const int* in_sizes, int n_in,
                              void* d_out, int out_size)
{
    const float* query  = (const float*)d_in[0];
    const float* key    = (const float*)d_in[1];
    const float* value  = (const float*)d_in[2];
    const int*   amask  = (const int*)d_in[3];
    const int*   segids = (const int*)d_in[4];
    const float* Wq = (const float*)d_in[5];
    const float* bq = (const float*)d_in[6];
    const float* Wk = (const float*)d_in[7];
    const float* bk = (const float*)d_in[8];
    const float* Wv = (const float*)d_in[9];
    const float* bv = (const float*)d_in[10];
    const float* Wo = (const float*)d_in[11];
    const float* bo = (const float*)d_in[12];
    const float* seg_emb = (const float*)d_in[13];
    float* out = (float*)d_out;

    float *Qp, *Kp, *Vp, *Wt, *att;
    cudaGetSymbolAddress((void**)&Qp,  g_Q);
    cudaGetSymbolAddress((void**)&Kp,  g_K);
    cudaGetSymbolAddress((void**)&Vp,  g_V);
    cudaGetSymbolAddress((void**)&Wt,  g_Wt);
    cudaGetSymbolAddress((void**)&att, g_att);

    const int MQ = B_SZ * T_LEN;   // 2048
    const int MK = B_SZ * S_LEN;   // 16384

    // Projections
    gemm_bias_kernel<0><<<dim3(HID / 128, MQ / 128), 256>>>(query, Wq, bq, nullptr, nullptr, Qp, MQ, HID, HID);
    gemm_bias_kernel<1><<<dim3(HID / 128, MK / 128), 256>>>(key,   Wk, bk, segids, seg_emb, Kp, MK, HID, HID);
    gemm_bias_kernel<0><<<dim3(HID / 128, MK / 128), 256>>>(value, Wv, bv, nullptr, nullptr, Vp, MK, HID, HID);

    // Attention
    scores_kernel<<<dim3(S_LEN / 128, T_LEN / 128, B_SZ * NH), 256>>>(Qp, Kp, amask, Wt);
    softmax_kernel<<<B_SZ * NH * T_LEN, 256>>>(Wt);
    provenance_kernel<<<(B_SZ * T_LEN * S_LEN) / 256, 256>>>(Wt, out + (size_t)B_SZ * T_LEN * HID);
    attended_kernel<<<dim3(T_LEN / 64, B_SZ * NH), 256>>>(Wt, Vp, att);

    // Output projection -> first segment of d_out
    gemm_bias_kernel<0><<<dim3(HID / 128, MQ / 128), 256>>>(att, Wo, bo, nullptr, nullptr, out, MQ, HID, HID);
}

// round 4
// speedup vs baseline: 2.8067x; 2.8067x over previous
#include <cuda_runtime.h>
#include <cuda_bf16.h>
#include <cstdint>
#include <cstddef>

#define B_SZ   4
#define T_LEN  512
#define S_LEN  4096
#define HID    1024
#define NH     16
#define HD     64
#define NBH    (B_SZ * NH)

// ---------------------------------------------------------------------------
// helpers
// ---------------------------------------------------------------------------
__device__ __forceinline__ uint32_t smem_u32(const void* p) {
    uint32_t a;
    asm("{ .reg .u64 t; cvta.to.shared.u64 t, %1; cvt.u32.u64 %0, t; }" : "=r"(a) : "l"(p));
    return a;
}
// 64B-row tile swizzle: 4 chunks of 16B per row; conflict-free for ldmatrix groups
__device__ __forceinline__ uint32_t swzoff(int row, int chunk) {
    const int v = (row & 3) ^ ((row >> 2) & 1);
    return (uint32_t)(row * 64 + (((chunk ^ v) & 3) << 4));
}
__device__ __forceinline__ void cpa16(uint32_t dst, const void* src) {
    asm volatile("cp.async.cg.shared.global [%0], [%1], 16;" :: "r"(dst), "l"(src));
}
#define CP_COMMIT() asm volatile("cp.async.commit_group;" ::: "memory")
#define CP_WAIT(n)  asm volatile("cp.async.wait_group %0;" :: "n"(n) : "memory")

__device__ __forceinline__ void ldsm4(uint32_t* r, uint32_t a) {
    asm volatile("ldmatrix.sync.aligned.m8n8.x4.shared.b16 {%0,%1,%2,%3}, [%4];"
                 : "=r"(r[0]), "=r"(r[1]), "=r"(r[2]), "=r"(r[3]) : "r"(a));
}
__device__ __forceinline__ void mma_bf16(float* d, const uint32_t* a, const uint32_t* b) {
    asm volatile("mma.sync.aligned.m16n8k16.row.col.f32.bf16.bf16.f32 "
                 "{%0,%1,%2,%3}, {%4,%5,%6,%7}, {%8,%9}, {%0,%1,%2,%3};"
                 : "+f"(d[0]), "+f"(d[1]), "+f"(d[2]), "+f"(d[3])
                 : "r"(a[0]), "r"(a[1]), "r"(a[2]), "r"(a[3]), "r"(b[0]), "r"(b[1]));
}
__device__ __forceinline__ void split2(float v, __nv_bfloat16& h, __nv_bfloat16& l) {
    h = __float2bfloat16(v);
    l = __float2bfloat16(v - __bfloat162float(h));
}

// Load a [ROWS x 32] bf16 tile (row stride = stride elems) into swizzled SMEM
template<int ROWS>
__device__ __forceinline__ void load_stage(uint32_t sbuf, const __nv_bfloat16* g,
                                           int stride, int tid) {
    #pragma unroll
    for (int i = tid; i < ROWS * 4; i += 256) {
        const int row = i >> 2, ch = i & 3;
        cpa16(sbuf + swzoff(row, ch), g + (size_t)row * stride + ch * 8);
    }
}

// Warp mainloop body for one 32-k stage.  Warp computes A rows [wmr,wmr+64) x
// B rows [wnr,wnr+32).  acc[4][4][4] persistent.  3 split-bf16 products.
__device__ __forceinline__ void stage_compute(uint32_t sAh, uint32_t sAl,
                                              uint32_t sBh, uint32_t sBl,
                                              int wmr, int wnr, int lane,
                                              float (*acc)[4][4]) {
    const int l7 = lane & 7, l8 = (lane >> 3) & 1, l16 = (lane >> 4) & 1;
    const int arow = wmr + l7 + l8 * 8;
    const int brow = wnr + l16 * 8 + l7;
    #pragma unroll
    for (int ks = 0; ks < 2; ks++) {
        uint32_t ah[4][4], al[4][4], bh[2][4], bl[2][4];
        #pragma unroll
        for (int mi = 0; mi < 4; mi++) {
            const uint32_t off = swzoff(arow + mi * 16, ks * 2 + l16);
            ldsm4(ah[mi], sAh + off);
            ldsm4(al[mi], sAl + off);
        }
        #pragma unroll
        for (int p = 0; p < 2; p++) {
            const uint32_t off = swzoff(brow + p * 16, ks * 2 + l8);
            ldsm4(bh[p], sBh + off);
            ldsm4(bl[p], sBl + off);
        }
        #pragma unroll
        for (int mi = 0; mi < 4; mi++)
            #pragma unroll
            for (int nj = 0; nj < 4; nj++) {
                const uint32_t* bhj = &bh[nj >> 1][(nj & 1) * 2];
                const uint32_t* blj = &bl[nj >> 1][(nj & 1) * 2];
                mma_bf16(acc[mi][nj], ah[mi], bhj);
                mma_bf16(acc[mi][nj], ah[mi], blj);
                mma_bf16(acc[mi][nj], al[mi], bhj);
            }
    }
}

// ---------------- scratch ----------------
__device__ __nv_bfloat16 g_qh[2048 * HID],  g_ql[2048 * HID];
__device__ __nv_bfloat16 g_kh[16384 * HID], g_kl[16384 * HID];
__device__ __nv_bfloat16 g_vh[16384 * HID], g_vl[16384 * HID];
__device__ __nv_bfloat16 g_wqh[HID * HID], g_wql[HID * HID];
__device__ __nv_bfloat16 g_wkh[HID * HID], g_wkl[HID * HID];
__device__ __nv_bfloat16 g_wvh[HID * HID], g_wvl[HID * HID];
__device__ __nv_bfloat16 g_woh[HID * HID], g_wol[HID * HID];
__device__ __nv_bfloat16 g_Qh[2048 * HID],  g_Ql[2048 * HID];
__device__ __nv_bfloat16 g_Kh[16384 * HID], g_Kl[16384 * HID];
__device__ float         g_Vf[(size_t)16384 * HID];
__device__ __nv_bfloat16 g_Vth[(size_t)NBH * HD * S_LEN], g_Vtl[(size_t)NBH * HD * S_LEN];
__device__ float         g_S[(size_t)NBH * T_LEN * S_LEN];
__device__ __nv_bfloat16 g_Wh[(size_t)NBH * T_LEN * S_LEN], g_Wl[(size_t)NBH * T_LEN * S_LEN];
__device__ __nv_bfloat16 g_ah[2048 * HID], g_al[2048 * HID];

// ---------------- conversions ----------------
__global__ __launch_bounds__(256)
void conv_split(const float* __restrict__ X, __nv_bfloat16* __restrict__ H,
                __nv_bfloat16* __restrict__ L) {
    const size_t u = (size_t)blockIdx.x * 256 + threadIdx.x;
    float2 v = reinterpret_cast<const float2*>(X)[u];
    __nv_bfloat162 h2, l2;
    split2(v.x, h2.x, l2.x);
    split2(v.y, h2.y, l2.y);
    reinterpret_cast<__nv_bfloat162*>(H)[u] = h2;
    reinterpret_cast<__nv_bfloat162*>(L)[u] = l2;
}
__global__ __launch_bounds__(256)
void conv_wT(const float* __restrict__ W, __nv_bfloat16* __restrict__ WTh,
             __nv_bfloat16* __restrict__ WTl) {
    __shared__ float t[32][33];
    const int k0 = blockIdx.x * 32, n0 = blockIdx.y * 32;
    const int tx = threadIdx.x, ty = threadIdx.y;
    for (int r = ty; r < 32; r += 8) t[r][tx] = W[(size_t)(k0 + r) * HID + n0 + tx];
    __syncthreads();
    for (int r = ty; r < 32; r += 8) {
        __nv_bfloat16 h, l;
        split2(t[tx][r], h, l);
        WTh[(size_t)(n0 + r) * HID + k0 + tx] = h;
        WTl[(size_t)(n0 + r) * HID + k0 + tx] = l;
    }
}
__global__ __launch_bounds__(256)
void transpose_v(const float* __restrict__ V, __nv_bfloat16* __restrict__ Vth,
                 __nv_bfloat16* __restrict__ Vtl) {
    __shared__ float t[32][33];
    const int bh = blockIdx.z, b = bh >> 4, h = bh & 15;
    const int s0 = blockIdx.x * 32, d0 = blockIdx.y * 32;
    const int tx = threadIdx.x, ty = threadIdx.y;
    for (int r = ty; r < 32; r += 8)
        t[r][tx] = V[(size_t)(b * S_LEN + s0 + r) * HID + h * HD + d0 + tx];
    __syncthreads();
    for (int r = ty; r < 32; r += 8) {
        __nv_bfloat16 h2, l2;
        split2(t[tx][r], h2, l2);
        const size_t o = (size_t)(bh * HD + d0 + r) * S_LEN + s0 + tx;
        Vth[o] = h2;
        Vtl[o] = l2;
    }
}

// ---------------- projection GEMM: C[128,128] tile of A[M,1024]@W^T ----------------
// MODE 0: Q (bias then *0.125, split out)  1: K (bias+seg, split out)  2: fp32 out (V,O)
template<int MODE>
__global__ __launch_bounds__(256)
void proj_gemm(const __nv_bfloat16* __restrict__ Ah, const __nv_bfloat16* __restrict__ Al,
               const __nv_bfloat16* __restrict__ Bh, const __nv_bfloat16* __restrict__ Bl,
               const float* __restrict__ bias, const int* __restrict__ segids,
               const float* __restrict__ seg_emb, float* __restrict__ outF,
               __nv_bfloat16* __restrict__ outH, __nv_bfloat16* __restrict__ outL) {
    extern __shared__ __align__(128) char sm[];
    const uint32_t sb = smem_u32(sm);
    const int tid = threadIdx.x, lane = tid & 31, w = tid >> 5;
    const int wmr = (w & 1) * 64, wnr = (w >> 1) * 32;
    const int n0 = blockIdx.x * 128, m0 = blockIdx.y * 128;
    const __nv_bfloat16* gAh = Ah + (size_t)m0 * HID;
    const __nv_bfloat16* gAl = Al + (size_t)m0 * HID;
    const __nv_bfloat16* gBh = Bh + (size_t)n0 * HID;
    const __nv_bfloat16* gBl = Bl + (size_t)n0 * HID;

    float acc[4][4][4] = {};
    load_stage<128>(sb + 0,     gAh, HID, tid);
    load_stage<128>(sb + 8192,  gAl, HID, tid);
    load_stage<128>(sb + 16384, gBh, HID, tid);
    load_stage<128>(sb + 24576, gBl, HID, tid);
    CP_COMMIT();
    const int NST = HID / 32;
    for (int s = 0; s < NST; s++) {
        const uint32_t cur = sb + (s & 1) * 32768;
        if (s + 1 < NST) {
            const uint32_t nxt = sb + ((s + 1) & 1) * 32768;
            const int ko = (s + 1) * 32;
            load_stage<128>(nxt + 0,     gAh + ko, HID, tid);
            load_stage<128>(nxt + 8192,  gAl + ko, HID, tid);
            load_stage<128>(nxt + 16384, gBh + ko, HID, tid);
            load_stage<128>(nxt + 24576, gBl + ko, HID, tid);
            CP_COMMIT();
            CP_WAIT(1);
        } else {
            CP_WAIT(0);
        }
        __syncthreads();
        stage_compute(cur, cur + 8192, cur + 16384, cur + 24576, wmr, wnr, lane, acc);
        __syncthreads();
    }

    const int mq = lane >> 2, nq = (lane & 3) * 2;
    #pragma unroll
    for (int mi = 0; mi < 4; mi++)
        #pragma unroll
        for (int half = 0; half < 2; half++) {
            const int m = m0 + wmr + mi * 16 + mq + half * 8;
            const int sid = (MODE == 1) ? segids[m] : 0;
            #pragma unroll
            for (int nj = 0; nj < 4; nj++) {
                const int n = n0 + wnr + nj * 8 + nq;
                float v0 = acc[mi][nj][half * 2 + 0] + bias[n];
                float v1 = acc[mi][nj][half * 2 + 1] + bias[n + 1];
                if (MODE == 1) {
                    v0 += seg_emb[(size_t)sid * HID + n];
                    v1 += seg_emb[(size_t)sid * HID + n + 1];
                }
                if (MODE == 0) { v0 *= 0.125f; v1 *= 0.125f; }
                if (MODE <= 1) {
                    __nv_bfloat162 h2, l2;
                    split2(v0, h2.x, l2.x);
                    split2(v1, h2.y, l2.y);
                    *(__nv_bfloat162*)(outH + (size_t)m * HID + n) = h2;
                    *(__nv_bfloat162*)(outL + (size_t)m * HID + n) = l2;
                } else {
                    *(float2*)(outF + (size_t)m * HID + n) = make_float2(v0, v1);
                }
            }
        }
}

// ---------------- scores: Sc[bh,t,s] = Q·K^T (scale folded into Q), K-dim 64 ----------------
__global__ __launch_bounds__(256)
void scores_gemm(const __nv_bfloat16* __restrict__ Qh, const __nv_bfloat16* __restrict__ Ql,
                 const __nv_bfloat16* __restrict__ Kh, const __nv_bfloat16* __restrict__ Kl,
                 const int* __restrict__ amask, float* __restrict__ Sc) {
    extern __shared__ __align__(128) char sm[];
    const uint32_t sb = smem_u32(sm);
    const int tid = threadIdx.x, lane = tid & 31, w = tid >> 5;
    const int wmr = (w & 1) * 64, wnr = (w >> 1) * 32;
    const int bh = blockIdx.z, b = bh >> 4, h = bh & 15;
    const int t0 = blockIdx.y * 128, s0 = blockIdx.x * 128;
    const __nv_bfloat16* gAh = Qh + (size_t)(b * T_LEN + t0) * HID + h * HD;
    const __nv_bfloat16* gAl = Ql + (size_t)(b * T_LEN + t0) * HID + h * HD;
    const __nv_bfloat16* gBh = Kh + (size_t)(b * S_LEN + s0) * HID + h * HD;
    const __nv_bfloat16* gBl = Kl + (size_t)(b * S_LEN + s0) * HID + h * HD;

    float acc[4][4][4] = {};
    load_stage<128>(sb + 0,     gAh, HID, tid);
    load_stage<128>(sb + 8192,  gAl, HID, tid);
    load_stage<128>(sb + 16384, gBh, HID, tid);
    load_stage<128>(sb + 24576, gBl, HID, tid);
    CP_COMMIT();
    for (int s = 0; s < 2; s++) {
        const uint32_t cur = sb + (s & 1) * 32768;
        if (s == 0) {
            const uint32_t nxt = sb + 32768;
            load_stage<128>(nxt + 0,     gAh + 32, HID, tid);
            load_stage<128>(nxt + 8192,  gAl + 32, HID, tid);
            load_stage<128>(nxt + 16384, gBh + 32, HID, tid);
            load_stage<128>(nxt + 24576, gBl + 32, HID, tid);
            CP_COMMIT();
            CP_WAIT(1);
        } else {
            CP_WAIT(0);
        }
        __syncthreads();
        stage_compute(cur, cur + 8192, cur + 16384, cur + 24576, wmr, wnr, lane, acc);
        __syncthreads();
    }

    const int mq = lane >> 2, nq = (lane & 3) * 2;
    float* dstB = Sc + (size_t)bh * T_LEN * S_LEN;
    #pragma unroll
    for (int mi = 0; mi < 4; mi++)
        #pragma unroll
        for (int half = 0; half < 2; half++) {
            const int t = t0 + wmr + mi * 16 + mq + half * 8;
            #pragma unroll
            for (int nj = 0; nj < 4; nj++) {
                const int sidx = s0 + wnr + nj * 8 + nq;
                float v0 = acc[mi][nj][half * 2 + 0];
                float v1 = acc[mi][nj][half * 2 + 1];
                if (amask[b * S_LEN + sidx] == 0) v0 = -1e9f;
                if (amask[b * S_LEN + sidx + 1] == 0) v1 = -1e9f;
                *(float2*)(dstB + (size_t)t * S_LEN + sidx) = make_float2(v0, v1);
            }
        }
}

// ---------------- P·V: C[256,64] tile, K=4096 ----------------
__global__ __launch_bounds__(256)
void pv_gemm(const __nv_bfloat16* __restrict__ Wh, const __nv_bfloat16* __restrict__ Wl,
             const __nv_bfloat16* __restrict__ Vth, const __nv_bfloat16* __restrict__ Vtl,
             __nv_bfloat16* __restrict__ attH, __nv_bfloat16* __restrict__ attL) {
    extern __shared__ __align__(128) char sm[];
    const uint32_t sb = smem_u32(sm);
    const int tid = threadIdx.x, lane = tid & 31, w = tid >> 5;
    const int wmr = (w & 3) * 64, wnr = (w >> 2) * 32;
    const int bh = blockIdx.y, b = bh >> 4, h = bh & 15;
    const int t0 = blockIdx.x * 256;
    const __nv_bfloat16* gAh = Wh + ((size_t)bh * T_LEN + t0) * S_LEN;
    const __nv_bfloat16* gAl = Wl + ((size_t)bh * T_LEN + t0) * S_LEN;
    const __nv_bfloat16* gBh = Vth + (size_t)bh * HD * S_LEN;
    const __nv_bfloat16* gBl = Vtl + (size_t)bh * HD * S_LEN;

    // stage: Ah 16K @0, Al 16K @16384, Bh 4K @32768, Bl 4K @36864 (stage=40960)
    float acc[4][4][4] = {};
    load_stage<256>(sb + 0,     gAh, S_LEN, tid);
    load_stage<256>(sb + 16384, gAl, S_LEN, tid);
    load_stage<64>(sb + 32768,  gBh, S_LEN, tid);
    load_stage<64>(sb + 36864,  gBl, S_LEN, tid);
    CP_COMMIT();
    const int NST = S_LEN / 32;
    for (int s = 0; s < NST; s++) {
        const uint32_t cur = sb + (s & 1) * 40960;
        if (s + 1 < NST) {
            const uint32_t nxt = sb + ((s + 1) & 1) * 40960;
            const int ko = (s + 1) * 32;
            load_stage<256>(nxt + 0,     gAh + ko, S_LEN, tid);
            load_stage<256>(nxt + 16384, gAl + ko, S_LEN, tid);
            load_stage<64>(nxt + 32768,  gBh + ko, S_LEN, tid);
            load_stage<64>(nxt + 36864,  gBl + ko, S_LEN, tid);
            CP_COMMIT();
            CP_WAIT(1);
        } else {
            CP_WAIT(0);
        }
        __syncthreads();
        stage_compute(cur, cur + 16384, cur + 32768, cur + 36864, wmr, wnr, lane, acc);
        __syncthreads();
    }

    const int mq = lane >> 2, nq = (lane & 3) * 2;
    #pragma unroll
    for (int mi = 0; mi < 4; mi++)
        #pragma unroll
        for (int half = 0; half < 2; half++) {
            const int t = t0 + wmr + mi * 16 + mq + half * 8;
            const size_t mo = (size_t)(b * T_LEN + t) * HID + h * HD;
            #pragma unroll
            for (int nj = 0; nj < 4; nj++) {
                const int n = wnr + nj * 8 + nq;
                __nv_bfloat162 h2, l2;
                split2(acc[mi][nj][half * 2 + 0], h2.x, l2.x);
                split2(acc[mi][nj][half * 2 + 1], h2.y, l2.y);
                *(__nv_bfloat162*)(attH + mo + n) = h2;
                *(__nv_bfloat162*)(attL + mo + n) = l2;
            }
        }
}

// ---------------- softmax -> hi/lo bf16 weights ----------------
__global__ __launch_bounds__(256)
void softmax_kernel(const float* __restrict__ Sc, __nv_bfloat16* __restrict__ Wh,
                    __nv_bfloat16* __restrict__ Wl) {
    const size_t base = (size_t)blockIdx.x * S_LEN;
    const int tid = threadIdx.x;
    __shared__ float red[8];
    float v[16];
    #pragma unroll
    for (int i = 0; i < 16; i++) v[i] = Sc[base + tid + i * 256];
    float m = -1e30f;
    #pragma unroll
    for (int i = 0; i < 16; i++) m = fmaxf(m, v[i]);
    #pragma unroll
    for (int o = 16; o; o >>= 1) m = fmaxf(m, __shfl_xor_sync(0xFFFFFFFFu, m, o));
    if ((tid & 31) == 0) red[tid >> 5] = m;
    __syncthreads();
    float gmax = red[0];
    #pragma unroll
    for (int w = 1; w < 8; w++) gmax = fmaxf(gmax, red[w]);
    __syncthreads();
    float s = 0.f;
    #pragma unroll
    for (int i = 0; i < 16; i++) { v[i] = expf(v[i] - gmax); s += v[i]; }
    #pragma unroll
    for (int o = 16; o; o >>= 1) s += __shfl_xor_sync(0xFFFFFFFFu, s, o);
    if ((tid & 31) == 0) red[tid >> 5] = s;
    __syncthreads();
    float tot = red[0];
    #pragma unroll
    for (int w = 1; w < 8; w++) tot += red[w];
    const float inv = 1.0f / tot;
    #pragma unroll
    for (int i = 0; i < 16; i++) {
        __nv_bfloat16 h, l;
        split2(v[i] * inv, h, l);
        Wh[base + tid + i * 256] = h;
        Wl[base + tid + i * 256] = l;
    }
}

// ---------------- provenance = head-mean of (hi+lo) ----------------
__global__ __launch_bounds__(256)
void provenance_kernel(const __nv_bfloat16* __restrict__ Wh,
                       const __nv_bfloat16* __restrict__ Wl, float* __restrict__ out) {
    const size_t u = (size_t)blockIdx.x * 256 + threadIdx.x;
    const int s2 = (int)(u & 2047);
    const int t  = (int)((u >> 11) & 511);
    const int b  = (int)(u >> 20);
    float s0 = 0.f, s1 = 0.f;
    #pragma unroll
    for (int h = 0; h < NH; h++) {
        const size_t o = (((size_t)(b * NH + h) * T_LEN + t) * S_LEN) / 2 + s2;
        __nv_bfloat162 h2 = reinterpret_cast<const __nv_bfloat162*>(Wh)[o];
        __nv_bfloat162 l2 = reinterpret_cast<const __nv_bfloat162*>(Wl)[o];
        s0 += __bfloat162float(h2.x) + __bfloat162float(l2.x);
        s1 += __bfloat162float(h2.y) + __bfloat162float(l2.y);
    }
    reinterpret_cast<float2*>(out)[u] = make_float2(s0 * (1.0f / NH), s1 * (1.0f / NH));
}

// ---------------------------------------------------------------------------
extern "C" void kernel_launch(void* const* d_in, const int* in_sizes, int n_in,
                              void* d_out, int out_size) {
    const float* query  = (const float*)d_in[0];
    const float* key    = (const float*)d_in[1];
    const float* value  = (const float*)d_in[2];
    const int*   amask  = (const int*)d_in[3];
    const int*   segids = (const int*)d_in[4];
    const float* Wq = (const float*)d_in[5];
    const float* bq = (const float*)d_in[6];
    const float* Wk = (const float*)d_in[7];
    const float* bk = (const float*)d_in[8];
    const float* Wv = (const float*)d_in[9];
    const float* bv = (const float*)d_in[10];
    const float* Wo = (const float*)d_in[11];
    const float* bo = (const float*)d_in[12];
    const float* seg_emb = (const float*)d_in[13];
    float* out = (float*)d_out;

    __nv_bfloat16 *qh, *ql, *kh, *kl, *vh, *vl;
    __nv_bfloat16 *wqh, *wql, *wkh, *wkl, *wvh, *wvl, *woh, *wol;
    __nv_bfloat16 *Qh, *Ql, *Kh, *Kl, *Vth, *Vtl, *Wh, *Wl, *ah, *al;
    float *Vf, *S;
    cudaGetSymbolAddress((void**)&qh, g_qh);   cudaGetSymbolAddress((void**)&ql, g_ql);
    cudaGetSymbolAddress((void**)&kh, g_kh);   cudaGetSymbolAddress((void**)&kl, g_kl);
    cudaGetSymbolAddress((void**)&vh, g_vh);   cudaGetSymbolAddress((void**)&vl, g_vl);
    cudaGetSymbolAddress((void**)&wqh, g_wqh); cudaGetSymbolAddress((void**)&wql, g_wql);
    cudaGetSymbolAddress((void**)&wkh, g_wkh); cudaGetSymbolAddress((void**)&wkl, g_wkl);
    cudaGetSymbolAddress((void**)&wvh, g_wvh); cudaGetSymbolAddress((void**)&wvl, g_wvl);
    cudaGetSymbolAddress((void**)&woh, g_woh); cudaGetSymbolAddress((void**)&wol, g_wol);
    cudaGetSymbolAddress((void**)&Qh, g_Qh);   cudaGetSymbolAddress((void**)&Ql, g_Ql);
    cudaGetSymbolAddress((void**)&Kh, g_Kh);   cudaGetSymbolAddress((void**)&Kl, g_Kl);
    cudaGetSymbolAddress((void**)&Vf, g_Vf);
    cudaGetSymbolAddress((void**)&Vth, g_Vth); cudaGetSymbolAddress((void**)&Vtl, g_Vtl);
    cudaGetSymbolAddress((void**)&S, g_S);
    cudaGetSymbolAddress((void**)&Wh, g_Wh);   cudaGetSymbolAddress((void**)&Wl, g_Wl);
    cudaGetSymbolAddress((void**)&ah, g_ah);   cudaGetSymbolAddress((void**)&al, g_al);

    cudaFuncSetAttribute(proj_gemm<0>, cudaFuncAttributeMaxDynamicSharedMemorySize, 65536);
    cudaFuncSetAttribute(proj_gemm<1>, cudaFuncAttributeMaxDynamicSharedMemorySize, 65536);
    cudaFuncSetAttribute(proj_gemm<2>, cudaFuncAttributeMaxDynamicSharedMemorySize, 65536);
    cudaFuncSetAttribute(scores_gemm, cudaFuncAttributeMaxDynamicSharedMemorySize, 65536);
    cudaFuncSetAttribute(pv_gemm, cudaFuncAttributeMaxDynamicSharedMemorySize, 81920);

    // input + weight conversions
    conv_split<<<4096, 256>>>(query, qh, ql);
    conv_split<<<32768, 256>>>(key, kh, kl);
    conv_split<<<32768, 256>>>(value, vh, vl);
    dim3 wtb(32, 8), wtg(32, 32);
    conv_wT<<<wtg, wtb>>>(Wq, wqh, wql);
    conv_wT<<<wtg, wtb>>>(Wk, wkh, wkl);
    conv_wT<<<wtg, wtb>>>(Wv, wvh, wvl);
    conv_wT<<<wtg, wtb>>>(Wo, woh, wol);

    // projections (tensor cores via mma.sync)
    proj_gemm<0><<<dim3(8, 16),  256, 65536>>>(qh, ql, wqh, wql, bq, nullptr, nullptr, nullptr, Qh, Ql);
    proj_gemm<1><<<dim3(8, 128), 256, 65536>>>(kh, kl, wkh, wkl, bk, segids, seg_emb, nullptr, Kh, Kl);
    proj_gemm<2><<<dim3(8, 128), 256, 65536>>>(vh, vl, wvh, wvl, bv, nullptr, nullptr, Vf, nullptr, nullptr);
    transpose_v<<<dim3(128, 2, 64), dim3(32, 8)>>>(Vf, Vth, Vtl);

    // attention
    scores_gemm<<<dim3(32, 4, 64), 256, 65536>>>(Qh, Ql, Kh, Kl, amask, S);
    softmax_kernel<<<NBH * T_LEN, 256>>>(S, Wh, Wl);
    provenance_kernel<<<16384, 256>>>(Wh, Wl, out + (size_t)2048 * HID);
    pv_gemm<<<dim3(2, 64), 256, 81920>>>(Wh, Wl, Vth, Vtl, ah, al);

    // output projection -> d_out
    proj_gemm<2><<<dim3(8, 16), 256, 65536>>>(ah, al, woh, wol, bo, nullptr, nullptr, out, nullptr, nullptr);
}

// round 5
// speedup vs baseline: 2.9088x; 1.0364x over previous
#include <cuda_runtime.h>
#include <cuda_fp16.h>
#include <cstdint>
#include <cstddef>

#define B_SZ   4
#define T_LEN  512
#define S_LEN  4096
#define HID    1024
#define NH     16
#define HD     64
#define NBH    (B_SZ * NH)
#define CHUNK_H 8                 // heads per L2-resident score chunk

// ---------------------------------------------------------------------------
// helpers
// ---------------------------------------------------------------------------
__device__ __forceinline__ uint32_t smem_u32(const void* p) {
    uint32_t a;
    asm("{ .reg .u64 t; cvta.to.shared.u64 t, %1; cvt.u32.u64 %0, t; }" : "=r"(a) : "l"(p));
    return a;
}
// 64B-row tile swizzle (A operand / K-major tiles)
__device__ __forceinline__ uint32_t swzoff(int row, int chunk) {
    const int v = (row & 3) ^ ((row >> 2) & 1);
    return (uint32_t)(row * 64 + (((chunk ^ v) & 3) << 4));
}
__device__ __forceinline__ void cpa16(uint32_t dst, const void* src) {
    asm volatile("cp.async.cg.shared.global [%0], [%1], 16;" :: "r"(dst), "l"(src));
}
#define CP_COMMIT() asm volatile("cp.async.commit_group;" ::: "memory")
#define CP_WAIT(n)  asm volatile("cp.async.wait_group %0;" :: "n"(n) : "memory")

__device__ __forceinline__ void ldsm4(uint32_t* r, uint32_t a) {
    asm volatile("ldmatrix.sync.aligned.m8n8.x4.shared.b16 {%0,%1,%2,%3}, [%4];"
                 : "=r"(r[0]), "=r"(r[1]), "=r"(r[2]), "=r"(r[3]) : "r"(a));
}
__device__ __forceinline__ void ldsm4t(uint32_t* r, uint32_t a) {
    asm volatile("ldmatrix.sync.aligned.m8n8.x4.trans.shared.b16 {%0,%1,%2,%3}, [%4];"
                 : "=r"(r[0]), "=r"(r[1]), "=r"(r[2]), "=r"(r[3]) : "r"(a));
}
__device__ __forceinline__ void mma_f16(float* d, const uint32_t* a, const uint32_t* b) {
    asm volatile("mma.sync.aligned.m16n8k16.row.col.f32.f16.f16.f32 "
                 "{%0,%1,%2,%3}, {%4,%5,%6,%7}, {%8,%9}, {%0,%1,%2,%3};"
                 : "+f"(d[0]), "+f"(d[1]), "+f"(d[2]), "+f"(d[3])
                 : "r"(a[0]), "r"(a[1]), "r"(a[2]), "r"(a[3]), "r"(b[0]), "r"(b[1]));
}
__device__ __forceinline__ void split2h(float v, __half& h, __half& l) {
    h = __float2half_rn(v);
    l = __float2half_rn(v - __half2float(h));
}

// Load a [ROWS x 32] fp16 tile (row stride = stride elems) into swizzled SMEM
template<int ROWS>
__device__ __forceinline__ void load_stage(uint32_t sbuf, const __half* g,
                                           int stride, int tid) {
    #pragma unroll
    for (int i = tid; i < ROWS * 4; i += 256) {
        const int row = i >> 2, ch = i & 3;
        cpa16(sbuf + swzoff(row, ch), g + (size_t)row * stride + ch * 8);
    }
}
// Load a [32 x 64] fp16 tile (128B rows, chunk-XOR swizzle) for trans-B (V)
__device__ __forceinline__ void load_vtile(uint32_t sbuf, const __half* g,
                                           int stride, int tid) {
    if (tid < 256) {
        const int row = tid >> 3, ch = tid & 7;
        cpa16(sbuf + (uint32_t)(row * 128 + (((ch ^ row) & 7) << 4)),
              g + (size_t)row * stride + ch * 8);
    }
}

// One 32-k stage, both operands K-major via non-trans ldmatrix.  3 products.
__device__ __forceinline__ void stage_compute(uint32_t sAh, uint32_t sAl,
                                              uint32_t sBh, uint32_t sBl,
                                              int wmr, int wnr, int lane,
                                              float (*acc)[4][4]) {
    const int l7 = lane & 7, l8 = (lane >> 3) & 1, l16 = (lane >> 4) & 1;
    const int arow = wmr + l7 + l8 * 8;
    const int brow = wnr + l16 * 8 + l7;
    #pragma unroll
    for (int ks = 0; ks < 2; ks++) {
        uint32_t ah[4][4], al[4][4], bh[2][4], bl[2][4];
        #pragma unroll
        for (int mi = 0; mi < 4; mi++) {
            const uint32_t off = swzoff(arow + mi * 16, ks * 2 + l16);
            ldsm4(ah[mi], sAh + off);
            ldsm4(al[mi], sAl + off);
        }
        #pragma unroll
        for (int p = 0; p < 2; p++) {
            const uint32_t off = swzoff(brow + p * 16, ks * 2 + l8);
            ldsm4(bh[p], sBh + off);
            ldsm4(bl[p], sBl + off);
        }
        #pragma unroll
        for (int mi = 0; mi < 4; mi++)
            #pragma unroll
            for (int nj = 0; nj < 4; nj++) {
                const uint32_t* bhj = &bh[nj >> 1][(nj & 1) * 2];
                const uint32_t* blj = &bl[nj >> 1][(nj & 1) * 2];
                mma_f16(acc[mi][nj], ah[mi], bhj);
                mma_f16(acc[mi][nj], ah[mi], blj);
                mma_f16(acc[mi][nj], al[mi], bhj);
            }
    }
}

// One 32-k stage for PV: A K-major, B = V tile [32k x 64n] via ldmatrix.trans
__device__ __forceinline__ void pv_stage(uint32_t sAh, uint32_t sAl,
                                         uint32_t sBh, uint32_t sBl,
                                         int wmr, int wnr, int lane,
                                         float (*acc)[4][4]) {
    const int l7 = lane & 7, l8 = (lane >> 3) & 1, l16 = (lane >> 4) & 1;
    const int arow = wmr + l7 + l8 * 8;
    const int g = lane >> 3, q = lane & 7;
    #pragma unroll
    for (int ks = 0; ks < 2; ks++) {
        uint32_t ah[4][4], al[4][4];
        #pragma unroll
        for (int mi = 0; mi < 4; mi++) {
            const uint32_t off = swzoff(arow + mi * 16, ks * 2 + l16);
            ldsm4(ah[mi], sAh + off);
            ldsm4(al[mi], sAl + off);
        }
        #pragma unroll
        for (int half = 0; half < 2; half++) {
            const int r = ks * 16 + (g & 1) * 8 + q;
            const int cb = ((wnr + half * 16) >> 3) + (g >> 1);
            const uint32_t off = (uint32_t)(r * 128 + (((cb ^ r) & 7) << 4));
            uint32_t bh4[4], bl4[4];
            ldsm4t(bh4, sBh + off);
            ldsm4t(bl4, sBl + off);
            #pragma unroll
            for (int mi = 0; mi < 4; mi++)
                #pragma unroll
                for (int u = 0; u < 2; u++) {
                    const int nj = half * 2 + u;
                    mma_f16(acc[mi][nj], ah[mi], &bh4[u * 2]);
                    mma_f16(acc[mi][nj], ah[mi], &bl4[u * 2]);
                    mma_f16(acc[mi][nj], al[mi], &bh4[u * 2]);
                }
        }
    }
}

// ---------------- scratch ----------------
__device__ __half g_qh[2048 * HID],  g_ql[2048 * HID];
__device__ __half g_kh[16384 * HID], g_kl[16384 * HID];
__device__ __half g_vh[16384 * HID], g_vl[16384 * HID];
__device__ __half g_wqh[HID * HID], g_wql[HID * HID];
__device__ __half g_wkh[HID * HID], g_wkl[HID * HID];
__device__ __half g_wvh[HID * HID], g_wvl[HID * HID];
__device__ __half g_woh[HID * HID], g_wol[HID * HID];
__device__ __half g_Qh[2048 * HID],  g_Ql[2048 * HID];
__device__ __half g_Kh[16384 * HID], g_Kl[16384 * HID];
__device__ __half g_Vh[16384 * HID], g_Vl[16384 * HID];
__device__ float  g_Ssc[(size_t)CHUNK_H * T_LEN * S_LEN];          // 64 MB reused
__device__ __half g_Wh[(size_t)NBH * T_LEN * S_LEN], g_Wl[(size_t)NBH * T_LEN * S_LEN];
__device__ __half g_ah[2048 * HID], g_al[2048 * HID];

// ---------------- conversions ----------------
__global__ __launch_bounds__(256)
void conv_split(const float* __restrict__ X, __half* __restrict__ H,
                __half* __restrict__ L) {
    const size_t u = (size_t)blockIdx.x * 256 + threadIdx.x;
    float2 v = reinterpret_cast<const float2*>(X)[u];
    __half2 h2, l2;
    split2h(v.x, h2.x, l2.x);
    split2h(v.y, h2.y, l2.y);
    reinterpret_cast<__half2*>(H)[u] = h2;
    reinterpret_cast<__half2*>(L)[u] = l2;
}
__global__ __launch_bounds__(256)
void conv_wT(const float* __restrict__ W, __half* __restrict__ WTh,
             __half* __restrict__ WTl) {
    __shared__ float t[32][33];
    const int k0 = blockIdx.x * 32, n0 = blockIdx.y * 32;
    const int tx = threadIdx.x, ty = threadIdx.y;
    for (int r = ty; r < 32; r += 8) t[r][tx] = W[(size_t)(k0 + r) * HID + n0 + tx];
    __syncthreads();
    for (int r = ty; r < 32; r += 8) {
        __half h, l;
        split2h(t[tx][r], h, l);
        WTh[(size_t)(n0 + r) * HID + k0 + tx] = h;
        WTl[(size_t)(n0 + r) * HID + k0 + tx] = l;
    }
}

// ---------------- projection GEMM (3-stage pipeline) ----------------
// MODE 0: Q (bias, *0.125, fp16 out) 1: K (bias+seg, fp16 out) 2: O (fp32 out) 3: V (bias, fp16 out)
template<int MODE>
__global__ __launch_bounds__(256)
void proj_gemm(const __half* __restrict__ Ah, const __half* __restrict__ Al,
               const __half* __restrict__ Bh, const __half* __restrict__ Bl,
               const float* __restrict__ bias, const int* __restrict__ segids,
               const float* __restrict__ seg_emb, float* __restrict__ outF,
               __half* __restrict__ outH, __half* __restrict__ outL) {
    extern __shared__ __align__(128) char sm[];
    const uint32_t sb = smem_u32(sm);
    const int tid = threadIdx.x, lane = tid & 31, w = tid >> 5;
    const int wmr = (w & 1) * 64, wnr = (w >> 1) * 32;
    const int n0 = blockIdx.x * 128, m0 = blockIdx.y * 128;
    const __half* gAh = Ah + (size_t)m0 * HID;
    const __half* gAl = Al + (size_t)m0 * HID;
    const __half* gBh = Bh + (size_t)n0 * HID;
    const __half* gBl = Bl + (size_t)n0 * HID;

#define PJ_LOAD(st, ko) do {                                \
    const uint32_t b_ = sb + ((st) % 3) * 32768;            \
    load_stage<128>(b_ + 0,     gAh + (ko), HID, tid);      \
    load_stage<128>(b_ + 8192,  gAl + (ko), HID, tid);      \
    load_stage<128>(b_ + 16384, gBh + (ko), HID, tid);      \
    load_stage<128>(b_ + 24576, gBl + (ko), HID, tid);      \
    CP_COMMIT();                                            \
  } while (0)

    float acc[4][4][4] = {};
    PJ_LOAD(0, 0);
    PJ_LOAD(1, 32);
    const int NST = HID / 32;
    for (int s = 0; s < NST; s++) {
        if (s + 2 < NST) { PJ_LOAD(s + 2, (s + 2) * 32); CP_WAIT(2); }
        else if (s + 1 < NST) { CP_WAIT(1); }
        else { CP_WAIT(0); }
        __syncthreads();
        const uint32_t cur = sb + (s % 3) * 32768;
        stage_compute(cur, cur + 8192, cur + 16384, cur + 24576, wmr, wnr, lane, acc);
        __syncthreads();
    }
#undef PJ_LOAD

    const int mq = lane >> 2, nq = (lane & 3) * 2;
    #pragma unroll
    for (int mi = 0; mi < 4; mi++)
        #pragma unroll
        for (int half = 0; half < 2; half++) {
            const int m = m0 + wmr + mi * 16 + mq + half * 8;
            const int sid = (MODE == 1) ? segids[m] : 0;
            #pragma unroll
            for (int nj = 0; nj < 4; nj++) {
                const int n = n0 + wnr + nj * 8 + nq;
                float v0 = acc[mi][nj][half * 2 + 0] + bias[n];
                float v1 = acc[mi][nj][half * 2 + 1] + bias[n + 1];
                if (MODE == 1) {
                    v0 += seg_emb[(size_t)sid * HID + n];
                    v1 += seg_emb[(size_t)sid * HID + n + 1];
                }
                if (MODE == 0) { v0 *= 0.125f; v1 *= 0.125f; }
                if (MODE != 2) {
                    __half2 h2, l2;
                    split2h(v0, h2.x, l2.x);
                    split2h(v1, h2.y, l2.y);
                    *(__half2*)(outH + (size_t)m * HID + n) = h2;
                    *(__half2*)(outL + (size_t)m * HID + n) = l2;
                } else {
                    *(float2*)(outF + (size_t)m * HID + n) = make_float2(v0, v1);
                }
            }
        }
}

// ---------------- scores chunk: Sc[z,t,s] = Q·K^T (scale folded into Q) ----------------
__global__ __launch_bounds__(256)
void scores_gemm(const __half* __restrict__ Qh, const __half* __restrict__ Ql,
                 const __half* __restrict__ Kh, const __half* __restrict__ Kl,
                 const int* __restrict__ amask, float* __restrict__ Sc, int bh0) {
    extern __shared__ __align__(128) char sm[];
    const uint32_t sb = smem_u32(sm);
    const int tid = threadIdx.x, lane = tid & 31, w = tid >> 5;
    const int wmr = (w & 1) * 64, wnr = (w >> 1) * 32;
    const int zz = blockIdx.z, bh = bh0 + zz, b = bh >> 4, h = bh & 15;
    const int t0 = blockIdx.y * 128, s0 = blockIdx.x * 128;
    const __half* gAh = Qh + (size_t)(b * T_LEN + t0) * HID + h * HD;
    const __half* gAl = Ql + (size_t)(b * T_LEN + t0) * HID + h * HD;
    const __half* gBh = Kh + (size_t)(b * S_LEN + s0) * HID + h * HD;
    const __half* gBl = Kl + (size_t)(b * S_LEN + s0) * HID + h * HD;

    float acc[4][4][4] = {};
    load_stage<128>(sb + 0,     gAh, HID, tid);
    load_stage<128>(sb + 8192,  gAl, HID, tid);
    load_stage<128>(sb + 16384, gBh, HID, tid);
    load_stage<128>(sb + 24576, gBl, HID, tid);
    CP_COMMIT();
    for (int s = 0; s < 2; s++) {
        const uint32_t cur = sb + (s & 1) * 32768;
        if (s == 0) {
            const uint32_t nxt = sb + 32768;
            load_stage<128>(nxt + 0,     gAh + 32, HID, tid);
            load_stage<128>(nxt + 8192,  gAl + 32, HID, tid);
            load_stage<128>(nxt + 16384, gBh + 32, HID, tid);
            load_stage<128>(nxt + 24576, gBl + 32, HID, tid);
            CP_COMMIT();
            CP_WAIT(1);
        } else {
            CP_WAIT(0);
        }
        __syncthreads();
        stage_compute(cur, cur + 8192, cur + 16384, cur + 24576, wmr, wnr, lane, acc);
        __syncthreads();
    }

    const int mq = lane >> 2, nq = (lane & 3) * 2;
    float* dstB = Sc + (size_t)zz * T_LEN * S_LEN;
    #pragma unroll
    for (int mi = 0; mi < 4; mi++)
        #pragma unroll
        for (int half = 0; half < 2; half++) {
            const int t = t0 + wmr + mi * 16 + mq + half * 8;
            #pragma unroll
            for (int nj = 0; nj < 4; nj++) {
                const int sidx = s0 + wnr + nj * 8 + nq;
                float v0 = acc[mi][nj][half * 2 + 0];
                float v1 = acc[mi][nj][half * 2 + 1];
                if (amask[b * S_LEN + sidx] == 0) v0 = -1e9f;
                if (amask[b * S_LEN + sidx + 1] == 0) v1 = -1e9f;
                *(float2*)(dstB + (size_t)t * S_LEN + sidx) = make_float2(v0, v1);
            }
        }
}

// ---------------- softmax chunk: scratch row -> fp16 hi/lo weights ----------------
__global__ __launch_bounds__(256)
void softmax_kernel(const float* __restrict__ Sc, __half* __restrict__ Wh,
                    __half* __restrict__ Wl, int bh0) {
    const int r = blockIdx.x, z = r >> 9, t = r & 511;
    const size_t sbase = ((size_t)z * T_LEN + t) * S_LEN;
    const size_t wbase = ((size_t)(bh0 + z) * T_LEN + t) * S_LEN;
    const int tid = threadIdx.x;
    __shared__ float red[8];
    float v[16];
    #pragma unroll
    for (int i = 0; i < 16; i++) v[i] = Sc[sbase + tid + i * 256];
    float m = -1e30f;
    #pragma unroll
    for (int i = 0; i < 16; i++) m = fmaxf(m, v[i]);
    #pragma unroll
    for (int o = 16; o; o >>= 1) m = fmaxf(m, __shfl_xor_sync(0xFFFFFFFFu, m, o));
    if ((tid & 31) == 0) red[tid >> 5] = m;
    __syncthreads();
    float gmax = red[0];
    #pragma unroll
    for (int w = 1; w < 8; w++) gmax = fmaxf(gmax, red[w]);
    __syncthreads();
    float s = 0.f;
    #pragma unroll
    for (int i = 0; i < 16; i++) { v[i] = expf(v[i] - gmax); s += v[i]; }
    #pragma unroll
    for (int o = 16; o; o >>= 1) s += __shfl_xor_sync(0xFFFFFFFFu, s, o);
    if ((tid & 31) == 0) red[tid >> 5] = s;
    __syncthreads();
    float tot = red[0];
    #pragma unroll
    for (int w = 1; w < 8; w++) tot += red[w];
    const float inv = 1.0f / tot;
    #pragma unroll
    for (int i = 0; i < 16; i++) {
        __half h, l;
        split2h(v[i] * inv, h, l);
        Wh[wbase + tid + i * 256] = h;
        Wl[wbase + tid + i * 256] = l;
    }
}

// ---------------- provenance = head-mean of Wh (fp16 hi only) ----------------
__global__ __launch_bounds__(256)
void provenance_kernel(const __half* __restrict__ Wh, float* __restrict__ out) {
    const size_t u = (size_t)blockIdx.x * 256 + threadIdx.x;
    const int s2 = (int)(u & 2047);
    const int t  = (int)((u >> 11) & 511);
    const int b  = (int)(u >> 20);
    float s0 = 0.f, s1 = 0.f;
    #pragma unroll
    for (int h = 0; h < NH; h++) {
        const size_t o = (((size_t)(b * NH + h) * T_LEN + t) * S_LEN) / 2 + s2;
        __half2 h2 = reinterpret_cast<const __half2*>(Wh)[o];
        s0 += __half2float(h2.x);
        s1 += __half2float(h2.y);
    }
    reinterpret_cast<float2*>(out)[u] = make_float2(s0 * (1.0f / NH), s1 * (1.0f / NH));
}

// ---------------- P·V: C[256,64] per CTA, K=4096, B via ldmatrix.trans ----------------
__global__ __launch_bounds__(256)
void pv_gemm(const __half* __restrict__ Wh, const __half* __restrict__ Wl,
             const __half* __restrict__ Vh, const __half* __restrict__ Vl,
             __half* __restrict__ attH, __half* __restrict__ attL) {
    extern __shared__ __align__(128) char sm[];
    const uint32_t sb = smem_u32(sm);
    const int tid = threadIdx.x, lane = tid & 31, w = tid >> 5;
    const int wmr = (w & 3) * 64, wnr = (w >> 2) * 32;
    const int bh = blockIdx.y, b = bh >> 4, h = bh & 15;
    const int t0 = blockIdx.x * 256;
    const __half* gAh = Wh + ((size_t)bh * T_LEN + t0) * S_LEN;
    const __half* gAl = Wl + ((size_t)bh * T_LEN + t0) * S_LEN;
    const __half* gBh = Vh + (size_t)(b * S_LEN) * HID + h * HD;
    const __half* gBl = Vl + (size_t)(b * S_LEN) * HID + h * HD;

#define PV_LOAD(st, ko) do {                                              \
    const uint32_t b_ = sb + ((st) & 1) * 40960;                          \
    load_stage<256>(b_ + 0,     gAh + (ko), S_LEN, tid);                  \
    load_stage<256>(b_ + 16384, gAl + (ko), S_LEN, tid);                  \
    load_vtile(b_ + 32768, gBh + (size_t)(ko) * HID, HID, tid);           \
    load_vtile(b_ + 36864, gBl + (size_t)(ko) * HID, HID, tid);           \
    CP_COMMIT();                                                          \
  } while (0)

    float acc[4][4][4] = {};
    PV_LOAD(0, 0);
    const int NST = S_LEN / 32;
    for (int s = 0; s < NST; s++) {
        if (s + 1 < NST) { PV_LOAD(s + 1, (s + 1) * 32); CP_WAIT(1); }
        else { CP_WAIT(0); }
        __syncthreads();
        const uint32_t cur = sb + (s & 1) * 40960;
        pv_stage(cur, cur + 16384, cur + 32768, cur + 36864, wmr, wnr, lane, acc);
        __syncthreads();
    }
#undef PV_LOAD

    const int mq = lane >> 2, nq = (lane & 3) * 2;
    #pragma unroll
    for (int mi = 0; mi < 4; mi++)
        #pragma unroll
        for (int half = 0; half < 2; half++) {
            const int t = t0 + wmr + mi * 16 + mq + half * 8;
            const size_t mo = (size_t)(b * T_LEN + t) * HID + h * HD;
            #pragma unroll
            for (int nj = 0; nj < 4; nj++) {
                const int n = wnr + nj * 8 + nq;
                __half2 h2, l2;
                split2h(acc[mi][nj][half * 2 + 0], h2.x, l2.x);
                split2h(acc[mi][nj][half * 2 + 1], h2.y, l2.y);
                *(__half2*)(attH + mo + n) = h2;
                *(__half2*)(attL + mo + n) = l2;
            }
        }
}

// ---------------------------------------------------------------------------
extern "C" void kernel_launch(void* const* d_in, const int* in_sizes, int n_in,
                              void* d_out, int out_size) {
    const float* query  = (const float*)d_in[0];
    const float* key    = (const float*)d_in[1];
    const float* value  = (const float*)d_in[2];
    const int*   amask  = (const int*)d_in[3];
    const int*   segids = (const int*)d_in[4];
    const float* Wq = (const float*)d_in[5];
    const float* bq = (const float*)d_in[6];
    const float* Wk = (const float*)d_in[7];
    const float* bk = (const float*)d_in[8];
    const float* Wv = (const float*)d_in[9];
    const float* bv = (const float*)d_in[10];
    const float* Wo = (const float*)d_in[11];
    const float* bo = (const float*)d_in[12];
    const float* seg_emb = (const float*)d_in[13];
    float* out = (float*)d_out;

    __half *qh, *ql, *kh, *kl, *vh, *vl;
    __half *wqh, *wql, *wkh, *wkl, *wvh, *wvl, *woh, *wol;
    __half *Qh, *Ql, *Kh, *Kl, *Vh, *Vl, *Wh, *Wl, *ah, *al;
    float *Ssc;
    cudaGetSymbolAddress((void**)&qh, g_qh);   cudaGetSymbolAddress((void**)&ql, g_ql);
    cudaGetSymbolAddress((void**)&kh, g_kh);   cudaGetSymbolAddress((void**)&kl, g_kl);
    cudaGetSymbolAddress((void**)&vh, g_vh);   cudaGetSymbolAddress((void**)&vl, g_vl);
    cudaGetSymbolAddress((void**)&wqh, g_wqh); cudaGetSymbolAddress((void**)&wql, g_wql);
    cudaGetSymbolAddress((void**)&wkh, g_wkh); cudaGetSymbolAddress((void**)&wkl, g_wkl);
    cudaGetSymbolAddress((void**)&wvh, g_wvh); cudaGetSymbolAddress((void**)&wvl, g_wvl);
    cudaGetSymbolAddress((void**)&woh, g_woh); cudaGetSymbolAddress((void**)&wol, g_wol);
    cudaGetSymbolAddress((void**)&Qh, g_Qh);   cudaGetSymbolAddress((void**)&Ql, g_Ql);
    cudaGetSymbolAddress((void**)&Kh, g_Kh);   cudaGetSymbolAddress((void**)&Kl, g_Kl);
    cudaGetSymbolAddress((void**)&Vh, g_Vh);   cudaGetSymbolAddress((void**)&Vl, g_Vl);
    cudaGetSymbolAddress((void**)&Ssc, g_Ssc);
    cudaGetSymbolAddress((void**)&Wh, g_Wh);   cudaGetSymbolAddress((void**)&Wl, g_Wl);
    cudaGetSymbolAddress((void**)&ah, g_ah);   cudaGetSymbolAddress((void**)&al, g_al);

    cudaFuncSetAttribute(proj_gemm<0>, cudaFuncAttributeMaxDynamicSharedMemorySize, 98304);
    cudaFuncSetAttribute(proj_gemm<1>, cudaFuncAttributeMaxDynamicSharedMemorySize, 98304);
    cudaFuncSetAttribute(proj_gemm<2>, cudaFuncAttributeMaxDynamicSharedMemorySize, 98304);
    cudaFuncSetAttribute(proj_gemm<3>, cudaFuncAttributeMaxDynamicSharedMemorySize, 98304);
    cudaFuncSetAttribute(scores_gemm, cudaFuncAttributeMaxDynamicSharedMemorySize, 65536);
    cudaFuncSetAttribute(pv_gemm, cudaFuncAttributeMaxDynamicSharedMemorySize, 81920);

    // input + weight conversions (fp16 hi/lo)
    conv_split<<<4096, 256>>>(query, qh, ql);
    conv_split<<<32768, 256>>>(key, kh, kl);
    conv_split<<<32768, 256>>>(value, vh, vl);
    dim3 wtb(32, 8), wtg(32, 32);
    conv_wT<<<wtg, wtb>>>(Wq, wqh, wql);
    conv_wT<<<wtg, wtb>>>(Wk, wkh, wkl);
    conv_wT<<<wtg, wtb>>>(Wv, wvh, wvl);
    conv_wT<<<wtg, wtb>>>(Wo, woh, wol);

    // projections
    proj_gemm<0><<<dim3(8, 16),  256, 98304>>>(qh, ql, wqh, wql, bq, nullptr, nullptr, nullptr, Qh, Ql);
    proj_gemm<1><<<dim3(8, 128), 256, 98304>>>(kh, kl, wkh, wkl, bk, segids, seg_emb, nullptr, Kh, Kl);
    proj_gemm<3><<<dim3(8, 128), 256, 98304>>>(vh, vl, wvh, wvl, bv, nullptr, nullptr, nullptr, Vh, Vl);

    // attention: L2-blocked scores -> softmax per 8-head chunk (reused scratch)
    for (int c = 0; c < NBH / CHUNK_H; c++) {
        const int bh0 = c * CHUNK_H;
        scores_gemm<<<dim3(32, 4, CHUNK_H), 256, 65536>>>(Qh, Ql, Kh, Kl, amask, Ssc, bh0);
        softmax_kernel<<<CHUNK_H * T_LEN, 256>>>(Ssc, Wh, Wl, bh0);
    }
    provenance_kernel<<<16384, 256>>>(Wh, out + (size_t)2048 * HID);
    pv_gemm<<<dim3(2, 64), 256, 81920>>>(Wh, Wl, Vh, Vl, ah, al);

    // output projection -> d_out
    proj_gemm<2><<<dim3(8, 16), 256, 98304>>>(ah, al, woh, wol, bo, nullptr, nullptr, out, nullptr, nullptr);
}

// round 6
// speedup vs baseline: 3.3436x; 1.1495x over previous
#include <cuda_runtime.h>
#include <cuda_fp16.h>
#include <cstdint>
#include <cstddef>

#define B_SZ   4
#define T_LEN  512
#define S_LEN  4096
#define HID    1024
#define NH     16
#define HD     64
#define NBH    (B_SZ * NH)
#define CHUNK_H 8                 // heads per L2-resident score chunk

// ---------------------------------------------------------------------------
// helpers
// ---------------------------------------------------------------------------
__device__ __forceinline__ uint32_t smem_u32(const void* p) {
    uint32_t a;
    asm("{ .reg .u64 t; cvta.to.shared.u64 t, %1; cvt.u32.u64 %0, t; }" : "=r"(a) : "l"(p));
    return a;
}
// 64B-row tile swizzle (A operand / K-major tiles)
__device__ __forceinline__ uint32_t swzoff(int row, int chunk) {
    const int v = (row & 3) ^ ((row >> 2) & 1);
    return (uint32_t)(row * 64 + (((chunk ^ v) & 3) << 4));
}
__device__ __forceinline__ void cpa16(uint32_t dst, const void* src) {
    asm volatile("cp.async.cg.shared.global [%0], [%1], 16;" :: "r"(dst), "l"(src));
}
#define CP_COMMIT() asm volatile("cp.async.commit_group;" ::: "memory")
#define CP_WAIT(n)  asm volatile("cp.async.wait_group %0;" :: "n"(n) : "memory")

__device__ __forceinline__ void ldsm4(uint32_t* r, uint32_t a) {
    asm volatile("ldmatrix.sync.aligned.m8n8.x4.shared.b16 {%0,%1,%2,%3}, [%4];"
                 : "=r"(r[0]), "=r"(r[1]), "=r"(r[2]), "=r"(r[3]) : "r"(a));
}
__device__ __forceinline__ void ldsm4t(uint32_t* r, uint32_t a) {
    asm volatile("ldmatrix.sync.aligned.m8n8.x4.trans.shared.b16 {%0,%1,%2,%3}, [%4];"
                 : "=r"(r[0]), "=r"(r[1]), "=r"(r[2]), "=r"(r[3]) : "r"(a));
}
__device__ __forceinline__ void mma_f16(float* d, const uint32_t* a, const uint32_t* b) {
    asm volatile("mma.sync.aligned.m16n8k16.row.col.f32.f16.f16.f32 "
                 "{%0,%1,%2,%3}, {%4,%5,%6,%7}, {%8,%9}, {%0,%1,%2,%3};"
                 : "+f"(d[0]), "+f"(d[1]), "+f"(d[2]), "+f"(d[3])
                 : "r"(a[0]), "r"(a[1]), "r"(a[2]), "r"(a[3]), "r"(b[0]), "r"(b[1]));
}
__device__ __forceinline__ void split2h(float v, __half& h, __half& l) {
    h = __float2half_rn(v);
    l = __float2half_rn(v - __half2float(h));
}

// Load a [ROWS x 32] fp16 tile (row stride = stride elems) into swizzled SMEM
template<int ROWS>
__device__ __forceinline__ void load_stage(uint32_t sbuf, const __half* g,
                                           int stride, int tid) {
    #pragma unroll
    for (int i = tid; i < ROWS * 4; i += 256) {
        const int row = i >> 2, ch = i & 3;
        cpa16(sbuf + swzoff(row, ch), g + (size_t)row * stride + ch * 8);
    }
}
// Load a [32 x 64] fp16 tile (128B rows, chunk-XOR swizzle) for trans-B (V)
__device__ __forceinline__ void load_vtile(uint32_t sbuf, const __half* g,
                                           int stride, int tid) {
    if (tid < 256) {
        const int row = tid >> 3, ch = tid & 7;
        cpa16(sbuf + (uint32_t)(row * 128 + (((ch ^ row) & 7) << 4)),
              g + (size_t)row * stride + ch * 8);
    }
}

// One 32-k stage, A hi/lo + B hi/lo, 3 products.
__device__ __forceinline__ void stage_compute(uint32_t sAh, uint32_t sAl,
                                              uint32_t sBh, uint32_t sBl,
                                              int wmr, int wnr, int lane,
                                              float (*acc)[4][4]) {
    const int l7 = lane & 7, l8 = (lane >> 3) & 1, l16 = (lane >> 4) & 1;
    const int arow = wmr + l7 + l8 * 8;
    const int brow = wnr + l16 * 8 + l7;
    #pragma unroll
    for (int ks = 0; ks < 2; ks++) {
        uint32_t ah[4][4], al[4][4], bh[2][4], bl[2][4];
        #pragma unroll
        for (int mi = 0; mi < 4; mi++) {
            const uint32_t off = swzoff(arow + mi * 16, ks * 2 + l16);
            ldsm4(ah[mi], sAh + off);
            ldsm4(al[mi], sAl + off);
        }
        #pragma unroll
        for (int p = 0; p < 2; p++) {
            const uint32_t off = swzoff(brow + p * 16, ks * 2 + l8);
            ldsm4(bh[p], sBh + off);
            ldsm4(bl[p], sBl + off);
        }
        #pragma unroll
        for (int mi = 0; mi < 4; mi++)
            #pragma unroll
            for (int nj = 0; nj < 4; nj++) {
                const uint32_t* bhj = &bh[nj >> 1][(nj & 1) * 2];
                const uint32_t* blj = &bl[nj >> 1][(nj & 1) * 2];
                mma_f16(acc[mi][nj], ah[mi], bhj);
                mma_f16(acc[mi][nj], ah[mi], blj);
                mma_f16(acc[mi][nj], al[mi], bhj);
            }
    }
}

// One 32-k stage, A single + B hi/lo, 2 products (V projection).
__device__ __forceinline__ void stage_compute_v(uint32_t sA,
                                                uint32_t sBh, uint32_t sBl,
                                                int wmr, int wnr, int lane,
                                                float (*acc)[4][4]) {
    const int l7 = lane & 7, l8 = (lane >> 3) & 1, l16 = (lane >> 4) & 1;
    const int arow = wmr + l7 + l8 * 8;
    const int brow = wnr + l16 * 8 + l7;
    #pragma unroll
    for (int ks = 0; ks < 2; ks++) {
        uint32_t ah[4][4], bh[2][4], bl[2][4];
        #pragma unroll
        for (int mi = 0; mi < 4; mi++)
            ldsm4(ah[mi], sA + swzoff(arow + mi * 16, ks * 2 + l16));
        #pragma unroll
        for (int p = 0; p < 2; p++) {
            const uint32_t off = swzoff(brow + p * 16, ks * 2 + l8);
            ldsm4(bh[p], sBh + off);
            ldsm4(bl[p], sBl + off);
        }
        #pragma unroll
        for (int mi = 0; mi < 4; mi++)
            #pragma unroll
            for (int nj = 0; nj < 4; nj++) {
                mma_f16(acc[mi][nj], ah[mi], &bh[nj >> 1][(nj & 1) * 2]);
                mma_f16(acc[mi][nj], ah[mi], &bl[nj >> 1][(nj & 1) * 2]);
            }
    }
}

// One 32-k PV stage: A = Wh single (K-major), B = V tile hi/lo via ldmatrix.trans
__device__ __forceinline__ void pv_stage2(uint32_t sA, uint32_t sBh, uint32_t sBl,
                                          int wmr, int wnr, int lane,
                                          float (*acc)[4][4]) {
    const int l7 = lane & 7, l8 = (lane >> 3) & 1, l16 = (lane >> 4) & 1;
    const int arow = wmr + l7 + l8 * 8;
    const int g = lane >> 3, q = lane & 7;
    #pragma unroll
    for (int ks = 0; ks < 2; ks++) {
        uint32_t ah[4][4];
        #pragma unroll
        for (int mi = 0; mi < 4; mi++)
            ldsm4(ah[mi], sA + swzoff(arow + mi * 16, ks * 2 + l16));
        #pragma unroll
        for (int half = 0; half < 2; half++) {
            const int r = ks * 16 + (g & 1) * 8 + q;
            const int cb = ((wnr + half * 16) >> 3) + (g >> 1);
            const uint32_t off = (uint32_t)(r * 128 + (((cb ^ r) & 7) << 4));
            uint32_t bh4[4], bl4[4];
            ldsm4t(bh4, sBh + off);
            ldsm4t(bl4, sBl + off);
            #pragma unroll
            for (int mi = 0; mi < 4; mi++)
                #pragma unroll
                for (int u = 0; u < 2; u++) {
                    const int nj = half * 2 + u;
                    mma_f16(acc[mi][nj], ah[mi], &bh4[u * 2]);
                    mma_f16(acc[mi][nj], ah[mi], &bl4[u * 2]);
                }
        }
    }
}

// ---------------- scratch ----------------
__device__ __half g_qh[2048 * HID],  g_ql[2048 * HID];
__device__ __half g_kh[16384 * HID], g_kl[16384 * HID];
__device__ __half g_vh[16384 * HID];
__device__ __half g_wqh[HID * HID], g_wql[HID * HID];
__device__ __half g_wkh[HID * HID], g_wkl[HID * HID];
__device__ __half g_wvh[HID * HID], g_wvl[HID * HID];
__device__ __half g_woh[HID * HID], g_wol[HID * HID];
__device__ __half g_Qh[2048 * HID],  g_Ql[2048 * HID];
__device__ __half g_Kh[16384 * HID], g_Kl[16384 * HID];
__device__ __half g_Vh[16384 * HID], g_Vl[16384 * HID];
__device__ float  g_Ssc[(size_t)CHUNK_H * T_LEN * S_LEN];          // 64 MB reused
__device__ __half g_Wh[(size_t)NBH * T_LEN * S_LEN];
__device__ __half g_ah[2048 * HID], g_al[2048 * HID];

// ---------------- conversions ----------------
__global__ __launch_bounds__(256)
void conv_split(const float* __restrict__ X, __half* __restrict__ H,
                __half* __restrict__ L) {
    const size_t u = (size_t)blockIdx.x * 256 + threadIdx.x;
    float2 v = reinterpret_cast<const float2*>(X)[u];
    __half2 h2, l2;
    split2h(v.x, h2.x, l2.x);
    split2h(v.y, h2.y, l2.y);
    reinterpret_cast<__half2*>(H)[u] = h2;
    reinterpret_cast<__half2*>(L)[u] = l2;
}
__global__ __launch_bounds__(256)
void conv_h(const float* __restrict__ X, __half* __restrict__ H) {
    const size_t u = (size_t)blockIdx.x * 256 + threadIdx.x;
    float2 v = reinterpret_cast<const float2*>(X)[u];
    reinterpret_cast<__half2*>(H)[u] =
        __halves2half2(__float2half_rn(v.x), __float2half_rn(v.y));
}
__global__ __launch_bounds__(256)
void conv_wT(const float* __restrict__ W, __half* __restrict__ WTh,
             __half* __restrict__ WTl) {
    __shared__ float t[32][33];
    const int k0 = blockIdx.x * 32, n0 = blockIdx.y * 32;
    const int tx = threadIdx.x, ty = threadIdx.y;
    for (int r = ty; r < 32; r += 8) t[r][tx] = W[(size_t)(k0 + r) * HID + n0 + tx];
    __syncthreads();
    for (int r = ty; r < 32; r += 8) {
        __half h, l;
        split2h(t[tx][r], h, l);
        WTh[(size_t)(n0 + r) * HID + k0 + tx] = h;
        WTl[(size_t)(n0 + r) * HID + k0 + tx] = l;
    }
}

// ---------------- projection GEMM (3-stage pipeline, 3-product) ----------------
// MODE 0: Q (bias, *0.125, fp16 out) 1: K (bias+seg, fp16 out) 2: O (fp32 out)
template<int MODE>
__global__ __launch_bounds__(256)
void proj_gemm(const __half* __restrict__ Ah, const __half* __restrict__ Al,
               const __half* __restrict__ Bh, const __half* __restrict__ Bl,
               const float* __restrict__ bias, const int* __restrict__ segids,
               const float* __restrict__ seg_emb, float* __restrict__ outF,
               __half* __restrict__ outH, __half* __restrict__ outL) {
    extern __shared__ __align__(128) char sm[];
    const uint32_t sb = smem_u32(sm);
    const int tid = threadIdx.x, lane = tid & 31, w = tid >> 5;
    const int wmr = (w & 1) * 64, wnr = (w >> 1) * 32;
    const int n0 = blockIdx.x * 128, m0 = blockIdx.y * 128;
    const __half* gAh = Ah + (size_t)m0 * HID;
    const __half* gAl = Al + (size_t)m0 * HID;
    const __half* gBh = Bh + (size_t)n0 * HID;
    const __half* gBl = Bl + (size_t)n0 * HID;

#define PJ_LOAD(st, ko) do {                                \
    const uint32_t b_ = sb + ((st) % 3) * 32768;            \
    load_stage<128>(b_ + 0,     gAh + (ko), HID, tid);      \
    load_stage<128>(b_ + 8192,  gAl + (ko), HID, tid);      \
    load_stage<128>(b_ + 16384, gBh + (ko), HID, tid);      \
    load_stage<128>(b_ + 24576, gBl + (ko), HID, tid);      \
    CP_COMMIT();                                            \
  } while (0)

    float acc[4][4][4] = {};
    PJ_LOAD(0, 0);
    PJ_LOAD(1, 32);
    const int NST = HID / 32;
    for (int s = 0; s < NST; s++) {
        if (s + 2 < NST) { PJ_LOAD(s + 2, (s + 2) * 32); CP_WAIT(2); }
        else if (s + 1 < NST) { CP_WAIT(1); }
        else { CP_WAIT(0); }
        __syncthreads();
        const uint32_t cur = sb + (s % 3) * 32768;
        stage_compute(cur, cur + 8192, cur + 16384, cur + 24576, wmr, wnr, lane, acc);
        __syncthreads();
    }
#undef PJ_LOAD

    const int mq = lane >> 2, nq = (lane & 3) * 2;
    #pragma unroll
    for (int mi = 0; mi < 4; mi++)
        #pragma unroll
        for (int half = 0; half < 2; half++) {
            const int m = m0 + wmr + mi * 16 + mq + half * 8;
            const int sid = (MODE == 1) ? segids[m] : 0;
            #pragma unroll
            for (int nj = 0; nj < 4; nj++) {
                const int n = n0 + wnr + nj * 8 + nq;
                float v0 = acc[mi][nj][half * 2 + 0] + bias[n];
                float v1 = acc[mi][nj][half * 2 + 1] + bias[n + 1];
                if (MODE == 1) {
                    v0 += seg_emb[(size_t)sid * HID + n];
                    v1 += seg_emb[(size_t)sid * HID + n + 1];
                }
                if (MODE == 0) { v0 *= 0.125f; v1 *= 0.125f; }
                if (MODE != 2) {
                    __half2 h2, l2;
                    split2h(v0, h2.x, l2.x);
                    split2h(v1, h2.y, l2.y);
                    *(__half2*)(outH + (size_t)m * HID + n) = h2;
                    *(__half2*)(outL + (size_t)m * HID + n) = l2;
                } else {
                    *(float2*)(outF + (size_t)m * HID + n) = make_float2(v0, v1);
                }
            }
        }
}

// ---------------- V projection GEMM (2-product, A single) ----------------
__global__ __launch_bounds__(256)
void proj_gemm_v(const __half* __restrict__ A,
                 const __half* __restrict__ Bh, const __half* __restrict__ Bl,
                 const float* __restrict__ bias,
                 __half* __restrict__ outH, __half* __restrict__ outL) {
    extern __shared__ __align__(128) char sm[];
    const uint32_t sb = smem_u32(sm);
    const int tid = threadIdx.x, lane = tid & 31, w = tid >> 5;
    const int wmr = (w & 1) * 64, wnr = (w >> 1) * 32;
    const int n0 = blockIdx.x * 128, m0 = blockIdx.y * 128;
    const __half* gA  = A + (size_t)m0 * HID;
    const __half* gBh = Bh + (size_t)n0 * HID;
    const __half* gBl = Bl + (size_t)n0 * HID;

#define PV_LOADW(st, ko) do {                               \
    const uint32_t b_ = sb + ((st) % 3) * 24576;            \
    load_stage<128>(b_ + 0,     gA  + (ko), HID, tid);      \
    load_stage<128>(b_ + 8192,  gBh + (ko), HID, tid);      \
    load_stage<128>(b_ + 16384, gBl + (ko), HID, tid);      \
    CP_COMMIT();                                            \
  } while (0)

    float acc[4][4][4] = {};
    PV_LOADW(0, 0);
    PV_LOADW(1, 32);
    const int NST = HID / 32;
    for (int s = 0; s < NST; s++) {
        if (s + 2 < NST) { PV_LOADW(s + 2, (s + 2) * 32); CP_WAIT(2); }
        else if (s + 1 < NST) { CP_WAIT(1); }
        else { CP_WAIT(0); }
        __syncthreads();
        const uint32_t cur = sb + (s % 3) * 24576;
        stage_compute_v(cur, cur + 8192, cur + 16384, wmr, wnr, lane, acc);
        __syncthreads();
    }
#undef PV_LOADW

    const int mq = lane >> 2, nq = (lane & 3) * 2;
    #pragma unroll
    for (int mi = 0; mi < 4; mi++)
        #pragma unroll
        for (int half = 0; half < 2; half++) {
            const int m = m0 + wmr + mi * 16 + mq + half * 8;
            #pragma unroll
            for (int nj = 0; nj < 4; nj++) {
                const int n = n0 + wnr + nj * 8 + nq;
                float v0 = acc[mi][nj][half * 2 + 0] + bias[n];
                float v1 = acc[mi][nj][half * 2 + 1] + bias[n + 1];
                __half2 h2, l2;
                split2h(v0, h2.x, l2.x);
                split2h(v1, h2.y, l2.y);
                *(__half2*)(outH + (size_t)m * HID + n) = h2;
                *(__half2*)(outL + (size_t)m * HID + n) = l2;
            }
        }
}

// ---------------- scores chunk: Sc[z,t,s] = Q·K^T (scale folded into Q) ----------------
__global__ __launch_bounds__(256)
void scores_gemm(const __half* __restrict__ Qh, const __half* __restrict__ Ql,
                 const __half* __restrict__ Kh, const __half* __restrict__ Kl,
                 const int* __restrict__ amask, float* __restrict__ Sc, int bh0) {
    extern __shared__ __align__(128) char sm[];
    const uint32_t sb = smem_u32(sm);
    const int tid = threadIdx.x, lane = tid & 31, w = tid >> 5;
    const int wmr = (w & 1) * 64, wnr = (w >> 1) * 32;
    const int zz = blockIdx.z, bh = bh0 + zz, b = bh >> 4, h = bh & 15;
    const int t0 = blockIdx.y * 128, s0 = blockIdx.x * 128;
    const __half* gAh = Qh + (size_t)(b * T_LEN + t0) * HID + h * HD;
    const __half* gAl = Ql + (size_t)(b * T_LEN + t0) * HID + h * HD;
    const __half* gBh = Kh + (size_t)(b * S_LEN + s0) * HID + h * HD;
    const __half* gBl = Kl + (size_t)(b * S_LEN + s0) * HID + h * HD;

    float acc[4][4][4] = {};
    load_stage<128>(sb + 0,     gAh, HID, tid);
    load_stage<128>(sb + 8192,  gAl, HID, tid);
    load_stage<128>(sb + 16384, gBh, HID, tid);
    load_stage<128>(sb + 24576, gBl, HID, tid);
    CP_COMMIT();
    for (int s = 0; s < 2; s++) {
        const uint32_t cur = sb + (s & 1) * 32768;
        if (s == 0) {
            const uint32_t nxt = sb + 32768;
            load_stage<128>(nxt + 0,     gAh + 32, HID, tid);
            load_stage<128>(nxt + 8192,  gAl + 32, HID, tid);
            load_stage<128>(nxt + 16384, gBh + 32, HID, tid);
            load_stage<128>(nxt + 24576, gBl + 32, HID, tid);
            CP_COMMIT();
            CP_WAIT(1);
        } else {
            CP_WAIT(0);
        }
        __syncthreads();
        stage_compute(cur, cur + 8192, cur + 16384, cur + 24576, wmr, wnr, lane, acc);
        __syncthreads();
    }

    const int mq = lane >> 2, nq = (lane & 3) * 2;
    float* dstB = Sc + (size_t)zz * T_LEN * S_LEN;
    #pragma unroll
    for (int mi = 0; mi < 4; mi++)
        #pragma unroll
        for (int half = 0; half < 2; half++) {
            const int t = t0 + wmr + mi * 16 + mq + half * 8;
            #pragma unroll
            for (int nj = 0; nj < 4; nj++) {
                const int sidx = s0 + wnr + nj * 8 + nq;
                float v0 = acc[mi][nj][half * 2 + 0];
                float v1 = acc[mi][nj][half * 2 + 1];
                if (amask[b * S_LEN + sidx] == 0) v0 = -1e9f;
                if (amask[b * S_LEN + sidx + 1] == 0) v1 = -1e9f;
                *(float2*)(dstB + (size_t)t * S_LEN + sidx) = make_float2(v0, v1);
            }
        }
}

// ---------------- softmax chunk: scratch row -> fp16 hi weights ----------------
__global__ __launch_bounds__(256)
void softmax_kernel(const float* __restrict__ Sc, __half* __restrict__ Wh, int bh0) {
    const int r = blockIdx.x, z = r >> 9, t = r & 511;
    const size_t sbase = ((size_t)z * T_LEN + t) * S_LEN;
    const size_t wbase = ((size_t)(bh0 + z) * T_LEN + t) * S_LEN;
    const int tid = threadIdx.x;
    __shared__ float red[8];
    float v[16];
    #pragma unroll
    for (int i = 0; i < 16; i++) v[i] = Sc[sbase + tid + i * 256];
    float m = -1e30f;
    #pragma unroll
    for (int i = 0; i < 16; i++) m = fmaxf(m, v[i]);
    #pragma unroll
    for (int o = 16; o; o >>= 1) m = fmaxf(m, __shfl_xor_sync(0xFFFFFFFFu, m, o));
    if ((tid & 31) == 0) red[tid >> 5] = m;
    __syncthreads();
    float gmax = red[0];
    #pragma unroll
    for (int w = 1; w < 8; w++) gmax = fmaxf(gmax, red[w]);
    __syncthreads();
    float s = 0.f;
    #pragma unroll
    for (int i = 0; i < 16; i++) { v[i] = expf(v[i] - gmax); s += v[i]; }
    #pragma unroll
    for (int o = 16; o; o >>= 1) s += __shfl_xor_sync(0xFFFFFFFFu, s, o);
    if ((tid & 31) == 0) red[tid >> 5] = s;
    __syncthreads();
    float tot = red[0];
    #pragma unroll
    for (int w = 1; w < 8; w++) tot += red[w];
    const float inv = 1.0f / tot;
    #pragma unroll
    for (int i = 0; i < 16; i += 2) {
        __half2 h2;
        h2.x = __float2half_rn(v[i] * inv);
        h2.y = __float2half_rn(v[i + 1] * inv);
        // note: adjacent i are 256 apart, not contiguous — store separately
        Wh[wbase + tid + i * 256] = h2.x;
        Wh[wbase + tid + (i + 1) * 256] = h2.y;
    }
}

// ---------------- provenance = head-mean of Wh (fp16 hi only) ----------------
__global__ __launch_bounds__(256)
void provenance_kernel(const __half* __restrict__ Wh, float* __restrict__ out) {
    const size_t u = (size_t)blockIdx.x * 256 + threadIdx.x;
    const int s2 = (int)(u & 2047);
    const int t  = (int)((u >> 11) & 511);
    const int b  = (int)(u >> 20);
    float s0 = 0.f, s1 = 0.f;
    #pragma unroll
    for (int h = 0; h < NH; h++) {
        const size_t o = (((size_t)(b * NH + h) * T_LEN + t) * S_LEN) / 2 + s2;
        __half2 h2 = reinterpret_cast<const __half2*>(Wh)[o];
        s0 += __half2float(h2.x);
        s1 += __half2float(h2.y);
    }
    reinterpret_cast<float2*>(out)[u] = make_float2(s0 * (1.0f / NH), s1 * (1.0f / NH));
}

// ---------------- P·V: C[256,64] per CTA, K=4096, Wh-only A, 3-stage ----------------
__global__ __launch_bounds__(256)
void pv_gemm(const __half* __restrict__ Wh,
             const __half* __restrict__ Vh, const __half* __restrict__ Vl,
             __half* __restrict__ attH, __half* __restrict__ attL) {
    extern __shared__ __align__(128) char sm[];
    const uint32_t sb = smem_u32(sm);
    const int tid = threadIdx.x, lane = tid & 31, w = tid >> 5;
    const int wmr = (w & 3) * 64, wnr = (w >> 2) * 32;
    const int bh = blockIdx.y, b = bh >> 4, h = bh & 15;
    const int t0 = blockIdx.x * 256;
    const __half* gA  = Wh + ((size_t)bh * T_LEN + t0) * S_LEN;
    const __half* gBh = Vh + (size_t)(b * S_LEN) * HID + h * HD;
    const __half* gBl = Vl + (size_t)(b * S_LEN) * HID + h * HD;

#define PV_LOAD(st, ko) do {                                              \
    const uint32_t b_ = sb + ((st) % 3) * 24576;                          \
    load_stage<256>(b_ + 0, gA + (ko), S_LEN, tid);                       \
    load_vtile(b_ + 16384, gBh + (size_t)(ko) * HID, HID, tid);           \
    load_vtile(b_ + 20480, gBl + (size_t)(ko) * HID, HID, tid);           \
    CP_COMMIT();                                                          \
  } while (0)

    float acc[4][4][4] = {};
    PV_LOAD(0, 0);
    PV_LOAD(1, 32);
    const int NST = S_LEN / 32;
    for (int s = 0; s < NST; s++) {
        if (s + 2 < NST) { PV_LOAD(s + 2, (s + 2) * 32); CP_WAIT(2); }
        else if (s + 1 < NST) { CP_WAIT(1); }
        else { CP_WAIT(0); }
        __syncthreads();
        const uint32_t cur = sb + (s % 3) * 24576;
        pv_stage2(cur, cur + 16384, cur + 20480, wmr, wnr, lane, acc);
        __syncthreads();
    }
#undef PV_LOAD

    const int mq = lane >> 2, nq = (lane & 3) * 2;
    #pragma unroll
    for (int mi = 0; mi < 4; mi++)
        #pragma unroll
        for (int half = 0; half < 2; half++) {
            const int t = t0 + wmr + mi * 16 + mq + half * 8;
            const size_t mo = (size_t)(b * T_LEN + t) * HID + h * HD;
            #pragma unroll
            for (int nj = 0; nj < 4; nj++) {
                const int n = wnr + nj * 8 + nq;
                __half2 h2, l2;
                split2h(acc[mi][nj][half * 2 + 0], h2.x, l2.x);
                split2h(acc[mi][nj][half * 2 + 1], h2.y, l2.y);
                *(__half2*)(attH + mo + n) = h2;
                *(__half2*)(attL + mo + n) = l2;
            }
        }
}

// ---------------------------------------------------------------------------
extern "C" void kernel_launch(void* const* d_in, const int* in_sizes, int n_in,
                              void* d_out, int out_size) {
    const float* query  = (const float*)d_in[0];
    const float* key    = (const float*)d_in[1];
    const float* value  = (const float*)d_in[2];
    const int*   amask  = (const int*)d_in[3];
    const int*   segids = (const int*)d_in[4];
    const float* Wq = (const float*)d_in[5];
    const float* bq = (const float*)d_in[6];
    const float* Wk = (const float*)d_in[7];
    const float* bk = (const float*)d_in[8];
    const float* Wv = (const float*)d_in[9];
    const float* bv = (const float*)d_in[10];
    const float* Wo = (const float*)d_in[11];
    const float* bo = (const float*)d_in[12];
    const float* seg_emb = (const float*)d_in[13];
    float* out = (float*)d_out;

    __half *qh, *ql, *kh, *kl, *vh;
    __half *wqh, *wql, *wkh, *wkl, *wvh, *wvl, *woh, *wol;
    __half *Qh, *Ql, *Kh, *Kl, *Vh, *Vl, *Wh, *ah, *al;
    float *Ssc;
    cudaGetSymbolAddress((void**)&qh, g_qh);   cudaGetSymbolAddress((void**)&ql, g_ql);
    cudaGetSymbolAddress((void**)&kh, g_kh);   cudaGetSymbolAddress((void**)&kl, g_kl);
    cudaGetSymbolAddress((void**)&vh, g_vh);
    cudaGetSymbolAddress((void**)&wqh, g_wqh); cudaGetSymbolAddress((void**)&wql, g_wql);
    cudaGetSymbolAddress((void**)&wkh, g_wkh); cudaGetSymbolAddress((void**)&wkl, g_wkl);
    cudaGetSymbolAddress((void**)&wvh, g_wvh); cudaGetSymbolAddress((void**)&wvl, g_wvl);
    cudaGetSymbolAddress((void**)&woh, g_woh); cudaGetSymbolAddress((void**)&wol, g_wol);
    cudaGetSymbolAddress((void**)&Qh, g_Qh);   cudaGetSymbolAddress((void**)&Ql, g_Ql);
    cudaGetSymbolAddress((void**)&Kh, g_Kh);   cudaGetSymbolAddress((void**)&Kl, g_Kl);
    cudaGetSymbolAddress((void**)&Vh, g_Vh);   cudaGetSymbolAddress((void**)&Vl, g_Vl);
    cudaGetSymbolAddress((void**)&Ssc, g_Ssc);
    cudaGetSymbolAddress((void**)&Wh, g_Wh);
    cudaGetSymbolAddress((void**)&ah, g_ah);   cudaGetSymbolAddress((void**)&al, g_al);

    cudaFuncSetAttribute(proj_gemm<0>, cudaFuncAttributeMaxDynamicSharedMemorySize, 98304);
    cudaFuncSetAttribute(proj_gemm<1>, cudaFuncAttributeMaxDynamicSharedMemorySize, 98304);
    cudaFuncSetAttribute(proj_gemm<2>, cudaFuncAttributeMaxDynamicSharedMemorySize, 98304);
    cudaFuncSetAttribute(proj_gemm_v, cudaFuncAttributeMaxDynamicSharedMemorySize, 73728);
    cudaFuncSetAttribute(scores_gemm, cudaFuncAttributeMaxDynamicSharedMemorySize, 65536);
    cudaFuncSetAttribute(pv_gemm, cudaFuncAttributeMaxDynamicSharedMemorySize, 73728);

    // input + weight conversions (fp16 hi/lo)
    conv_split<<<4096, 256>>>(query, qh, ql);
    conv_split<<<32768, 256>>>(key, kh, kl);
    conv_h<<<32768, 256>>>(value, vh);
    dim3 wtb(32, 8), wtg(32, 32);
    conv_wT<<<wtg, wtb>>>(Wq, wqh, wql);
    conv_wT<<<wtg, wtb>>>(Wk, wkh, wkl);
    conv_wT<<<wtg, wtb>>>(Wv, wvh, wvl);
    conv_wT<<<wtg, wtb>>>(Wo, woh, wol);

    // projections
    proj_gemm<0><<<dim3(8, 16),  256, 98304>>>(qh, ql, wqh, wql, bq, nullptr, nullptr, nullptr, Qh, Ql);
    proj_gemm<1><<<dim3(8, 128), 256, 98304>>>(kh, kl, wkh, wkl, bk, segids, seg_emb, nullptr, Kh, Kl);
    proj_gemm_v<<<dim3(8, 128), 256, 73728>>>(vh, wvh, wvl, bv, Vh, Vl);

    // attention: L2-blocked scores -> softmax per 8-head chunk (reused scratch)
    for (int c = 0; c < NBH / CHUNK_H; c++) {
        const int bh0 = c * CHUNK_H;
        scores_gemm<<<dim3(32, 4, CHUNK_H), 256, 65536>>>(Qh, Ql, Kh, Kl, amask, Ssc, bh0);
        softmax_kernel<<<CHUNK_H * T_LEN, 256>>>(Ssc, Wh, bh0);
    }
    provenance_kernel<<<16384, 256>>>(Wh, out + (size_t)2048 * HID);
    pv_gemm<<<dim3(2, 64), 256, 73728>>>(Wh, Vh, Vl, ah, al);

    // output projection -> d_out
    proj_gemm<2><<<dim3(8, 16), 256, 98304>>>(ah, al, woh, wol, bo, nullptr, nullptr, out, nullptr, nullptr);
}

// round 7
// speedup vs baseline: 3.6758x; 1.0993x over previous
#include <cuda_runtime.h>
#include <cuda_fp16.h>
#include <cstdint>
#include <cstddef>

#define B_SZ   4
#define T_LEN  512
#define S_LEN  4096
#define HID    1024
#define NH     16
#define HD     64
#define NBH    (B_SZ * NH)
#define CHUNK_H 8                 // heads per L2-resident score chunk

// ---------------------------------------------------------------------------
// helpers
// ---------------------------------------------------------------------------
__device__ __forceinline__ uint32_t smem_u32(const void* p) {
    uint32_t a;
    asm("{ .reg .u64 t; cvta.to.shared.u64 t, %1; cvt.u32.u64 %0, t; }" : "=r"(a) : "l"(p));
    return a;
}
// 64B-row tile swizzle (K-major tiles)
__device__ __forceinline__ uint32_t swzoff(int row, int chunk) {
    const int v = (row & 3) ^ ((row >> 2) & 1);
    return (uint32_t)(row * 64 + (((chunk ^ v) & 3) << 4));
}
__device__ __forceinline__ void cpa16(uint32_t dst, const void* src) {
    asm volatile("cp.async.cg.shared.global [%0], [%1], 16;" :: "r"(dst), "l"(src));
}
#define CP_COMMIT() asm volatile("cp.async.commit_group;" ::: "memory")
#define CP_WAIT(n)  asm volatile("cp.async.wait_group %0;" :: "n"(n) : "memory")

__device__ __forceinline__ void ldsm4(uint32_t* r, uint32_t a) {
    asm volatile("ldmatrix.sync.aligned.m8n8.x4.shared.b16 {%0,%1,%2,%3}, [%4];"
                 : "=r"(r[0]), "=r"(r[1]), "=r"(r[2]), "=r"(r[3]) : "r"(a));
}
__device__ __forceinline__ void ldsm4t(uint32_t* r, uint32_t a) {
    asm volatile("ldmatrix.sync.aligned.m8n8.x4.trans.shared.b16 {%0,%1,%2,%3}, [%4];"
                 : "=r"(r[0]), "=r"(r[1]), "=r"(r[2]), "=r"(r[3]) : "r"(a));
}
__device__ __forceinline__ void mma_f16(float* d, const uint32_t* a, const uint32_t* b) {
    asm volatile("mma.sync.aligned.m16n8k16.row.col.f32.f16.f16.f32 "
                 "{%0,%1,%2,%3}, {%4,%5,%6,%7}, {%8,%9}, {%0,%1,%2,%3};"
                 : "+f"(d[0]), "+f"(d[1]), "+f"(d[2]), "+f"(d[3])
                 : "r"(a[0]), "r"(a[1]), "r"(a[2]), "r"(a[3]), "r"(b[0]), "r"(b[1]));
}
__device__ __forceinline__ void split2h(float v, __half& h, __half& l) {
    h = __float2half_rn(v);
    l = __float2half_rn(v - __half2float(h));
}

// Load a [ROWS x 32] fp16 tile (row stride = stride elems) into swizzled SMEM
template<int ROWS>
__device__ __forceinline__ void load_stage(uint32_t sbuf, const __half* g,
                                           int stride, int tid) {
    #pragma unroll
    for (int i = tid; i < ROWS * 4; i += 256) {
        const int row = i >> 2, ch = i & 3;
        cpa16(sbuf + swzoff(row, ch), g + (size_t)row * stride + ch * 8);
    }
}
// Load a [32 x 64] fp16 tile (128B rows, chunk-XOR swizzle) for trans-B (V)
__device__ __forceinline__ void load_vtile(uint32_t sbuf, const __half* g,
                                           int stride, int tid) {
    if (tid < 256) {
        const int row = tid >> 3, ch = tid & 7;
        cpa16(sbuf + (uint32_t)(row * 128 + (((ch ^ row) & 7) << 4)),
              g + (size_t)row * stride + ch * 8);
    }
}

// One 32-k stage, A hi/lo + B hi/lo, 3 products (scores only).
__device__ __forceinline__ void stage_compute3(uint32_t sAh, uint32_t sAl,
                                               uint32_t sBh, uint32_t sBl,
                                               int wmr, int wnr, int lane,
                                               float (*acc)[4][4]) {
    const int l7 = lane & 7, l8 = (lane >> 3) & 1, l16 = (lane >> 4) & 1;
    const int arow = wmr + l7 + l8 * 8;
    const int brow = wnr + l16 * 8 + l7;
    #pragma unroll
    for (int ks = 0; ks < 2; ks++) {
        uint32_t ah[4][4], al[4][4], bh[2][4], bl[2][4];
        #pragma unroll
        for (int mi = 0; mi < 4; mi++) {
            const uint32_t off = swzoff(arow + mi * 16, ks * 2 + l16);
            ldsm4(ah[mi], sAh + off);
            ldsm4(al[mi], sAl + off);
        }
        #pragma unroll
        for (int p = 0; p < 2; p++) {
            const uint32_t off = swzoff(brow + p * 16, ks * 2 + l8);
            ldsm4(bh[p], sBh + off);
            ldsm4(bl[p], sBl + off);
        }
        #pragma unroll
        for (int mi = 0; mi < 4; mi++)
            #pragma unroll
            for (int nj = 0; nj < 4; nj++) {
                const uint32_t* bhj = &bh[nj >> 1][(nj & 1) * 2];
                const uint32_t* blj = &bl[nj >> 1][(nj & 1) * 2];
                mma_f16(acc[mi][nj], ah[mi], bhj);
                mma_f16(acc[mi][nj], ah[mi], blj);
                mma_f16(acc[mi][nj], al[mi], bhj);
            }
    }
}

// One 32-k stage, A single + B hi/lo, 2 products (all projections).
__device__ __forceinline__ void stage_compute2(uint32_t sA,
                                               uint32_t sBh, uint32_t sBl,
                                               int wmr, int wnr, int lane,
                                               float (*acc)[4][4]) {
    const int l7 = lane & 7, l8 = (lane >> 3) & 1, l16 = (lane >> 4) & 1;
    const int arow = wmr + l7 + l8 * 8;
    const int brow = wnr + l16 * 8 + l7;
    #pragma unroll
    for (int ks = 0; ks < 2; ks++) {
        uint32_t ah[4][4], bh[2][4], bl[2][4];
        #pragma unroll
        for (int mi = 0; mi < 4; mi++)
            ldsm4(ah[mi], sA + swzoff(arow + mi * 16, ks * 2 + l16));
        #pragma unroll
        for (int p = 0; p < 2; p++) {
            const uint32_t off = swzoff(brow + p * 16, ks * 2 + l8);
            ldsm4(bh[p], sBh + off);
            ldsm4(bl[p], sBl + off);
        }
        #pragma unroll
        for (int mi = 0; mi < 4; mi++)
            #pragma unroll
            for (int nj = 0; nj < 4; nj++) {
                mma_f16(acc[mi][nj], ah[mi], &bh[nj >> 1][(nj & 1) * 2]);
                mma_f16(acc[mi][nj], ah[mi], &bl[nj >> 1][(nj & 1) * 2]);
            }
    }
}

// One 32-k PV stage: A = Wh single (K-major), B = V tile hi/lo via ldmatrix.trans
__device__ __forceinline__ void pv_stage2(uint32_t sA, uint32_t sBh, uint32_t sBl,
                                          int wmr, int wnr, int lane,
                                          float (*acc)[4][4]) {
    const int l7 = lane & 7, l8 = (lane >> 3) & 1, l16 = (lane >> 4) & 1;
    const int arow = wmr + l7 + l8 * 8;
    const int g = lane >> 3, q = lane & 7;
    #pragma unroll
    for (int ks = 0; ks < 2; ks++) {
        uint32_t ah[4][4];
        #pragma unroll
        for (int mi = 0; mi < 4; mi++)
            ldsm4(ah[mi], sA + swzoff(arow + mi * 16, ks * 2 + l16));
        #pragma unroll
        for (int half = 0; half < 2; half++) {
            const int r = ks * 16 + (g & 1) * 8 + q;
            const int cb = ((wnr + half * 16) >> 3) + (g >> 1);
            const uint32_t off = (uint32_t)(r * 128 + (((cb ^ r) & 7) << 4));
            uint32_t bh4[4], bl4[4];
            ldsm4t(bh4, sBh + off);
            ldsm4t(bl4, sBl + off);
            #pragma unroll
            for (int mi = 0; mi < 4; mi++)
                #pragma unroll
                for (int u = 0; u < 2; u++) {
                    const int nj = half * 2 + u;
                    mma_f16(acc[mi][nj], ah[mi], &bh4[u * 2]);
                    mma_f16(acc[mi][nj], ah[mi], &bl4[u * 2]);
                }
        }
    }
}

// ---------------- scratch ----------------
__device__ __half g_qh[2048 * HID];
__device__ __half g_kh[16384 * HID];
__device__ __half g_vh[16384 * HID];
__device__ __half g_wqh[HID * HID], g_wql[HID * HID];
__device__ __half g_wkh[HID * HID], g_wkl[HID * HID];
__device__ __half g_wvh[HID * HID], g_wvl[HID * HID];
__device__ __half g_woh[HID * HID], g_wol[HID * HID];
__device__ __half g_Qh[2048 * HID],  g_Ql[2048 * HID];
__device__ __half g_Kh[16384 * HID], g_Kl[16384 * HID];
__device__ __half g_Vh[16384 * HID], g_Vl[16384 * HID];
__device__ float  g_Ssc[(size_t)CHUNK_H * T_LEN * S_LEN];          // 64 MB reused
__device__ __half g_Wh[(size_t)NBH * T_LEN * S_LEN];
__device__ __half g_ah[2048 * HID];

// ---------------- conversions ----------------
__global__ __launch_bounds__(256)
void conv_h(const float* __restrict__ X, __half* __restrict__ H) {
    const size_t u = (size_t)blockIdx.x * 256 + threadIdx.x;
    float2 v = reinterpret_cast<const float2*>(X)[u];
    reinterpret_cast<__half2*>(H)[u] =
        __halves2half2(__float2half_rn(v.x), __float2half_rn(v.y));
}
__global__ __launch_bounds__(256)
void conv_wT(const float* __restrict__ W, __half* __restrict__ WTh,
             __half* __restrict__ WTl) {
    __shared__ float t[32][33];
    const int k0 = blockIdx.x * 32, n0 = blockIdx.y * 32;
    const int tx = threadIdx.x, ty = threadIdx.y;
    for (int r = ty; r < 32; r += 8) t[r][tx] = W[(size_t)(k0 + r) * HID + n0 + tx];
    __syncthreads();
    for (int r = ty; r < 32; r += 8) {
        __half h, l;
        split2h(t[tx][r], h, l);
        WTh[(size_t)(n0 + r) * HID + k0 + tx] = h;
        WTl[(size_t)(n0 + r) * HID + k0 + tx] = l;
    }
}

// ---------------- projection GEMM (2-product, A single, 3-stage) ----------------
// MODE 0: Q (bias, *0.125, hi/lo out) 1: K (bias+seg, hi/lo out) 2: O (fp32 out) 3: V (bias, hi/lo out)
template<int MODE>
__global__ __launch_bounds__(256)
void proj2(const __half* __restrict__ A,
           const __half* __restrict__ Bh, const __half* __restrict__ Bl,
           const float* __restrict__ bias, const int* __restrict__ segids,
           const float* __restrict__ seg_emb, float* __restrict__ outF,
           __half* __restrict__ outH, __half* __restrict__ outL) {
    extern __shared__ __align__(128) char sm[];
    const uint32_t sb = smem_u32(sm);
    const int tid = threadIdx.x, lane = tid & 31, w = tid >> 5;
    const int wmr = (w & 1) * 64, wnr = (w >> 1) * 32;
    const int n0 = blockIdx.x * 128, m0 = blockIdx.y * 128;
    const __half* gA  = A + (size_t)m0 * HID;
    const __half* gBh = Bh + (size_t)n0 * HID;
    const __half* gBl = Bl + (size_t)n0 * HID;

#define PJ_LOAD(st, ko) do {                                \
    const uint32_t b_ = sb + ((st) % 3) * 24576;            \
    load_stage<128>(b_ + 0,     gA  + (ko), HID, tid);      \
    load_stage<128>(b_ + 8192,  gBh + (ko), HID, tid);      \
    load_stage<128>(b_ + 16384, gBl + (ko), HID, tid);      \
    CP_COMMIT();                                            \
  } while (0)

    float acc[4][4][4] = {};
    PJ_LOAD(0, 0);
    PJ_LOAD(1, 32);
    const int NST = HID / 32;
    for (int s = 0; s < NST; s++) {
        if (s + 2 < NST) { PJ_LOAD(s + 2, (s + 2) * 32); CP_WAIT(2); }
        else if (s + 1 < NST) { CP_WAIT(1); }
        else { CP_WAIT(0); }
        __syncthreads();
        const uint32_t cur = sb + (s % 3) * 24576;
        stage_compute2(cur, cur + 8192, cur + 16384, wmr, wnr, lane, acc);
        __syncthreads();
    }
#undef PJ_LOAD

    const int mq = lane >> 2, nq = (lane & 3) * 2;
    #pragma unroll
    for (int mi = 0; mi < 4; mi++)
        #pragma unroll
        for (int half = 0; half < 2; half++) {
            const int m = m0 + wmr + mi * 16 + mq + half * 8;
            const int sid = (MODE == 1) ? segids[m] : 0;
            #pragma unroll
            for (int nj = 0; nj < 4; nj++) {
                const int n = n0 + wnr + nj * 8 + nq;
                float v0 = acc[mi][nj][half * 2 + 0] + bias[n];
                float v1 = acc[mi][nj][half * 2 + 1] + bias[n + 1];
                if (MODE == 1) {
                    v0 += seg_emb[(size_t)sid * HID + n];
                    v1 += seg_emb[(size_t)sid * HID + n + 1];
                }
                if (MODE == 0) { v0 *= 0.125f; v1 *= 0.125f; }
                if (MODE != 2) {
                    __half2 h2, l2;
                    split2h(v0, h2.x, l2.x);
                    split2h(v1, h2.y, l2.y);
                    *(__half2*)(outH + (size_t)m * HID + n) = h2;
                    *(__half2*)(outL + (size_t)m * HID + n) = l2;
                } else {
                    *(float2*)(outF + (size_t)m * HID + n) = make_float2(v0, v1);
                }
            }
        }
}

// ---------------- scores chunk: Sc[z,t,s] = Q·K^T (scale folded into Q), 3-product ----------------
__global__ __launch_bounds__(256)
void scores_gemm(const __half* __restrict__ Qh, const __half* __restrict__ Ql,
                 const __half* __restrict__ Kh, const __half* __restrict__ Kl,
                 const int* __restrict__ amask, float* __restrict__ Sc, int bh0) {
    extern __shared__ __align__(128) char sm[];
    const uint32_t sb = smem_u32(sm);
    const int tid = threadIdx.x, lane = tid & 31, w = tid >> 5;
    const int wmr = (w & 1) * 64, wnr = (w >> 1) * 32;
    const int zz = blockIdx.z, bh = bh0 + zz, b = bh >> 4, h = bh & 15;
    const int t0 = blockIdx.y * 128, s0 = blockIdx.x * 128;
    const __half* gAh = Qh + (size_t)(b * T_LEN + t0) * HID + h * HD;
    const __half* gAl = Ql + (size_t)(b * T_LEN + t0) * HID + h * HD;
    const __half* gBh = Kh + (size_t)(b * S_LEN + s0) * HID + h * HD;
    const __half* gBl = Kl + (size_t)(b * S_LEN + s0) * HID + h * HD;

    float acc[4][4][4] = {};
    load_stage<128>(sb + 0,     gAh, HID, tid);
    load_stage<128>(sb + 8192,  gAl, HID, tid);
    load_stage<128>(sb + 16384, gBh, HID, tid);
    load_stage<128>(sb + 24576, gBl, HID, tid);
    CP_COMMIT();
    for (int s = 0; s < 2; s++) {
        const uint32_t cur = sb + (s & 1) * 32768;
        if (s == 0) {
            const uint32_t nxt = sb + 32768;
            load_stage<128>(nxt + 0,     gAh + 32, HID, tid);
            load_stage<128>(nxt + 8192,  gAl + 32, HID, tid);
            load_stage<128>(nxt + 16384, gBh + 32, HID, tid);
            load_stage<128>(nxt + 24576, gBl + 32, HID, tid);
            CP_COMMIT();
            CP_WAIT(1);
        } else {
            CP_WAIT(0);
        }
        __syncthreads();
        stage_compute3(cur, cur + 8192, cur + 16384, cur + 24576, wmr, wnr, lane, acc);
        __syncthreads();
    }

    const int mq = lane >> 2, nq = (lane & 3) * 2;
    float* dstB = Sc + (size_t)zz * T_LEN * S_LEN;
    #pragma unroll
    for (int mi = 0; mi < 4; mi++)
        #pragma unroll
        for (int half = 0; half < 2; half++) {
            const int t = t0 + wmr + mi * 16 + mq + half * 8;
            #pragma unroll
            for (int nj = 0; nj < 4; nj++) {
                const int sidx = s0 + wnr + nj * 8 + nq;
                float v0 = acc[mi][nj][half * 2 + 0];
                float v1 = acc[mi][nj][half * 2 + 1];
                if (amask[b * S_LEN + sidx] == 0) v0 = -1e9f;
                if (amask[b * S_LEN + sidx + 1] == 0) v1 = -1e9f;
                *(float2*)(dstB + (size_t)t * S_LEN + sidx) = make_float2(v0, v1);
            }
        }
}

// ---------------- softmax chunk: scratch row -> fp16 hi weights ----------------
__global__ __launch_bounds__(256)
void softmax_kernel(const float* __restrict__ Sc, __half* __restrict__ Wh, int bh0) {
    const int r = blockIdx.x, z = r >> 9, t = r & 511;
    const size_t sbase = ((size_t)z * T_LEN + t) * S_LEN;
    const size_t wbase = ((size_t)(bh0 + z) * T_LEN + t) * S_LEN;
    const int tid = threadIdx.x;
    __shared__ float red[8];
    float v[16];
    #pragma unroll
    for (int i = 0; i < 16; i++) v[i] = Sc[sbase + tid + i * 256];
    float m = -1e30f;
    #pragma unroll
    for (int i = 0; i < 16; i++) m = fmaxf(m, v[i]);
    #pragma unroll
    for (int o = 16; o; o >>= 1) m = fmaxf(m, __shfl_xor_sync(0xFFFFFFFFu, m, o));
    if ((tid & 31) == 0) red[tid >> 5] = m;
    __syncthreads();
    float gmax = red[0];
    #pragma unroll
    for (int w = 1; w < 8; w++) gmax = fmaxf(gmax, red[w]);
    __syncthreads();
    float s = 0.f;
    #pragma unroll
    for (int i = 0; i < 16; i++) { v[i] = expf(v[i] - gmax); s += v[i]; }
    #pragma unroll
    for (int o = 16; o; o >>= 1) s += __shfl_xor_sync(0xFFFFFFFFu, s, o);
    if ((tid & 31) == 0) red[tid >> 5] = s;
    __syncthreads();
    float tot = red[0];
    #pragma unroll
    for (int w = 1; w < 8; w++) tot += red[w];
    const float inv = 1.0f / tot;
    #pragma unroll
    for (int i = 0; i < 16; i++)
        Wh[wbase + tid + i * 256] = __float2half_rn(v[i] * inv);
}

// ---------------- provenance = head-mean of Wh ----------------
__global__ __launch_bounds__(256)
void provenance_kernel(const __half* __restrict__ Wh, float* __restrict__ out) {
    const size_t u = (size_t)blockIdx.x * 256 + threadIdx.x;
    const int s2 = (int)(u & 2047);
    const int t  = (int)((u >> 11) & 511);
    const int b  = (int)(u >> 20);
    float s0 = 0.f, s1 = 0.f;
    #pragma unroll
    for (int h = 0; h < NH; h++) {
        const size_t o = (((size_t)(b * NH + h) * T_LEN + t) * S_LEN) / 2 + s2;
        __half2 h2 = reinterpret_cast<const __half2*>(Wh)[o];
        s0 += __half2float(h2.x);
        s1 += __half2float(h2.y);
    }
    reinterpret_cast<float2*>(out)[u] = make_float2(s0 * (1.0f / NH), s1 * (1.0f / NH));
}

// ---------------- P·V: C[256,64] per CTA, K=4096, Wh-only A, 3-stage ----------------
__global__ __launch_bounds__(256)
void pv_gemm(const __half* __restrict__ Wh,
             const __half* __restrict__ Vh, const __half* __restrict__ Vl,
             __half* __restrict__ attH) {
    extern __shared__ __align__(128) char sm[];
    const uint32_t sb = smem_u32(sm);
    const int tid = threadIdx.x, lane = tid & 31, w = tid >> 5;
    const int wmr = (w & 3) * 64, wnr = (w >> 2) * 32;
    const int bh = blockIdx.y, b = bh >> 4, h = bh & 15;
    const int t0 = blockIdx.x * 256;
    const __half* gA  = Wh + ((size_t)bh * T_LEN + t0) * S_LEN;
    const __half* gBh = Vh + (size_t)(b * S_LEN) * HID + h * HD;
    const __half* gBl = Vl + (size_t)(b * S_LEN) * HID + h * HD;

#define PV_LOAD(st, ko) do {                                              \
    const uint32_t b_ = sb + ((st) % 3) * 24576;                          \
    load_stage<256>(b_ + 0, gA + (ko), S_LEN, tid);                       \
    load_vtile(b_ + 16384, gBh + (size_t)(ko) * HID, HID, tid);           \
    load_vtile(b_ + 20480, gBl + (size_t)(ko) * HID, HID, tid);           \
    CP_COMMIT();                                                          \
  } while (0)

    float acc[4][4][4] = {};
    PV_LOAD(0, 0);
    PV_LOAD(1, 32);
    const int NST = S_LEN / 32;
    for (int s = 0; s < NST; s++) {
        if (s + 2 < NST) { PV_LOAD(s + 2, (s + 2) * 32); CP_WAIT(2); }
        else if (s + 1 < NST) { CP_WAIT(1); }
        else { CP_WAIT(0); }
        __syncthreads();
        const uint32_t cur = sb + (s % 3) * 24576;
        pv_stage2(cur, cur + 16384, cur + 20480, wmr, wnr, lane, acc);
        __syncthreads();
    }
#undef PV_LOAD

    const int mq = lane >> 2, nq = (lane & 3) * 2;
    #pragma unroll
    for (int mi = 0; mi < 4; mi++)
        #pragma unroll
        for (int half = 0; half < 2; half++) {
            const int t = t0 + wmr + mi * 16 + mq + half * 8;
            const size_t mo = (size_t)(b * T_LEN + t) * HID + h * HD;
            #pragma unroll
            for (int nj = 0; nj < 4; nj++) {
                const int n = wnr + nj * 8 + nq;
                __half2 h2;
                h2.x = __float2half_rn(acc[mi][nj][half * 2 + 0]);
                h2.y = __float2half_rn(acc[mi][nj][half * 2 + 1]);
                *(__half2*)(attH + mo + n) = h2;
            }
        }
}

// ---------------------------------------------------------------------------
extern "C" void kernel_launch(void* const* d_in, const int* in_sizes, int n_in,
                              void* d_out, int out_size) {
    const float* query  = (const float*)d_in[0];
    const float* key    = (const float*)d_in[1];
    const float* value  = (const float*)d_in[2];
    const int*   amask  = (const int*)d_in[3];
    const int*   segids = (const int*)d_in[4];
    const float* Wq = (const float*)d_in[5];
    const float* bq = (const float*)d_in[6];
    const float* Wk = (const float*)d_in[7];
    const float* bk = (const float*)d_in[8];
    const float* Wv = (const float*)d_in[9];
    const float* bv = (const float*)d_in[10];
    const float* Wo = (const float*)d_in[11];
    const float* bo = (const float*)d_in[12];
    const float* seg_emb = (const float*)d_in[13];
    float* out = (float*)d_out;

    __half *qh, *kh, *vh;
    __half *wqh, *wql, *wkh, *wkl, *wvh, *wvl, *woh, *wol;
    __half *Qh, *Ql, *Kh, *Kl, *Vh, *Vl, *Wh, *ah;
    float *Ssc;
    cudaGetSymbolAddress((void**)&qh, g_qh);
    cudaGetSymbolAddress((void**)&kh, g_kh);
    cudaGetSymbolAddress((void**)&vh, g_vh);
    cudaGetSymbolAddress((void**)&wqh, g_wqh); cudaGetSymbolAddress((void**)&wql, g_wql);
    cudaGetSymbolAddress((void**)&wkh, g_wkh); cudaGetSymbolAddress((void**)&wkl, g_wkl);
    cudaGetSymbolAddress((void**)&wvh, g_wvh); cudaGetSymbolAddress((void**)&wvl, g_wvl);
    cudaGetSymbolAddress((void**)&woh, g_woh); cudaGetSymbolAddress((void**)&wol, g_wol);
    cudaGetSymbolAddress((void**)&Qh, g_Qh);   cudaGetSymbolAddress((void**)&Ql, g_Ql);
    cudaGetSymbolAddress((void**)&Kh, g_Kh);   cudaGetSymbolAddress((void**)&Kl, g_Kl);
    cudaGetSymbolAddress((void**)&Vh, g_Vh);   cudaGetSymbolAddress((void**)&Vl, g_Vl);
    cudaGetSymbolAddress((void**)&Ssc, g_Ssc);
    cudaGetSymbolAddress((void**)&Wh, g_Wh);
    cudaGetSymbolAddress((void**)&ah, g_ah);

    cudaFuncSetAttribute(proj2<0>, cudaFuncAttributeMaxDynamicSharedMemorySize, 73728);
    cudaFuncSetAttribute(proj2<1>, cudaFuncAttributeMaxDynamicSharedMemorySize, 73728);
    cudaFuncSetAttribute(proj2<2>, cudaFuncAttributeMaxDynamicSharedMemorySize, 73728);
    cudaFuncSetAttribute(proj2<3>, cudaFuncAttributeMaxDynamicSharedMemorySize, 73728);
    cudaFuncSetAttribute(scores_gemm, cudaFuncAttributeMaxDynamicSharedMemorySize, 65536);
    cudaFuncSetAttribute(pv_gemm, cudaFuncAttributeMaxDynamicSharedMemorySize, 73728);

    // input + weight conversions
    conv_h<<<4096, 256>>>(query, qh);
    conv_h<<<32768, 256>>>(key, kh);
    conv_h<<<32768, 256>>>(value, vh);
    dim3 wtb(32, 8), wtg(32, 32);
    conv_wT<<<wtg, wtb>>>(Wq, wqh, wql);
    conv_wT<<<wtg, wtb>>>(Wk, wkh, wkl);
    conv_wT<<<wtg, wtb>>>(Wv, wvh, wvl);
    conv_wT<<<wtg, wtb>>>(Wo, woh, wol);

    // projections (2-product)
    proj2<0><<<dim3(8, 16),  256, 73728>>>(qh, wqh, wql, bq, nullptr, nullptr, nullptr, Qh, Ql);
    proj2<1><<<dim3(8, 128), 256, 73728>>>(kh, wkh, wkl, bk, segids, seg_emb, nullptr, Kh, Kl);
    proj2<3><<<dim3(8, 128), 256, 73728>>>(vh, wvh, wvl, bv, nullptr, nullptr, nullptr, Vh, Vl);

    // attention: L2-blocked scores -> softmax per 8-head chunk (reused scratch)
    for (int c = 0; c < NBH / CHUNK_H; c++) {
        const int bh0 = c * CHUNK_H;
        scores_gemm<<<dim3(32, 4, CHUNK_H), 256, 65536>>>(Qh, Ql, Kh, Kl, amask, Ssc, bh0);
        softmax_kernel<<<CHUNK_H * T_LEN, 256>>>(Ssc, Wh, bh0);
    }
    provenance_kernel<<<16384, 256>>>(Wh, out + (size_t)2048 * HID);
    pv_gemm<<<dim3(2, 64), 256, 73728>>>(Wh, Vh, Vl, ah);

    // output projection -> d_out
    proj2<2><<<dim3(8, 16), 256, 73728>>>(ah, woh, wol, bo, nullptr, nullptr, out, nullptr, nullptr);
}

// round 8
// speedup vs baseline: 4.1826x; 1.1379x over previous
#include <cuda_runtime.h>
#include <cuda_fp16.h>
#include <cstdint>
#include <cstddef>

#define B_SZ   4
#define T_LEN  512
#define S_LEN  4096
#define HID    1024
#define NH     16
#define HD     64
#define NBH    (B_SZ * NH)
#define CHUNK_H 8                 // heads per L2-resident score chunk

// ---------------------------------------------------------------------------
// helpers
// ---------------------------------------------------------------------------
__device__ __forceinline__ uint32_t smem_u32(const void* p) {
    uint32_t a;
    asm("{ .reg .u64 t; cvta.to.shared.u64 t, %1; cvt.u32.u64 %0, t; }" : "=r"(a) : "l"(p));
    return a;
}
// 64B-row tile swizzle (K-major tiles)
__device__ __forceinline__ uint32_t swzoff(int row, int chunk) {
    const int v = (row & 3) ^ ((row >> 2) & 1);
    return (uint32_t)(row * 64 + (((chunk ^ v) & 3) << 4));
}
__device__ __forceinline__ void cpa16(uint32_t dst, const void* src) {
    asm volatile("cp.async.cg.shared.global [%0], [%1], 16;" :: "r"(dst), "l"(src));
}
#define CP_COMMIT() asm volatile("cp.async.commit_group;" ::: "memory")
#define CP_WAIT(n)  asm volatile("cp.async.wait_group %0;" :: "n"(n) : "memory")

__device__ __forceinline__ void ldsm4(uint32_t* r, uint32_t a) {
    asm volatile("ldmatrix.sync.aligned.m8n8.x4.shared.b16 {%0,%1,%2,%3}, [%4];"
                 : "=r"(r[0]), "=r"(r[1]), "=r"(r[2]), "=r"(r[3]) : "r"(a));
}
__device__ __forceinline__ void ldsm4t(uint32_t* r, uint32_t a) {
    asm volatile("ldmatrix.sync.aligned.m8n8.x4.trans.shared.b16 {%0,%1,%2,%3}, [%4];"
                 : "=r"(r[0]), "=r"(r[1]), "=r"(r[2]), "=r"(r[3]) : "r"(a));
}
__device__ __forceinline__ void mma_f16(float* d, const uint32_t* a, const uint32_t* b) {
    asm volatile("mma.sync.aligned.m16n8k16.row.col.f32.f16.f16.f32 "
                 "{%0,%1,%2,%3}, {%4,%5,%6,%7}, {%8,%9}, {%0,%1,%2,%3};"
                 : "+f"(d[0]), "+f"(d[1]), "+f"(d[2]), "+f"(d[3])
                 : "r"(a[0]), "r"(a[1]), "r"(a[2]), "r"(a[3]), "r"(b[0]), "r"(b[1]));
}
__device__ __forceinline__ void split2h(float v, __half& h, __half& l) {
    h = __float2half_rn(v);
    l = __float2half_rn(v - __half2float(h));
}

// Load a [ROWS x 32] fp16 tile (row stride = stride elems) into swizzled SMEM
template<int ROWS>
__device__ __forceinline__ void load_stage(uint32_t sbuf, const __half* g,
                                           int stride, int tid) {
    #pragma unroll
    for (int i = tid; i < ROWS * 4; i += 256) {
        const int row = i >> 2, ch = i & 3;
        cpa16(sbuf + swzoff(row, ch), g + (size_t)row * stride + ch * 8);
    }
}
// Load a [32 x 64] fp16 tile (128B rows, chunk-XOR swizzle) for trans-B (V)
__device__ __forceinline__ void load_vtile(uint32_t sbuf, const __half* g,
                                           int stride, int tid) {
    if (tid < 256) {
        const int row = tid >> 3, ch = tid & 7;
        cpa16(sbuf + (uint32_t)(row * 128 + (((ch ^ row) & 7) << 4)),
              g + (size_t)row * stride + ch * 8);
    }
}

// One 32-k stage, A hi/lo + B hi/lo, 3 products (scores only).
__device__ __forceinline__ void stage_compute3(uint32_t sAh, uint32_t sAl,
                                               uint32_t sBh, uint32_t sBl,
                                               int wmr, int wnr, int lane,
                                               float (*acc)[4][4]) {
    const int l7 = lane & 7, l8 = (lane >> 3) & 1, l16 = (lane >> 4) & 1;
    const int arow = wmr + l7 + l8 * 8;
    const int brow = wnr + l16 * 8 + l7;
    #pragma unroll
    for (int ks = 0; ks < 2; ks++) {
        uint32_t ah[4][4], al[4][4], bh[2][4], bl[2][4];
        #pragma unroll
        for (int mi = 0; mi < 4; mi++) {
            const uint32_t off = swzoff(arow + mi * 16, ks * 2 + l16);
            ldsm4(ah[mi], sAh + off);
            ldsm4(al[mi], sAl + off);
        }
        #pragma unroll
        for (int p = 0; p < 2; p++) {
            const uint32_t off = swzoff(brow + p * 16, ks * 2 + l8);
            ldsm4(bh[p], sBh + off);
            ldsm4(bl[p], sBl + off);
        }
        #pragma unroll
        for (int mi = 0; mi < 4; mi++)
            #pragma unroll
            for (int nj = 0; nj < 4; nj++) {
                const uint32_t* bhj = &bh[nj >> 1][(nj & 1) * 2];
                const uint32_t* blj = &bl[nj >> 1][(nj & 1) * 2];
                mma_f16(acc[mi][nj], ah[mi], bhj);
                mma_f16(acc[mi][nj], ah[mi], blj);
                mma_f16(acc[mi][nj], al[mi], bhj);
            }
    }
}

// One 32-k stage, A single + B hi/lo, 2 products (Q/K projections).
__device__ __forceinline__ void stage_compute2(uint32_t sA,
                                               uint32_t sBh, uint32_t sBl,
                                               int wmr, int wnr, int lane,
                                               float (*acc)[4][4]) {
    const int l7 = lane & 7, l8 = (lane >> 3) & 1, l16 = (lane >> 4) & 1;
    const int arow = wmr + l7 + l8 * 8;
    const int brow = wnr + l16 * 8 + l7;
    #pragma unroll
    for (int ks = 0; ks < 2; ks++) {
        uint32_t ah[4][4], bh[2][4], bl[2][4];
        #pragma unroll
        for (int mi = 0; mi < 4; mi++)
            ldsm4(ah[mi], sA + swzoff(arow + mi * 16, ks * 2 + l16));
        #pragma unroll
        for (int p = 0; p < 2; p++) {
            const uint32_t off = swzoff(brow + p * 16, ks * 2 + l8);
            ldsm4(bh[p], sBh + off);
            ldsm4(bl[p], sBl + off);
        }
        #pragma unroll
        for (int mi = 0; mi < 4; mi++)
            #pragma unroll
            for (int nj = 0; nj < 4; nj++) {
                mma_f16(acc[mi][nj], ah[mi], &bh[nj >> 1][(nj & 1) * 2]);
                mma_f16(acc[mi][nj], ah[mi], &bl[nj >> 1][(nj & 1) * 2]);
            }
    }
}

// One 32-k stage, A single + B single, 1 product (V/O projections).
__device__ __forceinline__ void stage_compute1(uint32_t sA, uint32_t sB,
                                               int wmr, int wnr, int lane,
                                               float (*acc)[4][4]) {
    const int l7 = lane & 7, l8 = (lane >> 3) & 1, l16 = (lane >> 4) & 1;
    const int arow = wmr + l7 + l8 * 8;
    const int brow = wnr + l16 * 8 + l7;
    #pragma unroll
    for (int ks = 0; ks < 2; ks++) {
        uint32_t ah[4][4], bh[2][4];
        #pragma unroll
        for (int mi = 0; mi < 4; mi++)
            ldsm4(ah[mi], sA + swzoff(arow + mi * 16, ks * 2 + l16));
        #pragma unroll
        for (int p = 0; p < 2; p++)
            ldsm4(bh[p], sB + swzoff(brow + p * 16, ks * 2 + l8));
        #pragma unroll
        for (int mi = 0; mi < 4; mi++)
            #pragma unroll
            for (int nj = 0; nj < 4; nj++)
                mma_f16(acc[mi][nj], ah[mi], &bh[nj >> 1][(nj & 1) * 2]);
    }
}

// One 32-k PV stage: A = Wh single (K-major), B = V single via ldmatrix.trans
__device__ __forceinline__ void pv_stage1(uint32_t sA, uint32_t sB,
                                          int wmr, int wnr, int lane,
                                          float (*acc)[4][4]) {
    const int l7 = lane & 7, l16 = (lane >> 4) & 1;
    const int l8 = (lane >> 3) & 1;
    const int arow = wmr + l7 + l8 * 8;
    const int g = lane >> 3, q = lane & 7;
    #pragma unroll
    for (int ks = 0; ks < 2; ks++) {
        uint32_t ah[4][4];
        #pragma unroll
        for (int mi = 0; mi < 4; mi++)
            ldsm4(ah[mi], sA + swzoff(arow + mi * 16, ks * 2 + l16));
        #pragma unroll
        for (int half = 0; half < 2; half++) {
            const int r = ks * 16 + (g & 1) * 8 + q;
            const int cb = ((wnr + half * 16) >> 3) + (g >> 1);
            const uint32_t off = (uint32_t)(r * 128 + (((cb ^ r) & 7) << 4));
            uint32_t bh4[4];
            ldsm4t(bh4, sB + off);
            #pragma unroll
            for (int mi = 0; mi < 4; mi++)
                #pragma unroll
                for (int u = 0; u < 2; u++)
                    mma_f16(acc[mi][half * 2 + u], ah[mi], &bh4[u * 2]);
        }
    }
}

// ---------------- scratch ----------------
__device__ __half g_qh[2048 * HID];
__device__ __half g_kh[16384 * HID];
__device__ __half g_vh[16384 * HID];
__device__ __half g_wqh[HID * HID], g_wql[HID * HID];
__device__ __half g_wkh[HID * HID], g_wkl[HID * HID];
__device__ __half g_wvh[HID * HID];
__device__ __half g_woh[HID * HID];
__device__ __half g_Qh[2048 * HID],  g_Ql[2048 * HID];
__device__ __half g_Kh[16384 * HID], g_Kl[16384 * HID];
__device__ __half g_Vh[16384 * HID];
__device__ float  g_Ssc[(size_t)CHUNK_H * T_LEN * S_LEN];          // 64 MB reused
__device__ __half g_Wh[(size_t)NBH * T_LEN * S_LEN];
__device__ __half g_ah[2048 * HID];

// ---------------- conversions ----------------
__global__ __launch_bounds__(256)
void conv_h(const float* __restrict__ X, __half* __restrict__ H) {
    const size_t u = (size_t)blockIdx.x * 256 + threadIdx.x;
    float2 v = reinterpret_cast<const float2*>(X)[u];
    reinterpret_cast<__half2*>(H)[u] =
        __halves2half2(__float2half_rn(v.x), __float2half_rn(v.y));
}
__global__ __launch_bounds__(256)
void conv_wT(const float* __restrict__ W, __half* __restrict__ WTh,
             __half* __restrict__ WTl) {
    __shared__ float t[32][33];
    const int k0 = blockIdx.x * 32, n0 = blockIdx.y * 32;
    const int tx = threadIdx.x, ty = threadIdx.y;
    for (int r = ty; r < 32; r += 8) t[r][tx] = W[(size_t)(k0 + r) * HID + n0 + tx];
    __syncthreads();
    for (int r = ty; r < 32; r += 8) {
        __half h, l;
        split2h(t[tx][r], h, l);
        WTh[(size_t)(n0 + r) * HID + k0 + tx] = h;
        if (WTl) WTl[(size_t)(n0 + r) * HID + k0 + tx] = l;
    }
}

// ---------------- Q/K projection (2-product, A single, 3-stage) ----------------
// MODE 0: Q (bias, *0.125, hi/lo out) 1: K (bias+seg, hi/lo out)
template<int MODE>
__global__ __launch_bounds__(256)
void proj2(const __half* __restrict__ A,
           const __half* __restrict__ Bh, const __half* __restrict__ Bl,
           const float* __restrict__ bias, const int* __restrict__ segids,
           const float* __restrict__ seg_emb,
           __half* __restrict__ outH, __half* __restrict__ outL) {
    extern __shared__ __align__(128) char sm[];
    const uint32_t sb = smem_u32(sm);
    const int tid = threadIdx.x, lane = tid & 31, w = tid >> 5;
    const int wmr = (w & 1) * 64, wnr = (w >> 1) * 32;
    const int n0 = blockIdx.x * 128, m0 = blockIdx.y * 128;
    const __half* gA  = A + (size_t)m0 * HID;
    const __half* gBh = Bh + (size_t)n0 * HID;
    const __half* gBl = Bl + (size_t)n0 * HID;

#define PJ_LOAD(st, ko) do {                                \
    const uint32_t b_ = sb + ((st) % 3) * 24576;            \
    load_stage<128>(b_ + 0,     gA  + (ko), HID, tid);      \
    load_stage<128>(b_ + 8192,  gBh + (ko), HID, tid);      \
    load_stage<128>(b_ + 16384, gBl + (ko), HID, tid);      \
    CP_COMMIT();                                            \
  } while (0)

    float acc[4][4][4] = {};
    PJ_LOAD(0, 0);
    PJ_LOAD(1, 32);
    const int NST = HID / 32;
    for (int s = 0; s < NST; s++) {
        if (s + 2 < NST) { PJ_LOAD(s + 2, (s + 2) * 32); CP_WAIT(2); }
        else if (s + 1 < NST) { CP_WAIT(1); }
        else { CP_WAIT(0); }
        __syncthreads();
        const uint32_t cur = sb + (s % 3) * 24576;
        stage_compute2(cur, cur + 8192, cur + 16384, wmr, wnr, lane, acc);
        __syncthreads();
    }
#undef PJ_LOAD

    const int mq = lane >> 2, nq = (lane & 3) * 2;
    #pragma unroll
    for (int mi = 0; mi < 4; mi++)
        #pragma unroll
        for (int half = 0; half < 2; half++) {
            const int m = m0 + wmr + mi * 16 + mq + half * 8;
            const int sid = (MODE == 1) ? segids[m] : 0;
            #pragma unroll
            for (int nj = 0; nj < 4; nj++) {
                const int n = n0 + wnr + nj * 8 + nq;
                float v0 = acc[mi][nj][half * 2 + 0] + bias[n];
                float v1 = acc[mi][nj][half * 2 + 1] + bias[n + 1];
                if (MODE == 1) {
                    v0 += seg_emb[(size_t)sid * HID + n];
                    v1 += seg_emb[(size_t)sid * HID + n + 1];
                }
                if (MODE == 0) { v0 *= 0.125f; v1 *= 0.125f; }
                __half2 h2, l2;
                split2h(v0, h2.x, l2.x);
                split2h(v1, h2.y, l2.y);
                *(__half2*)(outH + (size_t)m * HID + n) = h2;
                *(__half2*)(outL + (size_t)m * HID + n) = l2;
            }
        }
}

// ---------------- V/O projection (1-product, 3-stage) ----------------
// MODE 0: V (bias, fp16 out)  1: O (bias, fp32 out)
template<int MODE>
__global__ __launch_bounds__(256)
void proj1(const __half* __restrict__ A, const __half* __restrict__ B,
           const float* __restrict__ bias, float* __restrict__ outF,
           __half* __restrict__ outH) {
    extern __shared__ __align__(128) char sm[];
    const uint32_t sb = smem_u32(sm);
    const int tid = threadIdx.x, lane = tid & 31, w = tid >> 5;
    const int wmr = (w & 1) * 64, wnr = (w >> 1) * 32;
    const int n0 = blockIdx.x * 128, m0 = blockIdx.y * 128;
    const __half* gA = A + (size_t)m0 * HID;
    const __half* gB = B + (size_t)n0 * HID;

#define P1_LOAD(st, ko) do {                                \
    const uint32_t b_ = sb + ((st) % 3) * 16384;            \
    load_stage<128>(b_ + 0,    gA + (ko), HID, tid);        \
    load_stage<128>(b_ + 8192, gB + (ko), HID, tid);        \
    CP_COMMIT();                                            \
  } while (0)

    float acc[4][4][4] = {};
    P1_LOAD(0, 0);
    P1_LOAD(1, 32);
    const int NST = HID / 32;
    for (int s = 0; s < NST; s++) {
        if (s + 2 < NST) { P1_LOAD(s + 2, (s + 2) * 32); CP_WAIT(2); }
        else if (s + 1 < NST) { CP_WAIT(1); }
        else { CP_WAIT(0); }
        __syncthreads();
        const uint32_t cur = sb + (s % 3) * 16384;
        stage_compute1(cur, cur + 8192, wmr, wnr, lane, acc);
        __syncthreads();
    }
#undef P1_LOAD

    const int mq = lane >> 2, nq = (lane & 3) * 2;
    #pragma unroll
    for (int mi = 0; mi < 4; mi++)
        #pragma unroll
        for (int half = 0; half < 2; half++) {
            const int m = m0 + wmr + mi * 16 + mq + half * 8;
            #pragma unroll
            for (int nj = 0; nj < 4; nj++) {
                const int n = n0 + wnr + nj * 8 + nq;
                float v0 = acc[mi][nj][half * 2 + 0] + bias[n];
                float v1 = acc[mi][nj][half * 2 + 1] + bias[n + 1];
                if (MODE == 0) {
                    __half2 h2;
                    h2.x = __float2half_rn(v0);
                    h2.y = __float2half_rn(v1);
                    *(__half2*)(outH + (size_t)m * HID + n) = h2;
                } else {
                    *(float2*)(outF + (size_t)m * HID + n) = make_float2(v0, v1);
                }
            }
        }
}

// ---------------- scores chunk: Sc[z,t,s] = Q·K^T (scale folded into Q), 3-product ----------------
__global__ __launch_bounds__(256)
void scores_gemm(const __half* __restrict__ Qh, const __half* __restrict__ Ql,
                 const __half* __restrict__ Kh, const __half* __restrict__ Kl,
                 const int* __restrict__ amask, float* __restrict__ Sc, int bh0) {
    extern __shared__ __align__(128) char sm[];
    const uint32_t sb = smem_u32(sm);
    const int tid = threadIdx.x, lane = tid & 31, w = tid >> 5;
    const int wmr = (w & 1) * 64, wnr = (w >> 1) * 32;
    const int zz = blockIdx.z, bh = bh0 + zz, b = bh >> 4, h = bh & 15;
    const int t0 = blockIdx.y * 128, s0 = blockIdx.x * 128;
    const __half* gAh = Qh + (size_t)(b * T_LEN + t0) * HID + h * HD;
    const __half* gAl = Ql + (size_t)(b * T_LEN + t0) * HID + h * HD;
    const __half* gBh = Kh + (size_t)(b * S_LEN + s0) * HID + h * HD;
    const __half* gBl = Kl + (size_t)(b * S_LEN + s0) * HID + h * HD;

    float acc[4][4][4] = {};
    load_stage<128>(sb + 0,     gAh, HID, tid);
    load_stage<128>(sb + 8192,  gAl, HID, tid);
    load_stage<128>(sb + 16384, gBh, HID, tid);
    load_stage<128>(sb + 24576, gBl, HID, tid);
    CP_COMMIT();
    for (int s = 0; s < 2; s++) {
        const uint32_t cur = sb + (s & 1) * 32768;
        if (s == 0) {
            const uint32_t nxt = sb + 32768;
            load_stage<128>(nxt + 0,     gAh + 32, HID, tid);
            load_stage<128>(nxt + 8192,  gAl + 32, HID, tid);
            load_stage<128>(nxt + 16384, gBh + 32, HID, tid);
            load_stage<128>(nxt + 24576, gBl + 32, HID, tid);
            CP_COMMIT();
            CP_WAIT(1);
        } else {
            CP_WAIT(0);
        }
        __syncthreads();
        stage_compute3(cur, cur + 8192, cur + 16384, cur + 24576, wmr, wnr, lane, acc);
        __syncthreads();
    }

    const int mq = lane >> 2, nq = (lane & 3) * 2;
    float* dstB = Sc + (size_t)zz * T_LEN * S_LEN;
    #pragma unroll
    for (int mi = 0; mi < 4; mi++)
        #pragma unroll
        for (int half = 0; half < 2; half++) {
            const int t = t0 + wmr + mi * 16 + mq + half * 8;
            #pragma unroll
            for (int nj = 0; nj < 4; nj++) {
                const int sidx = s0 + wnr + nj * 8 + nq;
                float v0 = acc[mi][nj][half * 2 + 0];
                float v1 = acc[mi][nj][half * 2 + 1];
                if (amask[b * S_LEN + sidx] == 0) v0 = -1e9f;
                if (amask[b * S_LEN + sidx + 1] == 0) v1 = -1e9f;
                *(float2*)(dstB + (size_t)t * S_LEN + sidx) = make_float2(v0, v1);
            }
        }
}

// ---------------- softmax chunk: scratch row -> fp16 hi weights ----------------
__global__ __launch_bounds__(256)
void softmax_kernel(const float* __restrict__ Sc, __half* __restrict__ Wh, int bh0) {
    const int r = blockIdx.x, z = r >> 9, t = r & 511;
    const size_t sbase = ((size_t)z * T_LEN + t) * S_LEN;
    const size_t wbase = ((size_t)(bh0 + z) * T_LEN + t) * S_LEN;
    const int tid = threadIdx.x;
    __shared__ float red[8];
    float v[16];
    #pragma unroll
    for (int i = 0; i < 16; i++) v[i] = Sc[sbase + tid + i * 256];
    float m = -1e30f;
    #pragma unroll
    for (int i = 0; i < 16; i++) m = fmaxf(m, v[i]);
    #pragma unroll
    for (int o = 16; o; o >>= 1) m = fmaxf(m, __shfl_xor_sync(0xFFFFFFFFu, m, o));
    if ((tid & 31) == 0) red[tid >> 5] = m;
    __syncthreads();
    float gmax = red[0];
    #pragma unroll
    for (int w = 1; w < 8; w++) gmax = fmaxf(gmax, red[w]);
    __syncthreads();
    float s = 0.f;
    #pragma unroll
    for (int i = 0; i < 16; i++) { v[i] = expf(v[i] - gmax); s += v[i]; }
    #pragma unroll
    for (int o = 16; o; o >>= 1) s += __shfl_xor_sync(0xFFFFFFFFu, s, o);
    if ((tid & 31) == 0) red[tid >> 5] = s;
    __syncthreads();
    float tot = red[0];
    #pragma unroll
    for (int w = 1; w < 8; w++) tot += red[w];
    const float inv = 1.0f / tot;
    #pragma unroll
    for (int i = 0; i < 16; i++)
        Wh[wbase + tid + i * 256] = __float2half_rn(v[i] * inv);
}

// ---------------- provenance = head-mean of Wh ----------------
__global__ __launch_bounds__(256)
void provenance_kernel(const __half* __restrict__ Wh, float* __restrict__ out) {
    const size_t u = (size_t)blockIdx.x * 256 + threadIdx.x;
    const int s2 = (int)(u & 2047);
    const int t  = (int)((u >> 11) & 511);
    const int b  = (int)(u >> 20);
    float s0 = 0.f, s1 = 0.f;
    #pragma unroll
    for (int h = 0; h < NH; h++) {
        const size_t o = (((size_t)(b * NH + h) * T_LEN + t) * S_LEN) / 2 + s2;
        __half2 h2 = reinterpret_cast<const __half2*>(Wh)[o];
        s0 += __half2float(h2.x);
        s1 += __half2float(h2.y);
    }
    reinterpret_cast<float2*>(out)[u] = make_float2(s0 * (1.0f / NH), s1 * (1.0f / NH));
}

// ---------------- P·V: C[256,64] per CTA, K=4096, single-product, 3-stage ----------------
__global__ __launch_bounds__(256)
void pv_gemm(const __half* __restrict__ Wh, const __half* __restrict__ Vh,
             __half* __restrict__ attH) {
    extern __shared__ __align__(128) char sm[];
    const uint32_t sb = smem_u32(sm);
    const int tid = threadIdx.x, lane = tid & 31, w = tid >> 5;
    const int wmr = (w & 3) * 64, wnr = (w >> 2) * 32;
    const int bh = blockIdx.y, b = bh >> 4, h = bh & 15;
    const int t0 = blockIdx.x * 256;
    const __half* gA = Wh + ((size_t)bh * T_LEN + t0) * S_LEN;
    const __half* gB = Vh + (size_t)(b * S_LEN) * HID + h * HD;

#define PV_LOAD(st, ko) do {                                              \
    const uint32_t b_ = sb + ((st) % 3) * 20480;                          \
    load_stage<256>(b_ + 0, gA + (ko), S_LEN, tid);                       \
    load_vtile(b_ + 16384, gB + (size_t)(ko) * HID, HID, tid);            \
    CP_COMMIT();                                                          \
  } while (0)

    float acc[4][4][4] = {};
    PV_LOAD(0, 0);
    PV_LOAD(1, 32);
    const int NST = S_LEN / 32;
    for (int s = 0; s < NST; s++) {
        if (s + 2 < NST) { PV_LOAD(s + 2, (s + 2) * 32); CP_WAIT(2); }
        else if (s + 1 < NST) { CP_WAIT(1); }
        else { CP_WAIT(0); }
        __syncthreads();
        const uint32_t cur = sb + (s % 3) * 20480;
        pv_stage1(cur, cur + 16384, wmr, wnr, lane, acc);
        __syncthreads();
    }
#undef PV_LOAD

    const int mq = lane >> 2, nq = (lane & 3) * 2;
    #pragma unroll
    for (int mi = 0; mi < 4; mi++)
        #pragma unroll
        for (int half = 0; half < 2; half++) {
            const int t = t0 + wmr + mi * 16 + mq + half * 8;
            const size_t mo = (size_t)(b * T_LEN + t) * HID + h * HD;
            #pragma unroll
            for (int nj = 0; nj < 4; nj++) {
                const int n = wnr + nj * 8 + nq;
                __half2 h2;
                h2.x = __float2half_rn(acc[mi][nj][half * 2 + 0]);
                h2.y = __float2half_rn(acc[mi][nj][half * 2 + 1]);
                *(__half2*)(attH + mo + n) = h2;
            }
        }
}

// ---------------------------------------------------------------------------
extern "C" void kernel_launch(void* const* d_in, const int* in_sizes, int n_in,
                              void* d_out, int out_size) {
    const float* query  = (const float*)d_in[0];
    const float* key    = (const float*)d_in[1];
    const float* value  = (const float*)d_in[2];
    const int*   amask  = (const int*)d_in[3];
    const int*   segids = (const int*)d_in[4];
    const float* Wq = (const float*)d_in[5];
    const float* bq = (const float*)d_in[6];
    const float* Wk = (const float*)d_in[7];
    const float* bk = (const float*)d_in[8];
    const float* Wv = (const float*)d_in[9];
    const float* bv = (const float*)d_in[10];
    const float* Wo = (const float*)d_in[11];
    const float* bo = (const float*)d_in[12];
    const float* seg_emb = (const float*)d_in[13];
    float* out = (float*)d_out;

    __half *qh, *kh, *vh;
    __half *wqh, *wql, *wkh, *wkl, *wvh, *woh;
    __half *Qh, *Ql, *Kh, *Kl, *Vh, *Wh, *ah;
    float *Ssc;
    cudaGetSymbolAddress((void**)&qh, g_qh);
    cudaGetSymbolAddress((void**)&kh, g_kh);
    cudaGetSymbolAddress((void**)&vh, g_vh);
    cudaGetSymbolAddress((void**)&wqh, g_wqh); cudaGetSymbolAddress((void**)&wql, g_wql);
    cudaGetSymbolAddress((void**)&wkh, g_wkh); cudaGetSymbolAddress((void**)&wkl, g_wkl);
    cudaGetSymbolAddress((void**)&wvh, g_wvh);
    cudaGetSymbolAddress((void**)&woh, g_woh);
    cudaGetSymbolAddress((void**)&Qh, g_Qh);   cudaGetSymbolAddress((void**)&Ql, g_Ql);
    cudaGetSymbolAddress((void**)&Kh, g_Kh);   cudaGetSymbolAddress((void**)&Kl, g_Kl);
    cudaGetSymbolAddress((void**)&Vh, g_Vh);
    cudaGetSymbolAddress((void**)&Ssc, g_Ssc);
    cudaGetSymbolAddress((void**)&Wh, g_Wh);
    cudaGetSymbolAddress((void**)&ah, g_ah);

    cudaFuncSetAttribute(proj2<0>, cudaFuncAttributeMaxDynamicSharedMemorySize, 73728);
    cudaFuncSetAttribute(proj2<1>, cudaFuncAttributeMaxDynamicSharedMemorySize, 73728);
    cudaFuncSetAttribute(proj1<0>, cudaFuncAttributeMaxDynamicSharedMemorySize, 49152);
    cudaFuncSetAttribute(proj1<1>, cudaFuncAttributeMaxDynamicSharedMemorySize, 49152);
    cudaFuncSetAttribute(scores_gemm, cudaFuncAttributeMaxDynamicSharedMemorySize, 65536);
    cudaFuncSetAttribute(pv_gemm, cudaFuncAttributeMaxDynamicSharedMemorySize, 61440);

    // input + weight conversions
    conv_h<<<4096, 256>>>(query, qh);
    conv_h<<<32768, 256>>>(key, kh);
    conv_h<<<32768, 256>>>(value, vh);
    dim3 wtb(32, 8), wtg(32, 32);
    conv_wT<<<wtg, wtb>>>(Wq, wqh, wql);
    conv_wT<<<wtg, wtb>>>(Wk, wkh, wkl);
    conv_wT<<<wtg, wtb>>>(Wv, wvh, nullptr);
    conv_wT<<<wtg, wtb>>>(Wo, woh, nullptr);

    // projections
    proj2<0><<<dim3(8, 16),  256, 73728>>>(qh, wqh, wql, bq, nullptr, nullptr, Qh, Ql);
    proj2<1><<<dim3(8, 128), 256, 73728>>>(kh, wkh, wkl, bk, segids, seg_emb, Kh, Kl);
    proj1<0><<<dim3(8, 128), 256, 49152>>>(vh, wvh, bv, nullptr, Vh);

    // attention: L2-blocked scores -> softmax per 8-head chunk (reused scratch)
    for (int c = 0; c < NBH / CHUNK_H; c++) {
        const int bh0 = c * CHUNK_H;
        scores_gemm<<<dim3(32, 4, CHUNK_H), 256, 65536>>>(Qh, Ql, Kh, Kl, amask, Ssc, bh0);
        softmax_kernel<<<CHUNK_H * T_LEN, 256>>>(Ssc, Wh, bh0);
    }
    provenance_kernel<<<16384, 256>>>(Wh, out + (size_t)2048 * HID);
    pv_gemm<<<dim3(2, 64), 256, 61440>>>(Wh, Vh, ah);

    // output projection -> d_out
    proj1<1><<<dim3(8, 16), 256, 49152>>>(ah, woh, bo, out, nullptr);
}

// round 9
// speedup vs baseline: 4.8453x; 1.1585x over previous
#include <cuda_runtime.h>
#include <cuda_fp16.h>
#include <cstdint>
#include <cstddef>

#define B_SZ   4
#define T_LEN  512
#define S_LEN  4096
#define HID    1024
#define NH     16
#define HD     64
#define NBH    (B_SZ * NH)
#define CHUNK_H 8                 // heads per L2-resident score chunk

// ---------------------------------------------------------------------------
// helpers
// ---------------------------------------------------------------------------
__device__ __forceinline__ uint32_t smem_u32(const void* p) {
    uint32_t a;
    asm("{ .reg .u64 t; cvta.to.shared.u64 t, %1; cvt.u32.u64 %0, t; }" : "=r"(a) : "l"(p));
    return a;
}
// 64B-row tile swizzle (K-major tiles)
__device__ __forceinline__ uint32_t swzoff(int row, int chunk) {
    const int v = (row & 3) ^ ((row >> 2) & 1);
    return (uint32_t)(row * 64 + (((chunk ^ v) & 3) << 4));
}
__device__ __forceinline__ void cpa16(uint32_t dst, const void* src) {
    asm volatile("cp.async.cg.shared.global [%0], [%1], 16;" :: "r"(dst), "l"(src));
}
#define CP_COMMIT() asm volatile("cp.async.commit_group;" ::: "memory")
#define CP_WAIT(n)  asm volatile("cp.async.wait_group %0;" :: "n"(n) : "memory")

__device__ __forceinline__ void ldsm4(uint32_t* r, uint32_t a) {
    asm volatile("ldmatrix.sync.aligned.m8n8.x4.shared.b16 {%0,%1,%2,%3}, [%4];"
                 : "=r"(r[0]), "=r"(r[1]), "=r"(r[2]), "=r"(r[3]) : "r"(a));
}
__device__ __forceinline__ void ldsm4t(uint32_t* r, uint32_t a) {
    asm volatile("ldmatrix.sync.aligned.m8n8.x4.trans.shared.b16 {%0,%1,%2,%3}, [%4];"
                 : "=r"(r[0]), "=r"(r[1]), "=r"(r[2]), "=r"(r[3]) : "r"(a));
}
__device__ __forceinline__ void mma_f16(float* d, const uint32_t* a, const uint32_t* b) {
    asm volatile("mma.sync.aligned.m16n8k16.row.col.f32.f16.f16.f32 "
                 "{%0,%1,%2,%3}, {%4,%5,%6,%7}, {%8,%9}, {%0,%1,%2,%3};"
                 : "+f"(d[0]), "+f"(d[1]), "+f"(d[2]), "+f"(d[3])
                 : "r"(a[0]), "r"(a[1]), "r"(a[2]), "r"(a[3]), "r"(b[0]), "r"(b[1]));
}
__device__ __forceinline__ void split2h(float v, __half& h, __half& l) {
    h = __float2half_rn(v);
    l = __float2half_rn(v - __half2float(h));
}

// Load a [ROWS x 32] fp16 tile (row stride = stride elems) into swizzled SMEM
template<int ROWS>
__device__ __forceinline__ void load_stage(uint32_t sbuf, const __half* g,
                                           int stride, int tid) {
    #pragma unroll
    for (int i = tid; i < ROWS * 4; i += 256) {
        const int row = i >> 2, ch = i & 3;
        cpa16(sbuf + swzoff(row, ch), g + (size_t)row * stride + ch * 8);
    }
}
// Load a [32 x 64] fp16 tile (128B rows, chunk-XOR swizzle) for trans-B (V)
__device__ __forceinline__ void load_vtile(uint32_t sbuf, const __half* g,
                                           int stride, int tid) {
    if (tid < 256) {
        const int row = tid >> 3, ch = tid & 7;
        cpa16(sbuf + (uint32_t)(row * 128 + (((ch ^ row) & 7) << 4)),
              g + (size_t)row * stride + ch * 8);
    }
}

// One 32-k stage, A single + B hi/lo, 2 products (Q/K projections).
__device__ __forceinline__ void stage_compute2(uint32_t sA,
                                               uint32_t sBh, uint32_t sBl,
                                               int wmr, int wnr, int lane,
                                               float (*acc)[4][4]) {
    const int l7 = lane & 7, l8 = (lane >> 3) & 1, l16 = (lane >> 4) & 1;
    const int arow = wmr + l7 + l8 * 8;
    const int brow = wnr + l16 * 8 + l7;
    #pragma unroll
    for (int ks = 0; ks < 2; ks++) {
        uint32_t ah[4][4], bh[2][4], bl[2][4];
        #pragma unroll
        for (int mi = 0; mi < 4; mi++)
            ldsm4(ah[mi], sA + swzoff(arow + mi * 16, ks * 2 + l16));
        #pragma unroll
        for (int p = 0; p < 2; p++) {
            const uint32_t off = swzoff(brow + p * 16, ks * 2 + l8);
            ldsm4(bh[p], sBh + off);
            ldsm4(bl[p], sBl + off);
        }
        #pragma unroll
        for (int mi = 0; mi < 4; mi++)
            #pragma unroll
            for (int nj = 0; nj < 4; nj++) {
                mma_f16(acc[mi][nj], ah[mi], &bh[nj >> 1][(nj & 1) * 2]);
                mma_f16(acc[mi][nj], ah[mi], &bl[nj >> 1][(nj & 1) * 2]);
            }
    }
}

// One 32-k stage, A single + B single, 1 product (V/O projections, scores).
__device__ __forceinline__ void stage_compute1(uint32_t sA, uint32_t sB,
                                               int wmr, int wnr, int lane,
                                               float (*acc)[4][4]) {
    const int l7 = lane & 7, l8 = (lane >> 3) & 1, l16 = (lane >> 4) & 1;
    const int arow = wmr + l7 + l8 * 8;
    const int brow = wnr + l16 * 8 + l7;
    #pragma unroll
    for (int ks = 0; ks < 2; ks++) {
        uint32_t ah[4][4], bh[2][4];
        #pragma unroll
        for (int mi = 0; mi < 4; mi++)
            ldsm4(ah[mi], sA + swzoff(arow + mi * 16, ks * 2 + l16));
        #pragma unroll
        for (int p = 0; p < 2; p++)
            ldsm4(bh[p], sB + swzoff(brow + p * 16, ks * 2 + l8));
        #pragma unroll
        for (int mi = 0; mi < 4; mi++)
            #pragma unroll
            for (int nj = 0; nj < 4; nj++)
                mma_f16(acc[mi][nj], ah[mi], &bh[nj >> 1][(nj & 1) * 2]);
    }
}

// One 32-k PV stage: A = Wh single (K-major, MI m-frags), B = V via ldmatrix.trans
template<int MI>
__device__ __forceinline__ void pv_stage1(uint32_t sA, uint32_t sB,
                                          int wmr, int wnr, int lane,
                                          float (*acc)[4][4]) {
    const int l7 = lane & 7, l8 = (lane >> 3) & 1, l16 = (lane >> 4) & 1;
    const int arow = wmr + l7 + l8 * 8;
    const int g = lane >> 3, q = lane & 7;
    #pragma unroll
    for (int ks = 0; ks < 2; ks++) {
        uint32_t ah[MI][4];
        #pragma unroll
        for (int mi = 0; mi < MI; mi++)
            ldsm4(ah[mi], sA + swzoff(arow + mi * 16, ks * 2 + l16));
        #pragma unroll
        for (int half = 0; half < 2; half++) {
            const int r = ks * 16 + (g & 1) * 8 + q;
            const int cb = ((wnr + half * 16) >> 3) + (g >> 1);
            const uint32_t off = (uint32_t)(r * 128 + (((cb ^ r) & 7) << 4));
            uint32_t bh4[4];
            ldsm4t(bh4, sB + off);
            #pragma unroll
            for (int mi = 0; mi < MI; mi++)
                #pragma unroll
                for (int u = 0; u < 2; u++)
                    mma_f16(acc[mi][half * 2 + u], ah[mi], &bh4[u * 2]);
        }
    }
}

// ---------------- scratch ----------------
__device__ __half g_qh[2048 * HID];
__device__ __half g_kh[16384 * HID];
__device__ __half g_vh[16384 * HID];
__device__ __half g_wqh[HID * HID], g_wql[HID * HID];
__device__ __half g_wkh[HID * HID], g_wkl[HID * HID];
__device__ __half g_wvh[HID * HID];
__device__ __half g_woh[HID * HID];
__device__ __half g_Qh[2048 * HID];
__device__ __half g_Kh[16384 * HID];
__device__ __half g_Vh[16384 * HID];
__device__ float  g_Ssc[(size_t)CHUNK_H * T_LEN * S_LEN];          // 64 MB reused
__device__ __half g_Wh[(size_t)NBH * T_LEN * S_LEN];
__device__ __half g_ah[2048 * HID];

// ---------------- conversions ----------------
__global__ __launch_bounds__(256)
void conv_h(const float* __restrict__ X, __half* __restrict__ H) {
    const size_t u = (size_t)blockIdx.x * 256 + threadIdx.x;
    float2 v = reinterpret_cast<const float2*>(X)[u];
    reinterpret_cast<__half2*>(H)[u] =
        __halves2half2(__float2half_rn(v.x), __float2half_rn(v.y));
}
__global__ __launch_bounds__(256)
void conv_wT(const float* __restrict__ W, __half* __restrict__ WTh,
             __half* __restrict__ WTl) {
    __shared__ float t[32][33];
    const int k0 = blockIdx.x * 32, n0 = blockIdx.y * 32;
    const int tx = threadIdx.x, ty = threadIdx.y;
    for (int r = ty; r < 32; r += 8) t[r][tx] = W[(size_t)(k0 + r) * HID + n0 + tx];
    __syncthreads();
    for (int r = ty; r < 32; r += 8) {
        __half h, l;
        split2h(t[tx][r], h, l);
        WTh[(size_t)(n0 + r) * HID + k0 + tx] = h;
        if (WTl) WTl[(size_t)(n0 + r) * HID + k0 + tx] = l;
    }
}

// ---------------- Q/K projection (2-product weights, single fp16 out) ----------------
// MODE 0: Q (bias, *0.125) 1: K (bias+seg)
template<int MODE>
__global__ __launch_bounds__(256)
void proj2(const __half* __restrict__ A,
           const __half* __restrict__ Bh, const __half* __restrict__ Bl,
           const float* __restrict__ bias, const int* __restrict__ segids,
           const float* __restrict__ seg_emb, __half* __restrict__ outH) {
    extern __shared__ __align__(128) char sm[];
    const uint32_t sb = smem_u32(sm);
    const int tid = threadIdx.x, lane = tid & 31, w = tid >> 5;
    const int wmr = (w & 1) * 64, wnr = (w >> 1) * 32;
    const int n0 = blockIdx.x * 128, m0 = blockIdx.y * 128;
    const __half* gA  = A + (size_t)m0 * HID;
    const __half* gBh = Bh + (size_t)n0 * HID;
    const __half* gBl = Bl + (size_t)n0 * HID;

#define PJ_LOAD(st, ko) do {                                \
    const uint32_t b_ = sb + ((st) % 3) * 24576;            \
    load_stage<128>(b_ + 0,     gA  + (ko), HID, tid);      \
    load_stage<128>(b_ + 8192,  gBh + (ko), HID, tid);      \
    load_stage<128>(b_ + 16384, gBl + (ko), HID, tid);      \
    CP_COMMIT();                                            \
  } while (0)

    float acc[4][4][4] = {};
    PJ_LOAD(0, 0);
    PJ_LOAD(1, 32);
    const int NST = HID / 32;
    for (int s = 0; s < NST; s++) {
        if (s + 2 < NST) { PJ_LOAD(s + 2, (s + 2) * 32); CP_WAIT(2); }
        else if (s + 1 < NST) { CP_WAIT(1); }
        else { CP_WAIT(0); }
        __syncthreads();
        const uint32_t cur = sb + (s % 3) * 24576;
        stage_compute2(cur, cur + 8192, cur + 16384, wmr, wnr, lane, acc);
        __syncthreads();
    }
#undef PJ_LOAD

    const int mq = lane >> 2, nq = (lane & 3) * 2;
    #pragma unroll
    for (int mi = 0; mi < 4; mi++)
        #pragma unroll
        for (int half = 0; half < 2; half++) {
            const int m = m0 + wmr + mi * 16 + mq + half * 8;
            const int sid = (MODE == 1) ? segids[m] : 0;
            #pragma unroll
            for (int nj = 0; nj < 4; nj++) {
                const int n = n0 + wnr + nj * 8 + nq;
                float v0 = acc[mi][nj][half * 2 + 0] + bias[n];
                float v1 = acc[mi][nj][half * 2 + 1] + bias[n + 1];
                if (MODE == 1) {
                    v0 += seg_emb[(size_t)sid * HID + n];
                    v1 += seg_emb[(size_t)sid * HID + n + 1];
                }
                if (MODE == 0) { v0 *= 0.125f; v1 *= 0.125f; }
                __half2 h2;
                h2.x = __float2half_rn(v0);
                h2.y = __float2half_rn(v1);
                *(__half2*)(outH + (size_t)m * HID + n) = h2;
            }
        }
}

// ---------------- V/O projection (1-product, 3-stage) ----------------
// MODE 0: V (bias, fp16 out)  1: O (bias, fp32 out)
template<int MODE>
__global__ __launch_bounds__(256)
void proj1(const __half* __restrict__ A, const __half* __restrict__ B,
           const float* __restrict__ bias, float* __restrict__ outF,
           __half* __restrict__ outH) {
    extern __shared__ __align__(128) char sm[];
    const uint32_t sb = smem_u32(sm);
    const int tid = threadIdx.x, lane = tid & 31, w = tid >> 5;
    const int wmr = (w & 1) * 64, wnr = (w >> 1) * 32;
    const int n0 = blockIdx.x * 128, m0 = blockIdx.y * 128;
    const __half* gA = A + (size_t)m0 * HID;
    const __half* gB = B + (size_t)n0 * HID;

#define P1_LOAD(st, ko) do {                                \
    const uint32_t b_ = sb + ((st) % 3) * 16384;            \
    load_stage<128>(b_ + 0,    gA + (ko), HID, tid);        \
    load_stage<128>(b_ + 8192, gB + (ko), HID, tid);        \
    CP_COMMIT();                                            \
  } while (0)

    float acc[4][4][4] = {};
    P1_LOAD(0, 0);
    P1_LOAD(1, 32);
    const int NST = HID / 32;
    for (int s = 0; s < NST; s++) {
        if (s + 2 < NST) { P1_LOAD(s + 2, (s + 2) * 32); CP_WAIT(2); }
        else if (s + 1 < NST) { CP_WAIT(1); }
        else { CP_WAIT(0); }
        __syncthreads();
        const uint32_t cur = sb + (s % 3) * 16384;
        stage_compute1(cur, cur + 8192, wmr, wnr, lane, acc);
        __syncthreads();
    }
#undef P1_LOAD

    const int mq = lane >> 2, nq = (lane & 3) * 2;
    #pragma unroll
    for (int mi = 0; mi < 4; mi++)
        #pragma unroll
        for (int half = 0; half < 2; half++) {
            const int m = m0 + wmr + mi * 16 + mq + half * 8;
            #pragma unroll
            for (int nj = 0; nj < 4; nj++) {
                const int n = n0 + wnr + nj * 8 + nq;
                float v0 = acc[mi][nj][half * 2 + 0] + bias[n];
                float v1 = acc[mi][nj][half * 2 + 1] + bias[n + 1];
                if (MODE == 0) {
                    __half2 h2;
                    h2.x = __float2half_rn(v0);
                    h2.y = __float2half_rn(v1);
                    *(__half2*)(outH + (size_t)m * HID + n) = h2;
                } else {
                    *(float2*)(outF + (size_t)m * HID + n) = make_float2(v0, v1);
                }
            }
        }
}

// ---------------- scores chunk: Sc[z,t,s] = Q·K^T (1-product) ----------------
__global__ __launch_bounds__(256)
void scores_gemm(const __half* __restrict__ Qh, const __half* __restrict__ Kh,
                 const int* __restrict__ amask, float* __restrict__ Sc, int bh0) {
    extern __shared__ __align__(128) char sm[];
    const uint32_t sb = smem_u32(sm);
    const int tid = threadIdx.x, lane = tid & 31, w = tid >> 5;
    const int wmr = (w & 1) * 64, wnr = (w >> 1) * 32;
    const int zz = blockIdx.z, bh = bh0 + zz, b = bh >> 4, h = bh & 15;
    const int t0 = blockIdx.y * 128, s0 = blockIdx.x * 128;
    const __half* gA = Qh + (size_t)(b * T_LEN + t0) * HID + h * HD;
    const __half* gB = Kh + (size_t)(b * S_LEN + s0) * HID + h * HD;

    float acc[4][4][4] = {};
    load_stage<128>(sb + 0,    gA, HID, tid);
    load_stage<128>(sb + 8192, gB, HID, tid);
    CP_COMMIT();
    load_stage<128>(sb + 16384, gA + 32, HID, tid);
    load_stage<128>(sb + 24576, gB + 32, HID, tid);
    CP_COMMIT();
    for (int s = 0; s < 2; s++) {
        if (s == 0) CP_WAIT(1);
        else CP_WAIT(0);
        __syncthreads();
        const uint32_t cur = sb + s * 16384;
        stage_compute1(cur, cur + 8192, wmr, wnr, lane, acc);
        __syncthreads();
    }

    const int mq = lane >> 2, nq = (lane & 3) * 2;
    float* dstB = Sc + (size_t)zz * T_LEN * S_LEN;
    #pragma unroll
    for (int mi = 0; mi < 4; mi++)
        #pragma unroll
        for (int half = 0; half < 2; half++) {
            const int t = t0 + wmr + mi * 16 + mq + half * 8;
            #pragma unroll
            for (int nj = 0; nj < 4; nj++) {
                const int sidx = s0 + wnr + nj * 8 + nq;
                float v0 = acc[mi][nj][half * 2 + 0];
                float v1 = acc[mi][nj][half * 2 + 1];
                if (amask[b * S_LEN + sidx] == 0) v0 = -1e9f;
                if (amask[b * S_LEN + sidx + 1] == 0) v1 = -1e9f;
                *(float2*)(dstB + (size_t)t * S_LEN + sidx) = make_float2(v0, v1);
            }
        }
}

// ---------------- softmax chunk: scratch row -> fp16 hi weights ----------------
__global__ __launch_bounds__(256)
void softmax_kernel(const float* __restrict__ Sc, __half* __restrict__ Wh, int bh0) {
    const int r = blockIdx.x, z = r >> 9, t = r & 511;
    const size_t sbase = ((size_t)z * T_LEN + t) * S_LEN;
    const size_t wbase = ((size_t)(bh0 + z) * T_LEN + t) * S_LEN;
    const int tid = threadIdx.x;
    __shared__ float red[8];
    float v[16];
    #pragma unroll
    for (int i = 0; i < 16; i++) v[i] = Sc[sbase + tid + i * 256];
    float m = -1e30f;
    #pragma unroll
    for (int i = 0; i < 16; i++) m = fmaxf(m, v[i]);
    #pragma unroll
    for (int o = 16; o; o >>= 1) m = fmaxf(m, __shfl_xor_sync(0xFFFFFFFFu, m, o));
    if ((tid & 31) == 0) red[tid >> 5] = m;
    __syncthreads();
    float gmax = red[0];
    #pragma unroll
    for (int w = 1; w < 8; w++) gmax = fmaxf(gmax, red[w]);
    __syncthreads();
    float s = 0.f;
    #pragma unroll
    for (int i = 0; i < 16; i++) { v[i] = expf(v[i] - gmax); s += v[i]; }
    #pragma unroll
    for (int o = 16; o; o >>= 1) s += __shfl_xor_sync(0xFFFFFFFFu, s, o);
    if ((tid & 31) == 0) red[tid >> 5] = s;
    __syncthreads();
    float tot = red[0];
    #pragma unroll
    for (int w = 1; w < 8; w++) tot += red[w];
    const float inv = 1.0f / tot;
    #pragma unroll
    for (int i = 0; i < 16; i++)
        Wh[wbase + tid + i * 256] = __float2half_rn(v[i] * inv);
}

// ---------------- provenance = head-mean of Wh ----------------
__global__ __launch_bounds__(256)
void provenance_kernel(const __half* __restrict__ Wh, float* __restrict__ out) {
    const size_t u = (size_t)blockIdx.x * 256 + threadIdx.x;
    const int s2 = (int)(u & 2047);
    const int t  = (int)((u >> 11) & 511);
    const int b  = (int)(u >> 20);
    float s0 = 0.f, s1 = 0.f;
    #pragma unroll
    for (int h = 0; h < NH; h++) {
        const size_t o = (((size_t)(b * NH + h) * T_LEN + t) * S_LEN) / 2 + s2;
        __half2 h2 = reinterpret_cast<const __half2*>(Wh)[o];
        s0 += __half2float(h2.x);
        s1 += __half2float(h2.y);
    }
    reinterpret_cast<float2*>(out)[u] = make_float2(s0 * (1.0f / NH), s1 * (1.0f / NH));
}

// ---------------- P·V: C[128,64] per CTA, K=4096, single-product, 3-stage ----------------
__global__ __launch_bounds__(256)
void pv_gemm(const __half* __restrict__ Wh, const __half* __restrict__ Vh,
             __half* __restrict__ attH) {
    extern __shared__ __align__(128) char sm[];
    const uint32_t sb = smem_u32(sm);
    const int tid = threadIdx.x, lane = tid & 31, w = tid >> 5;
    const int wmr = (w & 3) * 32, wnr = (w >> 2) * 32;
    const int bh = blockIdx.y, b = bh >> 4, h = bh & 15;
    const int t0 = blockIdx.x * 128;
    const __half* gA = Wh + ((size_t)bh * T_LEN + t0) * S_LEN;
    const __half* gB = Vh + (size_t)(b * S_LEN) * HID + h * HD;

#define PV_LOAD(st, ko) do {                                              \
    const uint32_t b_ = sb + ((st) % 3) * 12288;                          \
    load_stage<128>(b_ + 0, gA + (ko), S_LEN, tid);                       \
    load_vtile(b_ + 8192, gB + (size_t)(ko) * HID, HID, tid);             \
    CP_COMMIT();                                                          \
  } while (0)

    float acc[2][4][4] = {};
    PV_LOAD(0, 0);
    PV_LOAD(1, 32);
    const int NST = S_LEN / 32;
    for (int s = 0; s < NST; s++) {
        if (s + 2 < NST) { PV_LOAD(s + 2, (s + 2) * 32); CP_WAIT(2); }
        else if (s + 1 < NST) { CP_WAIT(1); }
        else { CP_WAIT(0); }
        __syncthreads();
        const uint32_t cur = sb + (s % 3) * 12288;
        pv_stage1<2>(cur, cur + 8192, wmr, wnr, lane, acc);
        __syncthreads();
    }
#undef PV_LOAD

    const int mq = lane >> 2, nq = (lane & 3) * 2;
    #pragma unroll
    for (int mi = 0; mi < 2; mi++)
        #pragma unroll
        for (int half = 0; half < 2; half++) {
            const int t = t0 + wmr + mi * 16 + mq + half * 8;
            const size_t mo = (size_t)(b * T_LEN + t) * HID + h * HD;
            #pragma unroll
            for (int nj = 0; nj < 4; nj++) {
                const int n = wnr + nj * 8 + nq;
                __half2 h2;
                h2.x = __float2half_rn(acc[mi][nj][half * 2 + 0]);
                h2.y = __float2half_rn(acc[mi][nj][half * 2 + 1]);
                *(__half2*)(attH + mo + n) = h2;
            }
        }
}

// ---------------------------------------------------------------------------
extern "C" void kernel_launch(void* const* d_in, const int* in_sizes, int n_in,
                              void* d_out, int out_size) {
    const float* query  = (const float*)d_in[0];
    const float* key    = (const float*)d_in[1];
    const float* value  = (const float*)d_in[2];
    const int*   amask  = (const int*)d_in[3];
    const int*   segids = (const int*)d_in[4];
    const float* Wq = (const float*)d_in[5];
    const float* bq = (const float*)d_in[6];
    const float* Wk = (const float*)d_in[7];
    const float* bk = (const float*)d_in[8];
    const float* Wv = (const float*)d_in[9];
    const float* bv = (const float*)d_in[10];
    const float* Wo = (const float*)d_in[11];
    const float* bo = (const float*)d_in[12];
    const float* seg_emb = (const float*)d_in[13];
    float* out = (float*)d_out;

    __half *qh, *kh, *vh;
    __half *wqh, *wql, *wkh, *wkl, *wvh, *woh;
    __half *Qh, *Kh, *Vh, *Wh, *ah;
    float *Ssc;
    cudaGetSymbolAddress((void**)&qh, g_qh);
    cudaGetSymbolAddress((void**)&kh, g_kh);
    cudaGetSymbolAddress((void**)&vh, g_vh);
    cudaGetSymbolAddress((void**)&wqh, g_wqh); cudaGetSymbolAddress((void**)&wql, g_wql);
    cudaGetSymbolAddress((void**)&wkh, g_wkh); cudaGetSymbolAddress((void**)&wkl, g_wkl);
    cudaGetSymbolAddress((void**)&wvh, g_wvh);
    cudaGetSymbolAddress((void**)&woh, g_woh);
    cudaGetSymbolAddress((void**)&Qh, g_Qh);
    cudaGetSymbolAddress((void**)&Kh, g_Kh);
    cudaGetSymbolAddress((void**)&Vh, g_Vh);
    cudaGetSymbolAddress((void**)&Ssc, g_Ssc);
    cudaGetSymbolAddress((void**)&Wh, g_Wh);
    cudaGetSymbolAddress((void**)&ah, g_ah);

    cudaFuncSetAttribute(proj2<0>, cudaFuncAttributeMaxDynamicSharedMemorySize, 73728);
    cudaFuncSetAttribute(proj2<1>, cudaFuncAttributeMaxDynamicSharedMemorySize, 73728);
    cudaFuncSetAttribute(proj1<0>, cudaFuncAttributeMaxDynamicSharedMemorySize, 49152);
    cudaFuncSetAttribute(proj1<1>, cudaFuncAttributeMaxDynamicSharedMemorySize, 49152);
    cudaFuncSetAttribute(scores_gemm, cudaFuncAttributeMaxDynamicSharedMemorySize, 32768);
    cudaFuncSetAttribute(pv_gemm, cudaFuncAttributeMaxDynamicSharedMemorySize, 36864);

    // input + weight conversions
    conv_h<<<4096, 256>>>(query, qh);
    conv_h<<<32768, 256>>>(key, kh);
    conv_h<<<32768, 256>>>(value, vh);
    dim3 wtb(32, 8), wtg(32, 32);
    conv_wT<<<wtg, wtb>>>(Wq, wqh, wql);
    conv_wT<<<wtg, wtb>>>(Wk, wkh, wkl);
    conv_wT<<<wtg, wtb>>>(Wv, wvh, nullptr);
    conv_wT<<<wtg, wtb>>>(Wo, woh, nullptr);

    // projections
    proj2<0><<<dim3(8, 16),  256, 73728>>>(qh, wqh, wql, bq, nullptr, nullptr, Qh);
    proj2<1><<<dim3(8, 128), 256, 73728>>>(kh, wkh, wkl, bk, segids, seg_emb, Kh);
    proj1<0><<<dim3(8, 128), 256, 49152>>>(vh, wvh, bv, nullptr, Vh);

    // attention: L2-blocked scores -> softmax per 8-head chunk (reused scratch)
    for (int c = 0; c < NBH / CHUNK_H; c++) {
        const int bh0 = c * CHUNK_H;
        scores_gemm<<<dim3(32, 4, CHUNK_H), 256, 32768>>>(Qh, Kh, amask, Ssc, bh0);
        softmax_kernel<<<CHUNK_H * T_LEN, 256>>>(Ssc, Wh, bh0);
    }
    provenance_kernel<<<16384, 256>>>(Wh, out + (size_t)2048 * HID);
    pv_gemm<<<dim3(4, 64), 256, 36864>>>(Wh, Vh, ah);

    // output projection -> d_out
    proj1<1><<<dim3(8, 16), 256, 49152>>>(ah, woh, bo, out, nullptr);
}

// round 10
// speedup vs baseline: 4.9207x; 1.0156x over previous
#include <cuda_runtime.h>
#include <cuda_fp16.h>
#include <cstdint>
#include <cstddef>

#define B_SZ   4
#define T_LEN  512
#define S_LEN  4096
#define HID    1024
#define NH     16
#define HD     64
#define NBH    (B_SZ * NH)

// ---------------------------------------------------------------------------
// helpers
// ---------------------------------------------------------------------------
__device__ __forceinline__ uint32_t smem_u32(const void* p) {
    uint32_t a;
    asm("{ .reg .u64 t; cvta.to.shared.u64 t, %1; cvt.u32.u64 %0, t; }" : "=r"(a) : "l"(p));
    return a;
}
// 64B-row tile swizzle (K-major tiles)
__device__ __forceinline__ uint32_t swzoff(int row, int chunk) {
    const int v = (row & 3) ^ ((row >> 2) & 1);
    return (uint32_t)(row * 64 + (((chunk ^ v) & 3) << 4));
}
__device__ __forceinline__ void cpa16(uint32_t dst, const void* src) {
    asm volatile("cp.async.cg.shared.global [%0], [%1], 16;" :: "r"(dst), "l"(src));
}
#define CP_COMMIT() asm volatile("cp.async.commit_group;" ::: "memory")
#define CP_WAIT(n)  asm volatile("cp.async.wait_group %0;" :: "n"(n) : "memory")

__device__ __forceinline__ void ldsm4(uint32_t* r, uint32_t a) {
    asm volatile("ldmatrix.sync.aligned.m8n8.x4.shared.b16 {%0,%1,%2,%3}, [%4];"
                 : "=r"(r[0]), "=r"(r[1]), "=r"(r[2]), "=r"(r[3]) : "r"(a));
}
__device__ __forceinline__ void ldsm4t(uint32_t* r, uint32_t a) {
    asm volatile("ldmatrix.sync.aligned.m8n8.x4.trans.shared.b16 {%0,%1,%2,%3}, [%4];"
                 : "=r"(r[0]), "=r"(r[1]), "=r"(r[2]), "=r"(r[3]) : "r"(a));
}
__device__ __forceinline__ void mma_f16(float* d, const uint32_t* a, const uint32_t* b) {
    asm volatile("mma.sync.aligned.m16n8k16.row.col.f32.f16.f16.f32 "
                 "{%0,%1,%2,%3}, {%4,%5,%6,%7}, {%8,%9}, {%0,%1,%2,%3};"
                 : "+f"(d[0]), "+f"(d[1]), "+f"(d[2]), "+f"(d[3])
                 : "r"(a[0]), "r"(a[1]), "r"(a[2]), "r"(a[3]), "r"(b[0]), "r"(b[1]));
}
__device__ __forceinline__ void split2h(float v, __half& h, __half& l) {
    h = __float2half_rn(v);
    l = __float2half_rn(v - __half2float(h));
}

// Load a [ROWS x 32] fp16 tile (row stride = stride elems) into swizzled SMEM
template<int ROWS>
__device__ __forceinline__ void load_stage(uint32_t sbuf, const __half* g,
                                           int stride, int tid) {
    #pragma unroll
    for (int i = tid; i < ROWS * 4; i += 256) {
        const int row = i >> 2, ch = i & 3;
        cpa16(sbuf + swzoff(row, ch), g + (size_t)row * stride + ch * 8);
    }
}
// Load a [32 x 64] fp16 tile (128B rows, chunk-XOR swizzle) for trans-B (V)
__device__ __forceinline__ void load_vtile(uint32_t sbuf, const __half* g,
                                           int stride, int tid) {
    if (tid < 256) {
        const int row = tid >> 3, ch = tid & 7;
        cpa16(sbuf + (uint32_t)(row * 128 + (((ch ^ row) & 7) << 4)),
              g + (size_t)row * stride + ch * 8);
    }
}

// One 32-k stage, A single + B hi/lo, 2 products (Q/K projections).
__device__ __forceinline__ void stage_compute2(uint32_t sA,
                                               uint32_t sBh, uint32_t sBl,
                                               int wmr, int wnr, int lane,
                                               float (*acc)[4][4]) {
    const int l7 = lane & 7, l8 = (lane >> 3) & 1, l16 = (lane >> 4) & 1;
    const int arow = wmr + l7 + l8 * 8;
    const int brow = wnr + l16 * 8 + l7;
    #pragma unroll
    for (int ks = 0; ks < 2; ks++) {
        uint32_t ah[4][4], bh[2][4], bl[2][4];
        #pragma unroll
        for (int mi = 0; mi < 4; mi++)
            ldsm4(ah[mi], sA + swzoff(arow + mi * 16, ks * 2 + l16));
        #pragma unroll
        for (int p = 0; p < 2; p++) {
            const uint32_t off = swzoff(brow + p * 16, ks * 2 + l8);
            ldsm4(bh[p], sBh + off);
            ldsm4(bl[p], sBl + off);
        }
        #pragma unroll
        for (int mi = 0; mi < 4; mi++)
            #pragma unroll
            for (int nj = 0; nj < 4; nj++) {
                mma_f16(acc[mi][nj], ah[mi], &bh[nj >> 1][(nj & 1) * 2]);
                mma_f16(acc[mi][nj], ah[mi], &bl[nj >> 1][(nj & 1) * 2]);
            }
    }
}

// One 32-k stage, A single + B single, 1 product (V/O projections, scores).
__device__ __forceinline__ void stage_compute1(uint32_t sA, uint32_t sB,
                                               int wmr, int wnr, int lane,
                                               float (*acc)[4][4]) {
    const int l7 = lane & 7, l8 = (lane >> 3) & 1, l16 = (lane >> 4) & 1;
    const int arow = wmr + l7 + l8 * 8;
    const int brow = wnr + l16 * 8 + l7;
    #pragma unroll
    for (int ks = 0; ks < 2; ks++) {
        uint32_t ah[4][4], bh[2][4];
        #pragma unroll
        for (int mi = 0; mi < 4; mi++)
            ldsm4(ah[mi], sA + swzoff(arow + mi * 16, ks * 2 + l16));
        #pragma unroll
        for (int p = 0; p < 2; p++)
            ldsm4(bh[p], sB + swzoff(brow + p * 16, ks * 2 + l8));
        #pragma unroll
        for (int mi = 0; mi < 4; mi++)
            #pragma unroll
            for (int nj = 0; nj < 4; nj++)
                mma_f16(acc[mi][nj], ah[mi], &bh[nj >> 1][(nj & 1) * 2]);
    }
}

// One 32-k PV stage: A = E single (K-major, MI m-frags), B = V via ldmatrix.trans
template<int MI>
__device__ __forceinline__ void pv_stage1(uint32_t sA, uint32_t sB,
                                          int wmr, int wnr, int lane,
                                          float (*acc)[4][4]) {
    const int l7 = lane & 7, l8 = (lane >> 3) & 1, l16 = (lane >> 4) & 1;
    const int arow = wmr + l7 + l8 * 8;
    const int g = lane >> 3, q = lane & 7;
    #pragma unroll
    for (int ks = 0; ks < 2; ks++) {
        uint32_t ah[MI][4];
        #pragma unroll
        for (int mi = 0; mi < MI; mi++)
            ldsm4(ah[mi], sA + swzoff(arow + mi * 16, ks * 2 + l16));
        #pragma unroll
        for (int half = 0; half < 2; half++) {
            const int r = ks * 16 + (g & 1) * 8 + q;
            const int cb = ((wnr + half * 16) >> 3) + (g >> 1);
            const uint32_t off = (uint32_t)(r * 128 + (((cb ^ r) & 7) << 4));
            uint32_t bh4[4];
            ldsm4t(bh4, sB + off);
            #pragma unroll
            for (int mi = 0; mi < MI; mi++)
                #pragma unroll
                for (int u = 0; u < 2; u++)
                    mma_f16(acc[mi][half * 2 + u], ah[mi], &bh4[u * 2]);
        }
    }
}

// ---------------- scratch ----------------
__device__ __half g_qh[2048 * HID];
__device__ __half g_kh[16384 * HID];
__device__ __half g_vh[16384 * HID];
__device__ __half g_wqh[HID * HID], g_wql[HID * HID];
__device__ __half g_wkh[HID * HID], g_wkl[HID * HID];
__device__ __half g_wvh[HID * HID];
__device__ __half g_woh[HID * HID];
__device__ __half g_Qh[2048 * HID];
__device__ __half g_Kh[16384 * HID];
__device__ __half g_Vh[16384 * HID];
__device__ __half g_E[(size_t)NBH * T_LEN * S_LEN];     // exp(score-4), fp16
__device__ float  g_ps[(size_t)NBH * T_LEN * 32];       // per-block partial row sums
__device__ float  g_rs[NBH * T_LEN];                    // row sums
__device__ __half g_ah[2048 * HID];

// ---------------- conversions ----------------
__global__ __launch_bounds__(256)
void conv_h(const float* __restrict__ X, __half* __restrict__ H) {
    const size_t u = (size_t)blockIdx.x * 256 + threadIdx.x;
    float2 v = reinterpret_cast<const float2*>(X)[u];
    reinterpret_cast<__half2*>(H)[u] =
        __halves2half2(__float2half_rn(v.x), __float2half_rn(v.y));
}
__global__ __launch_bounds__(256)
void conv_wT(const float* __restrict__ W, __half* __restrict__ WTh,
             __half* __restrict__ WTl) {
    __shared__ float t[32][33];
    const int k0 = blockIdx.x * 32, n0 = blockIdx.y * 32;
    const int tx = threadIdx.x, ty = threadIdx.y;
    for (int r = ty; r < 32; r += 8) t[r][tx] = W[(size_t)(k0 + r) * HID + n0 + tx];
    __syncthreads();
    for (int r = ty; r < 32; r += 8) {
        __half h, l;
        split2h(t[tx][r], h, l);
        WTh[(size_t)(n0 + r) * HID + k0 + tx] = h;
        if (WTl) WTl[(size_t)(n0 + r) * HID + k0 + tx] = l;
    }
}

// ---------------- Q/K projection (2-product weights, single fp16 out) ----------------
// MODE 0: Q (bias, *0.125) 1: K (bias+seg)
template<int MODE>
__global__ __launch_bounds__(256)
void proj2(const __half* __restrict__ A,
           const __half* __restrict__ Bh, const __half* __restrict__ Bl,
           const float* __restrict__ bias, const int* __restrict__ segids,
           const float* __restrict__ seg_emb, __half* __restrict__ outH) {
    extern __shared__ __align__(128) char sm[];
    const uint32_t sb = smem_u32(sm);
    const int tid = threadIdx.x, lane = tid & 31, w = tid >> 5;
    const int wmr = (w & 1) * 64, wnr = (w >> 1) * 32;
    const int n0 = blockIdx.x * 128, m0 = blockIdx.y * 128;
    const __half* gA  = A + (size_t)m0 * HID;
    const __half* gBh = Bh + (size_t)n0 * HID;
    const __half* gBl = Bl + (size_t)n0 * HID;

#define PJ_LOAD(st, ko) do {                                \
    const uint32_t b_ = sb + ((st) % 3) * 24576;            \
    load_stage<128>(b_ + 0,     gA  + (ko), HID, tid);      \
    load_stage<128>(b_ + 8192,  gBh + (ko), HID, tid);      \
    load_stage<128>(b_ + 16384, gBl + (ko), HID, tid);      \
    CP_COMMIT();                                            \
  } while (0)

    float acc[4][4][4] = {};
    PJ_LOAD(0, 0);
    PJ_LOAD(1, 32);
    const int NST = HID / 32;
    for (int s = 0; s < NST; s++) {
        if (s + 2 < NST) { PJ_LOAD(s + 2, (s + 2) * 32); CP_WAIT(2); }
        else if (s + 1 < NST) { CP_WAIT(1); }
        else { CP_WAIT(0); }
        __syncthreads();
        const uint32_t cur = sb + (s % 3) * 24576;
        stage_compute2(cur, cur + 8192, cur + 16384, wmr, wnr, lane, acc);
        __syncthreads();
    }
#undef PJ_LOAD

    const int mq = lane >> 2, nq = (lane & 3) * 2;
    #pragma unroll
    for (int mi = 0; mi < 4; mi++)
        #pragma unroll
        for (int half = 0; half < 2; half++) {
            const int m = m0 + wmr + mi * 16 + mq + half * 8;
            const int sid = (MODE == 1) ? segids[m] : 0;
            #pragma unroll
            for (int nj = 0; nj < 4; nj++) {
                const int n = n0 + wnr + nj * 8 + nq;
                float v0 = acc[mi][nj][half * 2 + 0] + bias[n];
                float v1 = acc[mi][nj][half * 2 + 1] + bias[n + 1];
                if (MODE == 1) {
                    v0 += seg_emb[(size_t)sid * HID + n];
                    v1 += seg_emb[(size_t)sid * HID + n + 1];
                }
                if (MODE == 0) { v0 *= 0.125f; v1 *= 0.125f; }
                __half2 h2;
                h2.x = __float2half_rn(v0);
                h2.y = __float2half_rn(v1);
                *(__half2*)(outH + (size_t)m * HID + n) = h2;
            }
        }
}

// ---------------- V/O projection (1-product, 3-stage) ----------------
// MODE 0: V (bias, fp16 out)  1: O (bias, fp32 out)
template<int MODE>
__global__ __launch_bounds__(256)
void proj1(const __half* __restrict__ A, const __half* __restrict__ B,
           const float* __restrict__ bias, float* __restrict__ outF,
           __half* __restrict__ outH) {
    extern __shared__ __align__(128) char sm[];
    const uint32_t sb = smem_u32(sm);
    const int tid = threadIdx.x, lane = tid & 31, w = tid >> 5;
    const int wmr = (w & 1) * 64, wnr = (w >> 1) * 32;
    const int n0 = blockIdx.x * 128, m0 = blockIdx.y * 128;
    const __half* gA = A + (size_t)m0 * HID;
    const __half* gB = B + (size_t)n0 * HID;

#define P1_LOAD(st, ko) do {                                \
    const uint32_t b_ = sb + ((st) % 3) * 16384;            \
    load_stage<128>(b_ + 0,    gA + (ko), HID, tid);        \
    load_stage<128>(b_ + 8192, gB + (ko), HID, tid);        \
    CP_COMMIT();                                            \
  } while (0)

    float acc[4][4][4] = {};
    P1_LOAD(0, 0);
    P1_LOAD(1, 32);
    const int NST = HID / 32;
    for (int s = 0; s < NST; s++) {
        if (s + 2 < NST) { P1_LOAD(s + 2, (s + 2) * 32); CP_WAIT(2); }
        else if (s + 1 < NST) { CP_WAIT(1); }
        else { CP_WAIT(0); }
        __syncthreads();
        const uint32_t cur = sb + (s % 3) * 16384;
        stage_compute1(cur, cur + 8192, wmr, wnr, lane, acc);
        __syncthreads();
    }
#undef P1_LOAD

    const int mq = lane >> 2, nq = (lane & 3) * 2;
    #pragma unroll
    for (int mi = 0; mi < 4; mi++)
        #pragma unroll
        for (int half = 0; half < 2; half++) {
            const int m = m0 + wmr + mi * 16 + mq + half * 8;
            #pragma unroll
            for (int nj = 0; nj < 4; nj++) {
                const int n = n0 + wnr + nj * 8 + nq;
                float v0 = acc[mi][nj][half * 2 + 0] + bias[n];
                float v1 = acc[mi][nj][half * 2 + 1] + bias[n + 1];
                if (MODE == 0) {
                    __half2 h2;
                    h2.x = __float2half_rn(v0);
                    h2.y = __float2half_rn(v1);
                    *(__half2*)(outH + (size_t)m * HID + n) = h2;
                } else {
                    *(float2*)(outF + (size_t)m * HID + n) = make_float2(v0, v1);
                }
            }
        }
}

// ---------------- scores+exp: E[bh,t,s] = exp(Q·K^T - 4), partial row sums ----------------
__global__ __launch_bounds__(256)
void scores_exp(const __half* __restrict__ Qh, const __half* __restrict__ Kh,
                const int* __restrict__ amask, __half* __restrict__ E,
                float* __restrict__ gps) {
    extern __shared__ __align__(128) char sm[];
    __shared__ float psum[128][4];
    const uint32_t sb = smem_u32(sm);
    const int tid = threadIdx.x, lane = tid & 31, w = tid >> 5;
    const int wmr = (w & 1) * 64, wnr = (w >> 1) * 32;
    const int bh = blockIdx.z, b = bh >> 4, h = bh & 15;
    const int t0 = blockIdx.y * 128, s0 = blockIdx.x * 128;
    const __half* gA = Qh + (size_t)(b * T_LEN + t0) * HID + h * HD;
    const __half* gB = Kh + (size_t)(b * S_LEN + s0) * HID + h * HD;

    float acc[4][4][4] = {};
    load_stage<128>(sb + 0,    gA, HID, tid);
    load_stage<128>(sb + 8192, gB, HID, tid);
    CP_COMMIT();
    load_stage<128>(sb + 16384, gA + 32, HID, tid);
    load_stage<128>(sb + 24576, gB + 32, HID, tid);
    CP_COMMIT();
    for (int s = 0; s < 2; s++) {
        if (s == 0) CP_WAIT(1);
        else CP_WAIT(0);
        __syncthreads();
        const uint32_t cur = sb + s * 16384;
        stage_compute1(cur, cur + 8192, wmr, wnr, lane, acc);
        __syncthreads();
    }

    const int mq = lane >> 2, nq = (lane & 3) * 2;
    __half* dstB = E + (size_t)bh * T_LEN * S_LEN;
    #pragma unroll
    for (int mi = 0; mi < 4; mi++)
        #pragma unroll
        for (int half = 0; half < 2; half++) {
            const int t = t0 + wmr + mi * 16 + mq + half * 8;
            float rsum = 0.f;
            #pragma unroll
            for (int nj = 0; nj < 4; nj++) {
                const int sidx = s0 + wnr + nj * 8 + nq;
                float e0 = (amask[b * S_LEN + sidx] == 0) ? 0.f
                           : __expf(acc[mi][nj][half * 2 + 0] - 4.f);
                float e1 = (amask[b * S_LEN + sidx + 1] == 0) ? 0.f
                           : __expf(acc[mi][nj][half * 2 + 1] - 4.f);
                rsum += e0 + e1;
                __half2 h2;
                h2.x = __float2half_rn(e0);
                h2.y = __float2half_rn(e1);
                *(__half2*)(dstB + (size_t)t * S_LEN + sidx) = h2;
            }
            rsum += __shfl_xor_sync(0xFFFFFFFFu, rsum, 1);
            rsum += __shfl_xor_sync(0xFFFFFFFFu, rsum, 2);
            if ((lane & 3) == 0)
                psum[wmr + mi * 16 + half * 8 + mq][w >> 1] = rsum;
        }
    __syncthreads();
    if (tid < 128) {
        const float tot = psum[tid][0] + psum[tid][1] + psum[tid][2] + psum[tid][3];
        gps[((size_t)bh * T_LEN + t0 + tid) * 32 + blockIdx.x] = tot;
    }
}

// ---------------- row-sum reduce: rs[r] = sum of 32 partials ----------------
__global__ __launch_bounds__(256)
void rowsum_reduce(const float* __restrict__ gps, float* __restrict__ rs) {
    const int r = blockIdx.x * 256 + threadIdx.x;
    const float4* p = reinterpret_cast<const float4*>(gps + (size_t)r * 32);
    float s = 0.f;
    #pragma unroll
    for (int i = 0; i < 8; i++) {
        float4 v = p[i];
        s += v.x + v.y + v.z + v.w;
    }
    rs[r] = s;
}

// ---------------- provenance = head-mean of E/rowsum ----------------
__global__ __launch_bounds__(256)
void provenance_kernel(const __half* __restrict__ E, const float* __restrict__ rs,
                       float* __restrict__ out) {
    const size_t u = (size_t)blockIdx.x * 256 + threadIdx.x;
    const int s2 = (int)(u & 2047);
    const int t  = (int)((u >> 11) & 511);
    const int b  = (int)(u >> 20);
    float s0 = 0.f, s1 = 0.f;
    #pragma unroll
    for (int h = 0; h < NH; h++) {
        const int bh = b * NH + h;
        const float inv = 1.0f / rs[bh * T_LEN + t];
        const size_t o = (((size_t)bh * T_LEN + t) * S_LEN) / 2 + s2;
        __half2 h2 = reinterpret_cast<const __half2*>(E)[o];
        s0 += __half2float(h2.x) * inv;
        s1 += __half2float(h2.y) * inv;
    }
    reinterpret_cast<float2*>(out)[u] = make_float2(s0 * (1.0f / NH), s1 * (1.0f / NH));
}

// ---------------- P·V: C[128,64] per CTA, K=4096, normalized epilogue ----------------
__global__ __launch_bounds__(256)
void pv_gemm(const __half* __restrict__ E, const __half* __restrict__ Vh,
             const float* __restrict__ rs, __half* __restrict__ attH) {
    extern __shared__ __align__(128) char sm[];
    const uint32_t sb = smem_u32(sm);
    const int tid = threadIdx.x, lane = tid & 31, w = tid >> 5;
    const int wmr = (w & 3) * 32, wnr = (w >> 2) * 32;
    const int bh = blockIdx.y, b = bh >> 4, h = bh & 15;
    const int t0 = blockIdx.x * 128;
    const __half* gA = E + ((size_t)bh * T_LEN + t0) * S_LEN;
    const __half* gB = Vh + (size_t)(b * S_LEN) * HID + h * HD;

#define PV_LOAD(st, ko) do {                                              \
    const uint32_t b_ = sb + ((st) % 3) * 12288;                          \
    load_stage<128>(b_ + 0, gA + (ko), S_LEN, tid);                       \
    load_vtile(b_ + 8192, gB + (size_t)(ko) * HID, HID, tid);             \
    CP_COMMIT();                                                          \
  } while (0)

    float acc[2][4][4] = {};
    PV_LOAD(0, 0);
    PV_LOAD(1, 32);
    const int NST = S_LEN / 32;
    for (int s = 0; s < NST; s++) {
        if (s + 2 < NST) { PV_LOAD(s + 2, (s + 2) * 32); CP_WAIT(2); }
        else if (s + 1 < NST) { CP_WAIT(1); }
        else { CP_WAIT(0); }
        __syncthreads();
        const uint32_t cur = sb + (s % 3) * 12288;
        pv_stage1<2>(cur, cur + 8192, wmr, wnr, lane, acc);
        __syncthreads();
    }
#undef PV_LOAD

    const int mq = lane >> 2, nq = (lane & 3) * 2;
    #pragma unroll
    for (int mi = 0; mi < 2; mi++)
        #pragma unroll
        for (int half = 0; half < 2; half++) {
            const int t = t0 + wmr + mi * 16 + mq + half * 8;
            const float inv = 1.0f / rs[bh * T_LEN + t];
            const size_t mo = (size_t)(b * T_LEN + t) * HID + h * HD;
            #pragma unroll
            for (int nj = 0; nj < 4; nj++) {
                const int n = wnr + nj * 8 + nq;
                __half2 h2;
                h2.x = __float2half_rn(acc[mi][nj][half * 2 + 0] * inv);
                h2.y = __float2half_rn(acc[mi][nj][half * 2 + 1] * inv);
                *(__half2*)(attH + mo + n) = h2;
            }
        }
}

// ---------------------------------------------------------------------------
extern "C" void kernel_launch(void* const* d_in, const int* in_sizes, int n_in,
                              void* d_out, int out_size) {
    const float* query  = (const float*)d_in[0];
    const float* key    = (const float*)d_in[1];
    const float* value  = (const float*)d_in[2];
    const int*   amask  = (const int*)d_in[3];
    const int*   segids = (const int*)d_in[4];
    const float* Wq = (const float*)d_in[5];
    const float* bq = (const float*)d_in[6];
    const float* Wk = (const float*)d_in[7];
    const float* bk = (const float*)d_in[8];
    const float* Wv = (const float*)d_in[9];
    const float* bv = (const float*)d_in[10];
    const float* Wo = (const float*)d_in[11];
    const float* bo = (const float*)d_in[12];
    const float* seg_emb = (const float*)d_in[13];
    float* out = (float*)d_out;

    __half *qh, *kh, *vh;
    __half *wqh, *wql, *wkh, *wkl, *wvh, *woh;
    __half *Qh, *Kh, *Vh, *E, *ah;
    float *ps, *rs;
    cudaGetSymbolAddress((void**)&qh, g_qh);
    cudaGetSymbolAddress((void**)&kh, g_kh);
    cudaGetSymbolAddress((void**)&vh, g_vh);
    cudaGetSymbolAddress((void**)&wqh, g_wqh); cudaGetSymbolAddress((void**)&wql, g_wql);
    cudaGetSymbolAddress((void**)&wkh, g_wkh); cudaGetSymbolAddress((void**)&wkl, g_wkl);
    cudaGetSymbolAddress((void**)&wvh, g_wvh);
    cudaGetSymbolAddress((void**)&woh, g_woh);
    cudaGetSymbolAddress((void**)&Qh, g_Qh);
    cudaGetSymbolAddress((void**)&Kh, g_Kh);
    cudaGetSymbolAddress((void**)&Vh, g_Vh);
    cudaGetSymbolAddress((void**)&E, g_E);
    cudaGetSymbolAddress((void**)&ps, g_ps);
    cudaGetSymbolAddress((void**)&rs, g_rs);
    cudaGetSymbolAddress((void**)&ah, g_ah);

    cudaFuncSetAttribute(proj2<0>, cudaFuncAttributeMaxDynamicSharedMemorySize, 73728);
    cudaFuncSetAttribute(proj2<1>, cudaFuncAttributeMaxDynamicSharedMemorySize, 73728);
    cudaFuncSetAttribute(proj1<0>, cudaFuncAttributeMaxDynamicSharedMemorySize, 49152);
    cudaFuncSetAttribute(proj1<1>, cudaFuncAttributeMaxDynamicSharedMemorySize, 49152);
    cudaFuncSetAttribute(scores_exp, cudaFuncAttributeMaxDynamicSharedMemorySize, 32768);
    cudaFuncSetAttribute(pv_gemm, cudaFuncAttributeMaxDynamicSharedMemorySize, 36864);

    // input + weight conversions
    conv_h<<<4096, 256>>>(query, qh);
    conv_h<<<32768, 256>>>(key, kh);
    conv_h<<<32768, 256>>>(value, vh);
    dim3 wtb(32, 8), wtg(32, 32);
    conv_wT<<<wtg, wtb>>>(Wq, wqh, wql);
    conv_wT<<<wtg, wtb>>>(Wk, wkh, wkl);
    conv_wT<<<wtg, wtb>>>(Wv, wvh, nullptr);
    conv_wT<<<wtg, wtb>>>(Wo, woh, nullptr);

    // projections
    proj2<0><<<dim3(8, 16),  256, 73728>>>(qh, wqh, wql, bq, nullptr, nullptr, Qh);
    proj2<1><<<dim3(8, 128), 256, 73728>>>(kh, wkh, wkl, bk, segids, seg_emb, Kh);
    proj1<0><<<dim3(8, 128), 256, 49152>>>(vh, wvh, bv, nullptr, Vh);

    // fused scores+exp (single launch), deterministic row-sum reduction
    scores_exp<<<dim3(32, 4, NBH), 256, 32768>>>(Qh, Kh, amask, E, ps);
    rowsum_reduce<<<NBH * T_LEN / 256, 256>>>(ps, rs);

    // provenance + attended
    provenance_kernel<<<16384, 256>>>(E, rs, out + (size_t)2048 * HID);
    pv_gemm<<<dim3(4, 64), 256, 36864>>>(E, Vh, rs, ah);

    // output projection -> d_out
    proj1<1><<<dim3(8, 16), 256, 49152>>>(ah, woh, bo, out, nullptr);
}